// round 1
// baseline (speedup 1.0000x reference)
#include <cuda_runtime.h>
#include <math.h>

#define Bn 2
#define Tn 2048
#define Cn 1024
#define Hn 16
#define Dn 64
#define Mn (Bn*Tn)          // 4096
#define BHn (Bn*Hn)         // 32

// Scratch (device globals; no runtime allocation allowed)
__device__ float g_Q[BHn*Tn*Dn];      // head-major [b,h,t,d]
__device__ float g_K[BHn*Tn*Dn];
__device__ float g_V[BHn*Tn*Dn];      // raw v after QKV; then exp(z - zmax) in-place
__device__ float g_zmax[Bn*Cn];
__device__ float g_Y[Mn*Cn];          // pre-proj activations

__device__ __forceinline__ float clamp_p(float pp) {
    float sgn = (pp >= 0.0f) ? 1.0f : -1.0f;
    return sgn * fminf(fmaxf(fabsf(pp), 1e-4f), 1e3f);
}

// ---------------------------------------------------------------------------
// Tiled fp32 GEMM: C[M,N] = A[M,K] @ B[K,N] + bias
// BM=BN=128, BK=16, 256 threads, 8x8 microtile.
// MODE 0: write Cout directly.  MODE 1: scatter qkv into g_Q/g_K/g_V.
// ---------------------------------------------------------------------------
template<int MODE>
__global__ __launch_bounds__(256) void gemm128(
    const float* __restrict__ A, const float* __restrict__ Bw,
    const float* __restrict__ bias, float* __restrict__ Cout,
    int M, int N, int K)
{
    __shared__ float As[16*128];   // As[k][m] (transposed)
    __shared__ float Bs[16*128];   // Bs[k][n]

    const int tid = threadIdx.x;
    const int bm = blockIdx.y, bn = blockIdx.x;
    const int tr = tid >> 4, tc = tid & 15;
    const int m0 = tr * 8, n0 = tc * 8;

    float acc[8][8];
#pragma unroll
    for (int i = 0; i < 8; i++)
#pragma unroll
        for (int j = 0; j < 8; j++) acc[i][j] = 0.0f;

    for (int k0 = 0; k0 < K; k0 += 16) {
        // load A tile (128 rows x 16 cols), store transposed
#pragma unroll
        for (int l = tid; l < 512; l += 256) {
            int row = l >> 2, c4 = l & 3;
            float4 a = *(const float4*)(A + (size_t)(bm*128 + row)*K + k0 + c4*4);
            As[(c4*4+0)*128 + row] = a.x;
            As[(c4*4+1)*128 + row] = a.y;
            As[(c4*4+2)*128 + row] = a.z;
            As[(c4*4+3)*128 + row] = a.w;
        }
        // load B tile (16 rows x 128 cols)
#pragma unroll
        for (int l = tid; l < 512; l += 256) {
            int row = l >> 5, cb = l & 31;
            float4 b = *(const float4*)(Bw + (size_t)(k0 + row)*N + bn*128 + cb*4);
            *(float4*)(Bs + row*128 + cb*4) = b;
        }
        __syncthreads();

#pragma unroll
        for (int kk = 0; kk < 16; kk++) {
            float4 a0 = *(const float4*)(As + kk*128 + m0);
            float4 a1 = *(const float4*)(As + kk*128 + m0 + 4);
            float4 b0 = *(const float4*)(Bs + kk*128 + n0);
            float4 b1 = *(const float4*)(Bs + kk*128 + n0 + 4);
            float av[8] = {a0.x,a0.y,a0.z,a0.w,a1.x,a1.y,a1.z,a1.w};
            float bv[8] = {b0.x,b0.y,b0.z,b0.w,b1.x,b1.y,b1.z,b1.w};
#pragma unroll
            for (int i = 0; i < 8; i++)
#pragma unroll
                for (int j = 0; j < 8; j++)
                    acc[i][j] = fmaf(av[i], bv[j], acc[i][j]);
        }
        __syncthreads();
    }

    if (MODE == 0) {
        // direct output with bias
#pragma unroll
        for (int i = 0; i < 8; i++) {
            int m = bm*128 + m0 + i;
#pragma unroll
            for (int j4 = 0; j4 < 2; j4++) {
                int n = bn*128 + n0 + j4*4;
                float4 o;
                o.x = acc[i][j4*4+0] + bias[n+0];
                o.y = acc[i][j4*4+1] + bias[n+1];
                o.z = acc[i][j4*4+2] + bias[n+2];
                o.w = acc[i][j4*4+3] + bias[n+3];
                *(float4*)(Cout + (size_t)m*N + n) = o;
            }
        }
    } else {
        // scatter qkv into head-major buffers
#pragma unroll
        for (int i = 0; i < 8; i++) {
            int m = bm*128 + m0 + i;
            int b = m >> 11;            // /T
            int t = m & 2047;
#pragma unroll
            for (int j = 0; j < 8; j++) {
                int n = bn*128 + n0 + j;
                float val = acc[i][j] + bias[n];
                int sec = n >> 10;      // 0=q,1=k,2=v
                int c   = n & 1023;
                int h   = c >> 6;
                int dd  = c & 63;
                int idx = ((b*Hn + h)*Tn + t)*64 + dd;
                if (sec == 0)      g_Q[idx] = val;
                else if (sec == 1) g_K[idx] = val;
                else               g_V[idx] = val;
            }
        }
    }
}

// ---------------------------------------------------------------------------
// z_max over T per (b, c): z = p * log(clip(|v+5|, 1e-10))
// grid = B*H blocks; threads: dd = tid&63, group g = tid>>6 (4 t-groups)
// ---------------------------------------------------------------------------
__global__ __launch_bounds__(256) void zmax_kernel(const float* __restrict__ p_param)
{
    int bh = blockIdx.x;
    int b = bh >> 4, h = bh & 15;
    int dd = threadIdx.x & 63;
    int g  = threadIdx.x >> 6;
    int c  = h*64 + dd;
    float pv = clamp_p(p_param[c]);

    const float* vp = g_V + (size_t)bh * Tn * 64;
    float mx = -1e30f;
    for (int t = g; t < Tn; t += 4) {
        float v = vp[t*64 + dd];
        float z = pv * logf(fmaxf(fabsf(v + 5.0f), 1e-10f));
        mx = fmaxf(mx, z);
    }
    __shared__ float red[256];
    red[threadIdx.x] = mx;
    __syncthreads();
    if (g == 0) {
        mx = fmaxf(fmaxf(red[dd], red[64+dd]), fmaxf(red[128+dd], red[192+dd]));
        g_zmax[b*Cn + c] = mx;
    }
}

// ---------------------------------------------------------------------------
// V transform in-place: v = exp(p*log(clip(|v+5|)) - zmax)
// ---------------------------------------------------------------------------
__global__ __launch_bounds__(256) void vexp_kernel(const float* __restrict__ p_param)
{
    int idx = blockIdx.x * 256 + threadIdx.x;   // B*H*T*D = 4194304
    int dd = idx & 63;
    int bh = idx >> 17;                          // / (T*64)
    int h = bh & 15, b = bh >> 4;
    int c = h*64 + dd;
    float pv = clamp_p(p_param[c]);
    float v = g_V[idx];
    float z = pv * logf(fmaxf(fabsf(v + 5.0f), 1e-10f));
    g_V[idx] = expf(z - g_zmax[b*Cn + c]);
}

// ---------------------------------------------------------------------------
// Flash attention (causal) with fused inverse power-mean epilogue.
// grid = (T/64, B*H), 256 threads, BQ=BK=64.
// SMEM: Qs[d][r], Ks[d][c], Vs[k][c], Ss[r][65], rm/rl/ra[64]
// ---------------------------------------------------------------------------
#define FA_SMEM ((3*4096 + 64*65 + 3*64) * 4)

__global__ __launch_bounds__(256) void fa_kernel(const float* __restrict__ p_param)
{
    extern __shared__ float sm[];
    float* Qs = sm;              // [64][64] transposed: Qs[d*64 + r]
    float* Ks = sm + 4096;       // Ks[d*64 + c]
    float* Vs = sm + 8192;       // Vs[k*64 + c]
    float* Ss = sm + 12288;      // Ss[r*65 + k]
    float* rm = sm + 12288 + 4160;
    float* rl = rm + 64;
    float* ra = rl + 64;

    const int tid = threadIdx.x;
    const int bh = blockIdx.y;
    const int b = bh >> 4, h = bh & 15;
    const int qt = blockIdx.x;
    const int q0 = qt * 64;
    const float scale = 0.125f;   // 1/sqrt(64)

    const int r0 = (tid >> 4) * 4;
    const int c0 = (tid & 15) * 4;

    // load Q tile transposed
    const float* Qg = g_Q + ((size_t)bh * Tn + q0) * 64;
#pragma unroll
    for (int l = tid; l < 1024; l += 256) {
        int row = l >> 4, c4 = l & 15;
        float4 v = *(const float4*)(Qg + row*64 + c4*4);
        Qs[(c4*4+0)*64 + row] = v.x;
        Qs[(c4*4+1)*64 + row] = v.y;
        Qs[(c4*4+2)*64 + row] = v.z;
        Qs[(c4*4+3)*64 + row] = v.w;
    }
    if (tid < 64) { rm[tid] = -1e30f; rl[tid] = 0.0f; }

    float O[4][4];
#pragma unroll
    for (int i = 0; i < 4; i++)
#pragma unroll
        for (int j = 0; j < 4; j++) O[i][j] = 0.0f;

    for (int kt = 0; kt <= qt; kt++) {
        const float* Kg = g_K + ((size_t)bh * Tn + kt*64) * 64;
        const float* Vg = g_V + ((size_t)bh * Tn + kt*64) * 64;
#pragma unroll
        for (int l = tid; l < 1024; l += 256) {
            int row = l >> 4, c4 = l & 15;
            float4 kv = *(const float4*)(Kg + row*64 + c4*4);
            Ks[(c4*4+0)*64 + row] = kv.x;
            Ks[(c4*4+1)*64 + row] = kv.y;
            Ks[(c4*4+2)*64 + row] = kv.z;
            Ks[(c4*4+3)*64 + row] = kv.w;
            float4 vv = *(const float4*)(Vg + row*64 + c4*4);
            *(float4*)(Vs + row*64 + c4*4) = vv;
        }
        __syncthreads();

        // S = scale * Q K^T  (4x4 per thread)
        float s[4][4];
#pragma unroll
        for (int i = 0; i < 4; i++)
#pragma unroll
            for (int j = 0; j < 4; j++) s[i][j] = 0.0f;

#pragma unroll 8
        for (int d = 0; d < 64; d++) {
            float4 qv = *(const float4*)(Qs + d*64 + r0);
            float4 kv = *(const float4*)(Ks + d*64 + c0);
            float qa[4] = {qv.x, qv.y, qv.z, qv.w};
            float ka[4] = {kv.x, kv.y, kv.z, kv.w};
#pragma unroll
            for (int i = 0; i < 4; i++)
#pragma unroll
                for (int j = 0; j < 4; j++)
                    s[i][j] = fmaf(qa[i], ka[j], s[i][j]);
        }

        // scale, causal mask (only on diagonal tile), write to Ss
        const bool diag = (kt == qt);
#pragma unroll
        for (int i = 0; i < 4; i++) {
            int rg = q0 + r0 + i;
#pragma unroll
            for (int j = 0; j < 4; j++) {
                int cg = kt*64 + c0 + j;
                float val = s[i][j] * scale;
                if (diag && cg > rg) val = -1e30f;
                s[i][j] = val;
                Ss[(r0+i)*65 + (c0+j)] = val;
            }
        }
        __syncthreads();

        // row max update
        if (tid < 64) {
            float mx = rm[tid];
#pragma unroll 8
            for (int k = 0; k < 64; k++) mx = fmaxf(mx, Ss[tid*65 + k]);
            ra[tid] = __expf(rm[tid] - mx);
            rm[tid] = mx;
        }
        __syncthreads();

        // P = exp(S - m), rescale O
        float mrow[4], arow[4];
#pragma unroll
        for (int i = 0; i < 4; i++) { mrow[i] = rm[r0+i]; arow[i] = ra[r0+i]; }
#pragma unroll
        for (int i = 0; i < 4; i++) {
#pragma unroll
            for (int j = 0; j < 4; j++) {
                float pij = __expf(s[i][j] - mrow[i]);
                Ss[(r0+i)*65 + (c0+j)] = pij;
                O[i][j] *= arow[i];
            }
        }
        __syncthreads();

        // row sum update
        if (tid < 64) {
            float sum = 0.0f;
#pragma unroll 8
            for (int k = 0; k < 64; k++) sum += Ss[tid*65 + k];
            rl[tid] = rl[tid] * ra[tid] + sum;
        }

        // O += P @ V
#pragma unroll 4
        for (int k = 0; k < 64; k++) {
            float4 vv = *(const float4*)(Vs + k*64 + c0);
            float va[4] = {vv.x, vv.y, vv.z, vv.w};
            float pa[4];
#pragma unroll
            for (int i = 0; i < 4; i++) pa[i] = Ss[(r0+i)*65 + k];
#pragma unroll
            for (int i = 0; i < 4; i++)
#pragma unroll
                for (int j = 0; j < 4; j++)
                    O[i][j] = fmaf(pa[i], va[j], O[i][j]);
        }
        __syncthreads();
    }

    // epilogue: mean = O/l; y = exp((zmax + log(mean))/p) - SHIFT
    float rlv[4];
#pragma unroll
    for (int i = 0; i < 4; i++) rlv[i] = rl[r0+i];

#pragma unroll
    for (int j = 0; j < 4; j++) {
        int dd = c0 + j;
        int cg = h*64 + dd;
        float pv = clamp_p(p_param[cg]);
        float zm = g_zmax[b*Cn + cg];
        float inv_p = 1.0f / pv;
#pragma unroll
        for (int i = 0; i < 4; i++) {
            float mean = O[i][j] / rlv[i];
            float y = expf((zm + logf(mean)) * inv_p) - 5.0f;
            int t = q0 + r0 + i;
            g_Y[(size_t)(b*Tn + t)*Cn + cg] = y;
        }
    }
}

// ---------------------------------------------------------------------------

extern "C" void kernel_launch(void* const* d_in, const int* in_sizes, int n_in,
                              void* d_out, int out_size)
{
    const float* x       = (const float*)d_in[0];
    const float* w_attn  = (const float*)d_in[1];
    const float* b_attn  = (const float*)d_in[2];
    const float* w_proj  = (const float*)d_in[3];
    const float* b_proj  = (const float*)d_in[4];
    const float* p_param = (const float*)d_in[5];
    float* out = (float*)d_out;

    void* yptr = nullptr;
    cudaGetSymbolAddress(&yptr, g_Y);

    cudaFuncSetAttribute(fa_kernel, cudaFuncAttributeMaxDynamicSharedMemorySize, FA_SMEM);

    // 1) QKV GEMM + scatter into head-major Q/K/V
    gemm128<1><<<dim3(3072/128, Mn/128), 256>>>(x, w_attn, b_attn, nullptr, Mn, 3072, Cn);

    // 2) z_max reduction over T
    zmax_kernel<<<BHn, 256>>>(p_param);

    // 3) V power transform in-place
    vexp_kernel<<<(BHn*Tn*Dn)/256, 256>>>(p_param);

    // 4) causal flash attention + fused inverse power-mean epilogue
    fa_kernel<<<dim3(Tn/64, BHn), 256, FA_SMEM>>>(p_param);

    // 5) projection GEMM
    gemm128<0><<<dim3(Cn/128, Mn/128), 256>>>((const float*)yptr, w_proj, b_proj, out, Mn, Cn, Cn);
}

// round 2
// speedup vs baseline: 1.1887x; 1.1887x over previous
#include <cuda_runtime.h>
#include <math.h>

#define Bn 2
#define Tn 2048
#define Cn 1024
#define Hn 16
#define Dn 64
#define Mn (Bn*Tn)          // 4096
#define BHn (Bn*Hn)         // 32

typedef unsigned long long ull;

// Scratch (device globals; no runtime allocation allowed)
__device__ float g_Q[BHn*Tn*Dn];      // head-major [b,h,t,d]
__device__ float g_K[BHn*Tn*Dn];
__device__ float g_V[BHn*Tn*Dn];      // raw v after QKV; then exp(z - zmax) in-place
__device__ float g_zmax[Bn*Cn];
__device__ float g_Y[Mn*Cn];          // pre-proj activations

__device__ __forceinline__ float clamp_p(float pp) {
    float sgn = (pp >= 0.0f) ? 1.0f : -1.0f;
    return sgn * fminf(fmaxf(fabsf(pp), 1e-4f), 1e3f);
}

// ---- packed f32x2 helpers (Blackwell FFMA2 path) ----
__device__ __forceinline__ ull pk2(float lo, float hi) {
    ull r;
    asm("mov.b64 %0, {%1, %2};" : "=l"(r) : "f"(lo), "f"(hi));
    return r;
}
__device__ __forceinline__ float2 upk2(ull v) {
    float lo, hi;
    asm("mov.b64 {%0, %1}, %2;" : "=f"(lo), "=f"(hi) : "l"(v));
    return make_float2(lo, hi);
}
__device__ __forceinline__ ull ffma2(ull a, ull b, ull c) {
    ull d;
    asm("fma.rn.f32x2 %0, %1, %2, %3;" : "=l"(d) : "l"(a), "l"(b), "l"(c));
    return d;
}
__device__ __forceinline__ ull fmul2(ull a, ull b) {
    ull d;
    asm("mul.rn.f32x2 %0, %1, %2;" : "=l"(d) : "l"(a), "l"(b));
    return d;
}

// ---------------------------------------------------------------------------
// Tiled fp32 GEMM with f32x2 packed FMA: C[M,N] = A[M,K] @ B[K,N] + bias
// BM=BN=128, BK=16, 256 threads, 8x8 microtile.
// MODE 0: write Cout directly.  MODE 1: scatter qkv into g_Q/g_K/g_V.
// ---------------------------------------------------------------------------
template<int MODE>
__global__ __launch_bounds__(256) void gemm128(
    const float* __restrict__ A, const float* __restrict__ Bw,
    const float* __restrict__ bias, float* __restrict__ Cout,
    int M, int N, int K)
{
    __shared__ float As[16*128];   // As[k][m] (transposed)
    __shared__ float Bs[16*128];   // Bs[k][n]

    const int tid = threadIdx.x;
    const int bm = blockIdx.y, bn = blockIdx.x;
    const int tr = tid >> 4, tc = tid & 15;
    const int m0 = tr * 8, n0 = tc * 8;

    ull acc2[8][4];
#pragma unroll
    for (int i = 0; i < 8; i++)
#pragma unroll
        for (int j = 0; j < 4; j++) acc2[i][j] = 0ull;

    for (int k0 = 0; k0 < K; k0 += 16) {
#pragma unroll
        for (int l = tid; l < 512; l += 256) {
            int row = l >> 2, c4 = l & 3;
            float4 a = *(const float4*)(A + (size_t)(bm*128 + row)*K + k0 + c4*4);
            As[(c4*4+0)*128 + row] = a.x;
            As[(c4*4+1)*128 + row] = a.y;
            As[(c4*4+2)*128 + row] = a.z;
            As[(c4*4+3)*128 + row] = a.w;
        }
#pragma unroll
        for (int l = tid; l < 512; l += 256) {
            int row = l >> 5, cb = l & 31;
            float4 b = *(const float4*)(Bw + (size_t)(k0 + row)*N + bn*128 + cb*4);
            *(float4*)(Bs + row*128 + cb*4) = b;
        }
        __syncthreads();

#pragma unroll
        for (int kk = 0; kk < 16; kk++) {
            float4 a0 = *(const float4*)(As + kk*128 + m0);
            float4 a1 = *(const float4*)(As + kk*128 + m0 + 4);
            float4 b0 = *(const float4*)(Bs + kk*128 + n0);
            float4 b1 = *(const float4*)(Bs + kk*128 + n0 + 4);
            ull bp[4] = {pk2(b0.x,b0.y), pk2(b0.z,b0.w), pk2(b1.x,b1.y), pk2(b1.z,b1.w)};
            float av[8] = {a0.x,a0.y,a0.z,a0.w,a1.x,a1.y,a1.z,a1.w};
#pragma unroll
            for (int i = 0; i < 8; i++) {
                ull ap = pk2(av[i], av[i]);
#pragma unroll
                for (int j = 0; j < 4; j++)
                    acc2[i][j] = ffma2(ap, bp[j], acc2[i][j]);
            }
        }
        __syncthreads();
    }

    if (MODE == 0) {
#pragma unroll
        for (int i = 0; i < 8; i++) {
            int m = bm*128 + m0 + i;
            float2 u0 = upk2(acc2[i][0]), u1 = upk2(acc2[i][1]);
            float2 u2 = upk2(acc2[i][2]), u3 = upk2(acc2[i][3]);
            int n = bn*128 + n0;
            float4 o0, o1;
            o0.x = u0.x + bias[n+0]; o0.y = u0.y + bias[n+1];
            o0.z = u1.x + bias[n+2]; o0.w = u1.y + bias[n+3];
            o1.x = u2.x + bias[n+4]; o1.y = u2.y + bias[n+5];
            o1.z = u3.x + bias[n+6]; o1.w = u3.y + bias[n+7];
            *(float4*)(Cout + (size_t)m*N + n)     = o0;
            *(float4*)(Cout + (size_t)m*N + n + 4) = o1;
        }
    } else {
#pragma unroll
        for (int i = 0; i < 8; i++) {
            int m = bm*128 + m0 + i;
            int b = m >> 11;
            int t = m & 2047;
            float vals[8];
            float2 u0 = upk2(acc2[i][0]), u1 = upk2(acc2[i][1]);
            float2 u2 = upk2(acc2[i][2]), u3 = upk2(acc2[i][3]);
            vals[0]=u0.x; vals[1]=u0.y; vals[2]=u1.x; vals[3]=u1.y;
            vals[4]=u2.x; vals[5]=u2.y; vals[6]=u3.x; vals[7]=u3.y;
#pragma unroll
            for (int j = 0; j < 8; j++) {
                int n = bn*128 + n0 + j;
                float val = vals[j] + bias[n];
                int sec = n >> 10;      // 0=q,1=k,2=v
                int c   = n & 1023;
                int h   = c >> 6;
                int dd  = c & 63;
                int idx = ((b*Hn + h)*Tn + t)*64 + dd;
                if (sec == 0)      g_Q[idx] = val;
                else if (sec == 1) g_K[idx] = val;
                else               g_V[idx] = val;
            }
        }
    }
}

// ---------------------------------------------------------------------------
// z_max over T per (b, c)
// ---------------------------------------------------------------------------
__global__ __launch_bounds__(256) void zmax_kernel(const float* __restrict__ p_param)
{
    int bh = blockIdx.x;
    int b = bh >> 4, h = bh & 15;
    int dd = threadIdx.x & 63;
    int g  = threadIdx.x >> 6;
    int c  = h*64 + dd;
    float pv = clamp_p(p_param[c]);

    const float* vp = g_V + (size_t)bh * Tn * 64;
    float mx = -1e30f;
    for (int t = g; t < Tn; t += 4) {
        float v = vp[t*64 + dd];
        float z = pv * logf(fmaxf(fabsf(v + 5.0f), 1e-10f));
        mx = fmaxf(mx, z);
    }
    __shared__ float red[256];
    red[threadIdx.x] = mx;
    __syncthreads();
    if (g == 0) {
        mx = fmaxf(fmaxf(red[dd], red[64+dd]), fmaxf(red[128+dd], red[192+dd]));
        g_zmax[b*Cn + c] = mx;
    }
}

// ---------------------------------------------------------------------------
// V transform in-place: v = exp(p*log(clip(|v+5|)) - zmax)
// ---------------------------------------------------------------------------
__global__ __launch_bounds__(256) void vexp_kernel(const float* __restrict__ p_param)
{
    int idx = blockIdx.x * 256 + threadIdx.x;
    int dd = idx & 63;
    int bh = idx >> 17;
    int h = bh & 15, b = bh >> 4;
    int c = h*64 + dd;
    float pv = clamp_p(p_param[c]);
    float v = g_V[idx];
    float z = pv * logf(fmaxf(fabsf(v + 5.0f), 1e-10f));
    g_V[idx] = expf(z - g_zmax[b*Cn + c]);
}

// ---------------------------------------------------------------------------
// Flash attention (causal), BQ=BK=128, 256 threads, 8x8 microtile,
// register softmax with shuffle reductions, f32x2 packed FMA,
// fused inverse power-mean epilogue.
// Thread (tr=tid>>4, tc=tid&15): owns S rows {4tr..4tr+3, 64+4tr..+3},
// S cols {4tc..4tc+3, 64+4tc..+3}, O d-cols {4tc..4tc+3}.
// ---------------------------------------------------------------------------
#define PS 132
#define FA_SMEM ((64*PS + 64*PS + 128*64 + 128*PS) * 4)   // ~168 KB

__global__ __launch_bounds__(256) void fa_kernel(const float* __restrict__ p_param)
{
    extern __shared__ float sm[];
    float* Qs = sm;                  // [64][PS] : Qs[d][r]
    float* Ks = Qs + 64*PS;          // [64][PS] : Ks[d][c]
    float* Vs = Ks + 64*PS;          // [128][64]: Vs[k][d]
    float* Ps = Vs + 128*64;         // [128][PS]: Ps[r][k]

    const int tid = threadIdx.x;
    const int bh  = blockIdx.y;
    const int b = bh >> 4, h = bh & 15;
    const int qt = (int)gridDim.x - 1 - (int)blockIdx.x;   // heavy tiles first
    const int q0 = qt * 128;
    const int tr = tid >> 4;
    const int tc = tid & 15;
    const int rA = tr * 4;
    const int cA = tc * 4;
    const float scale = 0.125f;

    // ---- load Q tile transposed (rows = seq, store [d][r]) ----
    const float* Qg = g_Q + ((size_t)bh * Tn + q0) * 64;
#pragma unroll
    for (int it = 0; it < 8; it++) {
        int idx = tid + it*256;          // 0..2047 float4s
        int row = idx & 127;
        int d4  = idx >> 7;              // 0..15
        float4 v = *(const float4*)(Qg + row*64 + d4*4);
        Qs[(d4*4+0)*PS + row] = v.x;
        Qs[(d4*4+1)*PS + row] = v.y;
        Qs[(d4*4+2)*PS + row] = v.z;
        Qs[(d4*4+3)*PS + row] = v.w;
    }

    float m_i[8], l_i[8];
    ull O2[8][2];
#pragma unroll
    for (int i = 0; i < 8; i++) {
        m_i[i] = -1e30f; l_i[i] = 0.0f;
        O2[i][0] = 0ull; O2[i][1] = 0ull;
    }

    for (int kt = 0; kt <= qt; kt++) {
        const float* Kg = g_K + ((size_t)bh * Tn + kt*128) * 64;
        const float* Vg = g_V + ((size_t)bh * Tn + kt*128) * 64;
        // K transposed
#pragma unroll
        for (int it = 0; it < 8; it++) {
            int idx = tid + it*256;
            int row = idx & 127;
            int d4  = idx >> 7;
            float4 v = *(const float4*)(Kg + row*64 + d4*4);
            Ks[(d4*4+0)*PS + row] = v.x;
            Ks[(d4*4+1)*PS + row] = v.y;
            Ks[(d4*4+2)*PS + row] = v.z;
            Ks[(d4*4+3)*PS + row] = v.w;
        }
        // V straight (coalesced)
#pragma unroll
        for (int it = 0; it < 8; it++) {
            int idx = tid + it*256;
            int row = idx >> 4;
            int c4  = idx & 15;
            *(float4*)(Vs + row*64 + c4*4) = *(const float4*)(Vg + row*64 + c4*4);
        }
        __syncthreads();

        // ---- S = Q K^T over d=64 ----
        ull acc2[8][4];
#pragma unroll
        for (int i = 0; i < 8; i++)
#pragma unroll
            for (int j = 0; j < 4; j++) acc2[i][j] = 0ull;

#pragma unroll 4
        for (int d = 0; d < 64; d++) {
            float4 qa0 = *(const float4*)(Qs + d*PS + rA);
            float4 qa1 = *(const float4*)(Qs + d*PS + 64 + rA);
            float4 kb0 = *(const float4*)(Ks + d*PS + cA);
            float4 kb1 = *(const float4*)(Ks + d*PS + 64 + cA);
            ull bp[4] = {pk2(kb0.x,kb0.y), pk2(kb0.z,kb0.w),
                         pk2(kb1.x,kb1.y), pk2(kb1.z,kb1.w)};
            float av[8] = {qa0.x,qa0.y,qa0.z,qa0.w,qa1.x,qa1.y,qa1.z,qa1.w};
#pragma unroll
            for (int i = 0; i < 8; i++) {
                ull ap = pk2(av[i], av[i]);
#pragma unroll
                for (int j = 0; j < 4; j++)
                    acc2[i][j] = ffma2(ap, bp[j], acc2[i][j]);
            }
        }

        // ---- unpack, scale, mask ----
        float s[8][8];
#pragma unroll
        for (int i = 0; i < 8; i++) {
#pragma unroll
            for (int j4 = 0; j4 < 4; j4++) {
                float2 u = upk2(acc2[i][j4]);
                s[i][2*j4]   = u.x * scale;
                s[i][2*j4+1] = u.y * scale;
            }
        }
        if (kt == qt) {
            // mask cols > rows within diagonal tile (local indices suffice)
#pragma unroll
            for (int i = 0; i < 8; i++) {
                int rloc = (i < 4) ? (rA + i) : (64 + rA + i - 4);
#pragma unroll
                for (int jj = 0; jj < 8; jj++) {
                    // s[i][jj] pairs: jj 0,1 -> cols cA,cA+1; jj 2,3 -> cA+2,3;
                    // jj 4..7 -> 64+cA..+3
                    int cloc = (jj < 4) ? (cA + jj) : (64 + cA + jj - 4);
                    if (cloc > rloc) s[i][jj] = -1e30f;
                }
            }
        }

        // ---- register softmax with shuffle reductions (16-lane groups) ----
#pragma unroll
        for (int i = 0; i < 8; i++) {
            float mx = s[i][0];
#pragma unroll
            for (int jj = 1; jj < 8; jj++) mx = fmaxf(mx, s[i][jj]);
#pragma unroll
            for (int off = 1; off < 16; off <<= 1)
                mx = fmaxf(mx, __shfl_xor_sync(0xffffffffu, mx, off));
            float alpha = __expf(m_i[i] - mx);
            m_i[i] = mx;
            float sum = 0.0f;
#pragma unroll
            for (int jj = 0; jj < 8; jj++) {
                float pe = __expf(s[i][jj] - mx);
                s[i][jj] = pe;
                sum += pe;
            }
#pragma unroll
            for (int off = 1; off < 16; off <<= 1)
                sum += __shfl_xor_sync(0xffffffffu, sum, off);
            l_i[i] = l_i[i] * alpha + sum;
            ull a2 = pk2(alpha, alpha);
            O2[i][0] = fmul2(O2[i][0], a2);
            O2[i][1] = fmul2(O2[i][1], a2);
        }

        __syncthreads();   // prev-iter P reads done (guaranteed by loop-end sync) -> safe to write

        // ---- write P to shared (row-major, float4 over k) ----
#pragma unroll
        for (int i = 0; i < 8; i++) {
            int r = (i < 4) ? (rA + i) : (64 + rA + i - 4);
            float4 p0 = make_float4(s[i][0], s[i][1], s[i][2], s[i][3]);
            float4 p1 = make_float4(s[i][4], s[i][5], s[i][6], s[i][7]);
            *(float4*)(Ps + r*PS + cA)      = p0;
            *(float4*)(Ps + r*PS + 64 + cA) = p1;
        }
        __syncthreads();

        // ---- O += P @ V ----
#pragma unroll 2
        for (int k0 = 0; k0 < 128; k0 += 4) {
            float4 pa[8];
#pragma unroll
            for (int i = 0; i < 8; i++) {
                int r = (i < 4) ? (rA + i) : (64 + rA + i - 4);
                pa[i] = *(const float4*)(Ps + r*PS + k0);
            }
#pragma unroll
            for (int kk = 0; kk < 4; kk++) {
                float4 vv = *(const float4*)(Vs + (k0+kk)*64 + cA);
                ull v2a = pk2(vv.x, vv.y);
                ull v2b = pk2(vv.z, vv.w);
#pragma unroll
                for (int i = 0; i < 8; i++) {
                    float pv = (kk == 0) ? pa[i].x : (kk == 1) ? pa[i].y :
                               (kk == 2) ? pa[i].z : pa[i].w;
                    ull p2 = pk2(pv, pv);
                    O2[i][0] = ffma2(p2, v2a, O2[i][0]);
                    O2[i][1] = ffma2(p2, v2b, O2[i][1]);
                }
            }
        }
        __syncthreads();
    }

    // ---- epilogue: mean = O/l; y = exp((zmax + log(mean))/p) - SHIFT ----
#pragma unroll
    for (int i = 0; i < 8; i++) {
        int r = (i < 4) ? (rA + i) : (64 + rA + i - 4);
        int t = q0 + r;
        float linv = 1.0f / l_i[i];
        float2 o0 = upk2(O2[i][0]), o1 = upk2(O2[i][1]);
        float ov[4] = {o0.x, o0.y, o1.x, o1.y};
#pragma unroll
        for (int j = 0; j < 4; j++) {
            int dd = cA + j;
            int cg = h*64 + dd;
            float pv = clamp_p(p_param[cg]);
            float zm = g_zmax[b*Cn + cg];
            float mean = ov[j] * linv;
            float y = expf((zm + logf(mean)) / pv) - 5.0f;
            g_Y[(size_t)(b*Tn + t)*Cn + cg] = y;
        }
    }
}

// ---------------------------------------------------------------------------

extern "C" void kernel_launch(void* const* d_in, const int* in_sizes, int n_in,
                              void* d_out, int out_size)
{
    const float* x       = (const float*)d_in[0];
    const float* w_attn  = (const float*)d_in[1];
    const float* b_attn  = (const float*)d_in[2];
    const float* w_proj  = (const float*)d_in[3];
    const float* b_proj  = (const float*)d_in[4];
    const float* p_param = (const float*)d_in[5];
    float* out = (float*)d_out;

    void* yptr = nullptr;
    cudaGetSymbolAddress(&yptr, g_Y);

    cudaFuncSetAttribute(fa_kernel, cudaFuncAttributeMaxDynamicSharedMemorySize, FA_SMEM);

    // 1) QKV GEMM + scatter into head-major Q/K/V
    gemm128<1><<<dim3(3072/128, Mn/128), 256>>>(x, w_attn, b_attn, nullptr, Mn, 3072, Cn);

    // 2) z_max reduction over T
    zmax_kernel<<<BHn, 256>>>(p_param);

    // 3) V power transform in-place
    vexp_kernel<<<(BHn*Tn*Dn)/256, 256>>>(p_param);

    // 4) causal flash attention + fused inverse power-mean epilogue
    fa_kernel<<<dim3(Tn/128, BHn), 256, FA_SMEM>>>(p_param);

    // 5) projection GEMM
    gemm128<0><<<dim3(Cn/128, Mn/128), 256>>>((const float*)yptr, w_proj, b_proj, out, Mn, Cn, Cn);
}

// round 4
// speedup vs baseline: 1.9284x; 1.6223x over previous
#include <cuda_runtime.h>
#include <cuda_bf16.h>
#include <math.h>
#include <stdint.h>

#define Bn 2
#define Tn 2048
#define Cn 1024
#define Hn 16
#define Dn 64
#define Mn (Bn*Tn)          // 4096
#define BHn (Bn*Hn)         // 32

typedef unsigned long long ull;

// ---------------- device scratch ----------------
__device__ float g_Q[BHn*Tn*Dn];
__device__ float g_K[BHn*Tn*Dn];
__device__ float g_V[BHn*Tn*Dn];
__device__ float g_zmax[Bn*Cn];
__device__ float g_Y[Mn*Cn];
__device__ __nv_bfloat16 gA_hi[Mn*Cn];       // split A operand (x, then Y)
__device__ __nv_bfloat16 gA_lo[Mn*Cn];
__device__ __nv_bfloat16 gBT_hi[3*Cn*Cn];    // split+transposed weights [N][K]
__device__ __nv_bfloat16 gBT_lo[3*Cn*Cn];

__device__ __forceinline__ float clamp_p(float pp) {
    float sgn = (pp >= 0.0f) ? 1.0f : -1.0f;
    return sgn * fminf(fmaxf(fabsf(pp), 1e-4f), 1e3f);
}

// ---------------- ptx helpers ----------------
__device__ __forceinline__ uint32_t smem_u32(const void* p) {
    uint32_t a;
    asm("{ .reg .u64 t; cvta.to.shared.u64 t, %1; cvt.u32.u64 %0, t; }" : "=r"(a) : "l"(p));
    return a;
}
__device__ __forceinline__ void cp16(uint32_t dst, const void* src) {
    asm volatile("cp.async.cg.shared.global [%0], [%1], 16;\n" :: "r"(dst), "l"(src));
}
#define CP_COMMIT() asm volatile("cp.async.commit_group;\n" ::: "memory")

__device__ __forceinline__ void ldsm4(uint32_t& r0, uint32_t& r1, uint32_t& r2, uint32_t& r3,
                                      uint32_t addr) {
    asm volatile("ldmatrix.sync.aligned.m8n8.x4.shared.b16 {%0,%1,%2,%3}, [%4];"
                 : "=r"(r0), "=r"(r1), "=r"(r2), "=r"(r3) : "r"(addr));
}
__device__ __forceinline__ void ldsm2(uint32_t& r0, uint32_t& r1, uint32_t addr) {
    asm volatile("ldmatrix.sync.aligned.m8n8.x2.shared.b16 {%0,%1}, [%2];"
                 : "=r"(r0), "=r"(r1) : "r"(addr));
}
__device__ __forceinline__ void mma16816(float* c, const uint32_t* a, const uint32_t* b) {
    asm volatile(
        "mma.sync.aligned.m16n8k16.row.col.f32.bf16.bf16.f32 "
        "{%0,%1,%2,%3}, {%4,%5,%6,%7}, {%8,%9}, {%0,%1,%2,%3};"
        : "+f"(c[0]), "+f"(c[1]), "+f"(c[2]), "+f"(c[3])
        : "r"(a[0]), "r"(a[1]), "r"(a[2]), "r"(a[3]), "r"(b[0]), "r"(b[1]));
}

// ---------------- packed f32x2 (FA) ----------------
__device__ __forceinline__ ull pk2(float lo, float hi) {
    ull r; asm("mov.b64 %0, {%1, %2};" : "=l"(r) : "f"(lo), "f"(hi)); return r;
}
__device__ __forceinline__ float2 upk2(ull v) {
    float lo, hi; asm("mov.b64 {%0, %1}, %2;" : "=f"(lo), "=f"(hi) : "l"(v));
    return make_float2(lo, hi);
}
__device__ __forceinline__ ull ffma2(ull a, ull b, ull c) {
    ull d; asm("fma.rn.f32x2 %0, %1, %2, %3;" : "=l"(d) : "l"(a), "l"(b), "l"(c)); return d;
}
__device__ __forceinline__ ull fmul2(ull a, ull b) {
    ull d; asm("mul.rn.f32x2 %0, %1, %2;" : "=l"(d) : "l"(a), "l"(b)); return d;
}

// ---------------------------------------------------------------------------
// split: fp32 -> bf16 hi/lo (float4 per thread)
// ---------------------------------------------------------------------------
__global__ __launch_bounds__(256) void split_bf16(
    const float* __restrict__ A, __nv_bfloat16* __restrict__ Ah, __nv_bfloat16* __restrict__ Al)
{
    int i = blockIdx.x * 256 + threadIdx.x;
    float4 a = ((const float4*)A)[i];
    __nv_bfloat16 h0 = __float2bfloat16(a.x), h1 = __float2bfloat16(a.y);
    __nv_bfloat16 h2 = __float2bfloat16(a.z), h3 = __float2bfloat16(a.w);
    __nv_bfloat16 l0 = __float2bfloat16(a.x - __bfloat162float(h0));
    __nv_bfloat16 l1 = __float2bfloat16(a.y - __bfloat162float(h1));
    __nv_bfloat16 l2 = __float2bfloat16(a.z - __bfloat162float(h2));
    __nv_bfloat16 l3 = __float2bfloat16(a.w - __bfloat162float(h3));
    __nv_bfloat162 hh0 = {h0, h1}, hh1 = {h2, h3};
    __nv_bfloat162 ll0 = {l0, l1}, ll1 = {l2, l3};
    ((__nv_bfloat162*)Ah)[2*i]   = hh0;
    ((__nv_bfloat162*)Ah)[2*i+1] = hh1;
    ((__nv_bfloat162*)Al)[2*i]   = ll0;
    ((__nv_bfloat162*)Al)[2*i+1] = ll1;
}

// ---------------------------------------------------------------------------
// transpose + split: W[K=1024][Nd] -> Th/Tl[Nd][1024] (bf16)
// ---------------------------------------------------------------------------
__global__ void transpose_split(const float* __restrict__ W,
                                __nv_bfloat16* __restrict__ Th,
                                __nv_bfloat16* __restrict__ Tl, int Nd)
{
    __shared__ float tile[32][33];
    int nx = blockIdx.x * 32, kx = blockIdx.y * 32;
    int tx = threadIdx.x, ty = threadIdx.y;   // 32x8
#pragma unroll
    for (int r = ty; r < 32; r += 8)
        tile[r][tx] = W[(size_t)(kx + r) * Nd + nx + tx];
    __syncthreads();
#pragma unroll
    for (int r = ty; r < 32; r += 8) {
        float a = tile[tx][r];
        __nv_bfloat16 hi = __float2bfloat16(a);
        __nv_bfloat16 lo = __float2bfloat16(a - __bfloat162float(hi));
        size_t o = (size_t)(nx + r) * 1024 + kx + tx;
        Th[o] = hi; Tl[o] = lo;
    }
}

// ---------------------------------------------------------------------------
// bf16x3 mma.sync GEMM: D[128,128] tile, K=1024, BK=64, cp.async 2-stage.
// A[M][1024], B^T[N][1024] both bf16 hi/lo, K-major.
// MODE 0: Cout = D + bias.  MODE 1: scatter QKV into g_Q/g_K/g_V.
// ---------------------------------------------------------------------------
#define STG_BYTES 65536
#define AHI_OFF 0
#define ALO_OFF 16384
#define BHI_OFF 32768
#define BLO_OFF 49152
#define TCG_SMEM (2*STG_BYTES)

__device__ __forceinline__ void load_stage(
    uint32_t sbase,
    const __nv_bfloat16* __restrict__ Ah, const __nv_bfloat16* __restrict__ Al,
    const __nv_bfloat16* __restrict__ Bh, const __nv_bfloat16* __restrict__ Bl,
    int m0, int n0, int k0, int tid)
{
#pragma unroll
    for (int j = 0; j < 4; j++) {
        int idx = tid + j * 256;          // 0..1023
        int row = idx >> 3, c = idx & 7;  // row 0..127, 16B chunk 0..7
        uint32_t sw = row * 128 + ((c ^ (row & 7)) << 4);
        size_t ga = (size_t)(m0 + row) * 1024 + k0 + c * 8;
        size_t gb = (size_t)(n0 + row) * 1024 + k0 + c * 8;
        cp16(sbase + AHI_OFF + sw, Ah + ga);
        cp16(sbase + ALO_OFF + sw, Al + ga);
        cp16(sbase + BHI_OFF + sw, Bh + gb);
        cp16(sbase + BLO_OFF + sw, Bl + gb);
    }
}

template<int MODE>
__global__ __launch_bounds__(256) void tc_gemm(
    const __nv_bfloat16* __restrict__ Ah, const __nv_bfloat16* __restrict__ Al,
    const __nv_bfloat16* __restrict__ Bh, const __nv_bfloat16* __restrict__ Bl,
    const float* __restrict__ bias, float* __restrict__ Cout)
{
    extern __shared__ char smem[];
    uint32_t sb = smem_u32(smem);
    const int tid  = threadIdx.x;
    const int wid  = tid >> 5;
    const int lane = tid & 31;
    const int wm = wid & 1;        // 2 warp-rows of 64
    const int wn = wid >> 1;       // 4 warp-cols of 32
    const int m0 = blockIdx.y * 128;
    const int n0 = blockIdx.x * 128;

    float acc[4][4][4];
#pragma unroll
    for (int i = 0; i < 4; i++)
#pragma unroll
        for (int j = 0; j < 4; j++)
#pragma unroll
            for (int q = 0; q < 4; q++) acc[i][j][q] = 0.0f;

    load_stage(sb,             Ah, Al, Bh, Bl, m0, n0, 0,  tid); CP_COMMIT();
    load_stage(sb + STG_BYTES, Ah, Al, Bh, Bl, m0, n0, 64, tid); CP_COMMIT();

    // precomputed ldmatrix lane offsets
    const int a_row = wm * 64 + (lane & 15);        // + mf*16
    const int a_c16 = (lane >> 4);                  // + ks*2
    const int b_row = wn * 32 + (lane & 7);         // + nf*8
    const int b_c16 = ((lane >> 3) & 1);            // + ks*2

    for (int it = 0; it < 16; it++) {
        const int s = it & 1;
        const uint32_t sbase = sb + s * STG_BYTES;
        if (it < 15) asm volatile("cp.async.wait_group 1;\n" ::: "memory");
        else         asm volatile("cp.async.wait_group 0;\n" ::: "memory");
        __syncthreads();

#pragma unroll
        for (int ks = 0; ks < 4; ks++) {
            uint32_t ahi[4][4], alo[4][4], bhi[4][2], blo[4][2];
#pragma unroll
            for (int mf = 0; mf < 4; mf++) {
                int row = a_row + mf * 16;
                int c16 = ks * 2 + a_c16;
                uint32_t ad = sbase + row * 128 + ((c16 ^ (row & 7)) << 4);
                ldsm4(ahi[mf][0], ahi[mf][1], ahi[mf][2], ahi[mf][3], ad + AHI_OFF);
                ldsm4(alo[mf][0], alo[mf][1], alo[mf][2], alo[mf][3], ad + ALO_OFF);
            }
#pragma unroll
            for (int nf = 0; nf < 4; nf++) {
                int row = b_row + nf * 8;
                int c16 = ks * 2 + b_c16;
                uint32_t bd = sbase + row * 128 + ((c16 ^ (row & 7)) << 4);
                ldsm2(bhi[nf][0], bhi[nf][1], bd + BHI_OFF);
                ldsm2(blo[nf][0], blo[nf][1], bd + BLO_OFF);
            }
#pragma unroll
            for (int mf = 0; mf < 4; mf++)
#pragma unroll
                for (int nf = 0; nf < 4; nf++) {
                    mma16816(acc[mf][nf], ahi[mf], bhi[nf]);
                    mma16816(acc[mf][nf], alo[mf], bhi[nf]);
                    mma16816(acc[mf][nf], ahi[mf], blo[nf]);
                }
        }
        __syncthreads();
        if (it + 2 < 16) {
            load_stage(sbase, Ah, Al, Bh, Bl, m0, n0, (it + 2) * 64, tid);
            CP_COMMIT();
        }
    }

    // ---- epilogue ----
    const int mbase = m0 + wm * 64 + (lane >> 2);
    const int nbase = n0 + wn * 32 + (lane & 3) * 2;
#pragma unroll
    for (int mf = 0; mf < 4; mf++) {
#pragma unroll
        for (int half = 0; half < 2; half++) {
            int m = mbase + mf * 16 + half * 8;
#pragma unroll
            for (int nf = 0; nf < 4; nf++) {
                int n = nbase + nf * 8;
                float v0 = acc[mf][nf][half*2+0] + bias[n];
                float v1 = acc[mf][nf][half*2+1] + bias[n+1];
                if (MODE == 0) {
                    *(float2*)(Cout + (size_t)m * Cn + n) = make_float2(v0, v1);
                } else {
                    int sec = n >> 10;
                    int c1  = n & 1023;
                    int h   = c1 >> 6, dd = c1 & 63;
                    int bq  = m >> 11, t = m & 2047;
                    float* dst = (sec == 0 ? g_Q : sec == 1 ? g_K : g_V)
                                 + ((size_t)((bq * Hn + h) * Tn + t)) * 64 + dd;
                    *(float2*)dst = make_float2(v0, v1);
                }
            }
        }
    }
}

// ---------------------------------------------------------------------------
// z_max over T per (b, c)
// ---------------------------------------------------------------------------
__global__ __launch_bounds__(256) void zmax_kernel(const float* __restrict__ p_param)
{
    int bh = blockIdx.x;
    int b = bh >> 4, h = bh & 15;
    int dd = threadIdx.x & 63;
    int g  = threadIdx.x >> 6;
    int c  = h*64 + dd;
    float pv = clamp_p(p_param[c]);

    const float* vp = g_V + (size_t)bh * Tn * 64;
    float mx = -1e30f;
    for (int t = g; t < Tn; t += 4) {
        float v = vp[t*64 + dd];
        float z = pv * logf(fmaxf(fabsf(v + 5.0f), 1e-10f));
        mx = fmaxf(mx, z);
    }
    __shared__ float red[256];
    red[threadIdx.x] = mx;
    __syncthreads();
    if (g == 0) {
        mx = fmaxf(fmaxf(red[dd], red[64+dd]), fmaxf(red[128+dd], red[192+dd]));
        g_zmax[b*Cn + c] = mx;
    }
}

__global__ __launch_bounds__(256) void vexp_kernel(const float* __restrict__ p_param)
{
    int idx = blockIdx.x * 256 + threadIdx.x;
    int dd = idx & 63;
    int bh = idx >> 17;
    int h = bh & 15, b = bh >> 4;
    int c = h*64 + dd;
    float pv = clamp_p(p_param[c]);
    float v = g_V[idx];
    float z = pv * logf(fmaxf(fabsf(v + 5.0f), 1e-10f));
    g_V[idx] = expf(z - g_zmax[b*Cn + c]);
}

// ---------------------------------------------------------------------------
// Flash attention (causal), BQ=BK=128, 256 threads, 8x8 microtile,
// register softmax + shuffle reductions, f32x2 FMA, fused power-mean epilogue.
// ---------------------------------------------------------------------------
#define PS 132
#define FA_SMEM ((64*PS + 64*PS + 128*64 + 128*PS) * 4)

__global__ __launch_bounds__(256) void fa_kernel(const float* __restrict__ p_param)
{
    extern __shared__ float sm[];
    float* Qs = sm;
    float* Ks = Qs + 64*PS;
    float* Vs = Ks + 64*PS;
    float* Ps = Vs + 128*64;

    const int tid = threadIdx.x;
    const int bh  = blockIdx.y;
    const int b = bh >> 4, h = bh & 15;
    const int qt = (int)gridDim.x - 1 - (int)blockIdx.x;
    const int q0 = qt * 128;
    const int tr = tid >> 4;
    const int tc = tid & 15;
    const int rA = tr * 4;
    const int cA = tc * 4;
    const float scale = 0.125f;

    const float* Qg = g_Q + ((size_t)bh * Tn + q0) * 64;
#pragma unroll
    for (int it = 0; it < 8; it++) {
        int idx = tid + it*256;
        int row = idx & 127;
        int d4  = idx >> 7;
        float4 v = *(const float4*)(Qg + row*64 + d4*4);
        Qs[(d4*4+0)*PS + row] = v.x;
        Qs[(d4*4+1)*PS + row] = v.y;
        Qs[(d4*4+2)*PS + row] = v.z;
        Qs[(d4*4+3)*PS + row] = v.w;
    }

    float m_i[8], l_i[8];
    ull O2[8][2];
#pragma unroll
    for (int i = 0; i < 8; i++) {
        m_i[i] = -1e30f; l_i[i] = 0.0f;
        O2[i][0] = 0ull; O2[i][1] = 0ull;
    }

    for (int kt = 0; kt <= qt; kt++) {
        const float* Kg = g_K + ((size_t)bh * Tn + kt*128) * 64;
        const float* Vg = g_V + ((size_t)bh * Tn + kt*128) * 64;
#pragma unroll
        for (int it = 0; it < 8; it++) {
            int idx = tid + it*256;
            int row = idx & 127;
            int d4  = idx >> 7;
            float4 v = *(const float4*)(Kg + row*64 + d4*4);
            Ks[(d4*4+0)*PS + row] = v.x;
            Ks[(d4*4+1)*PS + row] = v.y;
            Ks[(d4*4+2)*PS + row] = v.z;
            Ks[(d4*4+3)*PS + row] = v.w;
        }
#pragma unroll
        for (int it = 0; it < 8; it++) {
            int idx = tid + it*256;
            int row = idx >> 4;
            int c4  = idx & 15;
            *(float4*)(Vs + row*64 + c4*4) = *(const float4*)(Vg + row*64 + c4*4);
        }
        __syncthreads();

        ull acc2[8][4];
#pragma unroll
        for (int i = 0; i < 8; i++)
#pragma unroll
            for (int j = 0; j < 4; j++) acc2[i][j] = 0ull;

#pragma unroll 4
        for (int d = 0; d < 64; d++) {
            float4 qa0 = *(const float4*)(Qs + d*PS + rA);
            float4 qa1 = *(const float4*)(Qs + d*PS + 64 + rA);
            float4 kb0 = *(const float4*)(Ks + d*PS + cA);
            float4 kb1 = *(const float4*)(Ks + d*PS + 64 + cA);
            ull bp[4] = {pk2(kb0.x,kb0.y), pk2(kb0.z,kb0.w),
                         pk2(kb1.x,kb1.y), pk2(kb1.z,kb1.w)};
            float av[8] = {qa0.x,qa0.y,qa0.z,qa0.w,qa1.x,qa1.y,qa1.z,qa1.w};
#pragma unroll
            for (int i = 0; i < 8; i++) {
                ull ap = pk2(av[i], av[i]);
#pragma unroll
                for (int j = 0; j < 4; j++)
                    acc2[i][j] = ffma2(ap, bp[j], acc2[i][j]);
            }
        }

        float s[8][8];
#pragma unroll
        for (int i = 0; i < 8; i++) {
#pragma unroll
            for (int j4 = 0; j4 < 4; j4++) {
                float2 u = upk2(acc2[i][j4]);
                s[i][2*j4]   = u.x * scale;
                s[i][2*j4+1] = u.y * scale;
            }
        }
        if (kt == qt) {
#pragma unroll
            for (int i = 0; i < 8; i++) {
                int rloc = (i < 4) ? (rA + i) : (64 + rA + i - 4);
#pragma unroll
                for (int jj = 0; jj < 8; jj++) {
                    int cloc = (jj < 4) ? (cA + jj) : (64 + cA + jj - 4);
                    if (cloc > rloc) s[i][jj] = -1e30f;
                }
            }
        }

#pragma unroll
        for (int i = 0; i < 8; i++) {
            float mx = s[i][0];
#pragma unroll
            for (int jj = 1; jj < 8; jj++) mx = fmaxf(mx, s[i][jj]);
#pragma unroll
            for (int off = 1; off < 16; off <<= 1)
                mx = fmaxf(mx, __shfl_xor_sync(0xffffffffu, mx, off));
            float alpha = __expf(m_i[i] - mx);
            m_i[i] = mx;
            float sum = 0.0f;
#pragma unroll
            for (int jj = 0; jj < 8; jj++) {
                float pe = __expf(s[i][jj] - mx);
                s[i][jj] = pe;
                sum += pe;
            }
#pragma unroll
            for (int off = 1; off < 16; off <<= 1)
                sum += __shfl_xor_sync(0xffffffffu, sum, off);
            l_i[i] = l_i[i] * alpha + sum;
            ull a2 = pk2(alpha, alpha);
            O2[i][0] = fmul2(O2[i][0], a2);
            O2[i][1] = fmul2(O2[i][1], a2);
        }

        __syncthreads();

#pragma unroll
        for (int i = 0; i < 8; i++) {
            int r = (i < 4) ? (rA + i) : (64 + rA + i - 4);
            float4 p0 = make_float4(s[i][0], s[i][1], s[i][2], s[i][3]);
            float4 p1 = make_float4(s[i][4], s[i][5], s[i][6], s[i][7]);
            *(float4*)(Ps + r*PS + cA)      = p0;
            *(float4*)(Ps + r*PS + 64 + cA) = p1;
        }
        __syncthreads();

#pragma unroll 2
        for (int k0 = 0; k0 < 128; k0 += 4) {
            float4 pa[8];
#pragma unroll
            for (int i = 0; i < 8; i++) {
                int r = (i < 4) ? (rA + i) : (64 + rA + i - 4);
                pa[i] = *(const float4*)(Ps + r*PS + k0);
            }
#pragma unroll
            for (int kk = 0; kk < 4; kk++) {
                float4 vv = *(const float4*)(Vs + (k0+kk)*64 + cA);
                ull v2a = pk2(vv.x, vv.y);
                ull v2b = pk2(vv.z, vv.w);
#pragma unroll
                for (int i = 0; i < 8; i++) {
                    float pv = (kk == 0) ? pa[i].x : (kk == 1) ? pa[i].y :
                               (kk == 2) ? pa[i].z : pa[i].w;
                    ull p2 = pk2(pv, pv);
                    O2[i][0] = ffma2(p2, v2a, O2[i][0]);
                    O2[i][1] = ffma2(p2, v2b, O2[i][1]);
                }
            }
        }
        __syncthreads();
    }

#pragma unroll
    for (int i = 0; i < 8; i++) {
        int r = (i < 4) ? (rA + i) : (64 + rA + i - 4);
        int t = q0 + r;
        float linv = 1.0f / l_i[i];
        float2 o0 = upk2(O2[i][0]), o1 = upk2(O2[i][1]);
        float ov[4] = {o0.x, o0.y, o1.x, o1.y};
#pragma unroll
        for (int j = 0; j < 4; j++) {
            int dd = cA + j;
            int cg = h*64 + dd;
            float pv = clamp_p(p_param[cg]);
            float zm = g_zmax[b*Cn + cg];
            float mean = ov[j] * linv;
            float y = expf((zm + logf(mean)) / pv) - 5.0f;
            g_Y[(size_t)(b*Tn + t)*Cn + cg] = y;
        }
    }
}

// ---------------------------------------------------------------------------

extern "C" void kernel_launch(void* const* d_in, const int* in_sizes, int n_in,
                              void* d_out, int out_size)
{
    const float* x       = (const float*)d_in[0];
    const float* w_attn  = (const float*)d_in[1];
    const float* b_attn  = (const float*)d_in[2];
    const float* w_proj  = (const float*)d_in[3];
    const float* b_proj  = (const float*)d_in[4];
    const float* p_param = (const float*)d_in[5];
    float* out = (float*)d_out;

    void *yptr, *ah, *al, *bth, *btl;
    cudaGetSymbolAddress(&yptr, g_Y);
    cudaGetSymbolAddress(&ah,  gA_hi);
    cudaGetSymbolAddress(&al,  gA_lo);
    cudaGetSymbolAddress(&bth, gBT_hi);
    cudaGetSymbolAddress(&btl, gBT_lo);

    cudaFuncSetAttribute(fa_kernel, cudaFuncAttributeMaxDynamicSharedMemorySize, FA_SMEM);
    cudaFuncSetAttribute(tc_gemm<0>, cudaFuncAttributeMaxDynamicSharedMemorySize, TCG_SMEM);
    cudaFuncSetAttribute(tc_gemm<1>, cudaFuncAttributeMaxDynamicSharedMemorySize, TCG_SMEM);

    // 1) split x; transpose+split w_attn (bf16 hi/lo)
    split_bf16<<<Mn*Cn/1024, 256>>>(x, (__nv_bfloat16*)ah, (__nv_bfloat16*)al);
    transpose_split<<<dim3(3072/32, Cn/32), dim3(32,8)>>>(
        w_attn, (__nv_bfloat16*)bth, (__nv_bfloat16*)btl, 3072);

    // 2) QKV GEMM (bf16x3 mma.sync) + head-major scatter
    tc_gemm<1><<<dim3(3072/128, Mn/128), 256, TCG_SMEM>>>(
        (const __nv_bfloat16*)ah, (const __nv_bfloat16*)al,
        (const __nv_bfloat16*)bth, (const __nv_bfloat16*)btl, b_attn, nullptr);

    // 3) z_max + V power transform
    zmax_kernel<<<BHn, 256>>>(p_param);
    vexp_kernel<<<(BHn*Tn*Dn)/256, 256>>>(p_param);

    // 4) causal flash attention + fused inverse power-mean epilogue
    fa_kernel<<<dim3(Tn/128, BHn), 256, FA_SMEM>>>(p_param);

    // 5) split Y; transpose+split w_proj; proj GEMM
    split_bf16<<<Mn*Cn/1024, 256>>>((const float*)yptr, (__nv_bfloat16*)ah, (__nv_bfloat16*)al);
    transpose_split<<<dim3(Cn/32, Cn/32), dim3(32,8)>>>(
        w_proj, (__nv_bfloat16*)bth, (__nv_bfloat16*)btl, Cn);
    tc_gemm<0><<<dim3(Cn/128, Mn/128), 256, TCG_SMEM>>>(
        (const __nv_bfloat16*)ah, (const __nv_bfloat16*)al,
        (const __nv_bfloat16*)bth, (const __nv_bfloat16*)btl, b_proj, out);
}

// round 5
// speedup vs baseline: 3.2514x; 1.6861x over previous
#include <cuda_runtime.h>
#include <cuda_bf16.h>
#include <math.h>
#include <stdint.h>

#define Bn 2
#define Tn 2048
#define Cn 1024
#define Hn 16
#define Dn 64
#define Mn (Bn*Tn)          // 4096
#define BHn (Bn*Hn)         // 32

typedef unsigned long long ull;

// ---------------- device scratch ----------------
__device__ __nv_bfloat16 g_Qh[BHn*Tn*Dn];   // head-major, pre-scaled by 0.125
__device__ __nv_bfloat16 g_Ql[BHn*Tn*Dn];
__device__ __nv_bfloat16 g_Kh[BHn*Tn*Dn];
__device__ __nv_bfloat16 g_Kl[BHn*Tn*Dn];
__device__ float         g_V [BHn*Tn*Dn];   // raw v (fp32) for zmax
__device__ __nv_bfloat16 g_Vh[BHn*Tn*Dn];   // exp(z - zmax) hi/lo
__device__ __nv_bfloat16 g_Vl[BHn*Tn*Dn];
__device__ float g_zmax[Bn*Cn];
__device__ float g_zpart[8*Bn*Cn];
__device__ float g_Y[Mn*Cn];
__device__ __nv_bfloat16 gA_hi[Mn*Cn];
__device__ __nv_bfloat16 gA_lo[Mn*Cn];
__device__ __nv_bfloat16 gBT_hi[3*Cn*Cn];
__device__ __nv_bfloat16 gBT_lo[3*Cn*Cn];

__device__ __forceinline__ float clamp_p(float pp) {
    float sgn = (pp >= 0.0f) ? 1.0f : -1.0f;
    return sgn * fminf(fmaxf(fabsf(pp), 1e-4f), 1e3f);
}

// ---------------- ptx helpers ----------------
__device__ __forceinline__ uint32_t smem_u32(const void* p) {
    uint32_t a;
    asm("{ .reg .u64 t; cvta.to.shared.u64 t, %1; cvt.u32.u64 %0, t; }" : "=r"(a) : "l"(p));
    return a;
}
__device__ __forceinline__ void cp16(uint32_t dst, const void* src) {
    asm volatile("cp.async.cg.shared.global [%0], [%1], 16;\n" :: "r"(dst), "l"(src));
}
#define CP_COMMIT() asm volatile("cp.async.commit_group;\n" ::: "memory")

__device__ __forceinline__ void ldsm4(uint32_t& r0, uint32_t& r1, uint32_t& r2, uint32_t& r3,
                                      uint32_t addr) {
    asm volatile("ldmatrix.sync.aligned.m8n8.x4.shared.b16 {%0,%1,%2,%3}, [%4];"
                 : "=r"(r0), "=r"(r1), "=r"(r2), "=r"(r3) : "r"(addr));
}
__device__ __forceinline__ void ldsm2(uint32_t& r0, uint32_t& r1, uint32_t addr) {
    asm volatile("ldmatrix.sync.aligned.m8n8.x2.shared.b16 {%0,%1}, [%2];"
                 : "=r"(r0), "=r"(r1) : "r"(addr));
}
__device__ __forceinline__ void ldsm2t(uint32_t& r0, uint32_t& r1, uint32_t addr) {
    asm volatile("ldmatrix.sync.aligned.m8n8.x2.trans.shared.b16 {%0,%1}, [%2];"
                 : "=r"(r0), "=r"(r1) : "r"(addr));
}
__device__ __forceinline__ void mma16816(float* c, const uint32_t* a, const uint32_t* b) {
    asm volatile(
        "mma.sync.aligned.m16n8k16.row.col.f32.bf16.bf16.f32 "
        "{%0,%1,%2,%3}, {%4,%5,%6,%7}, {%8,%9}, {%0,%1,%2,%3};"
        : "+f"(c[0]), "+f"(c[1]), "+f"(c[2]), "+f"(c[3])
        : "r"(a[0]), "r"(a[1]), "r"(a[2]), "r"(a[3]), "r"(b[0]), "r"(b[1]));
}
// pack (lo, hi) floats -> bf16x2 register
__device__ __forceinline__ uint32_t pkbf(float lo, float hi) {
    uint32_t r;
    asm("cvt.rn.bf16x2.f32 %0, %1, %2;" : "=r"(r) : "f"(hi), "f"(lo));
    return r;
}

// ---------------------------------------------------------------------------
// split: fp32 -> bf16 hi/lo
// ---------------------------------------------------------------------------
__global__ __launch_bounds__(256) void split_bf16(
    const float* __restrict__ A, __nv_bfloat16* __restrict__ Ah, __nv_bfloat16* __restrict__ Al)
{
    int i = blockIdx.x * 256 + threadIdx.x;
    float4 a = ((const float4*)A)[i];
    uint32_t h0 = pkbf(a.x, a.y), h1 = pkbf(a.z, a.w);
    float f0 = __uint_as_float(h0 << 16), f1 = __uint_as_float(h0 & 0xffff0000u);
    float f2 = __uint_as_float(h1 << 16), f3 = __uint_as_float(h1 & 0xffff0000u);
    uint32_t l0 = pkbf(a.x - f0, a.y - f1), l1 = pkbf(a.z - f2, a.w - f3);
    ((uint32_t*)Ah)[2*i]   = h0;
    ((uint32_t*)Ah)[2*i+1] = h1;
    ((uint32_t*)Al)[2*i]   = l0;
    ((uint32_t*)Al)[2*i+1] = l1;
}

// ---------------------------------------------------------------------------
// transpose + split: W[K=1024][Nd] -> Th/Tl[Nd][1024] (bf16)
// ---------------------------------------------------------------------------
__global__ void transpose_split(const float* __restrict__ W,
                                __nv_bfloat16* __restrict__ Th,
                                __nv_bfloat16* __restrict__ Tl, int Nd)
{
    __shared__ float tile[32][33];
    int nx = blockIdx.x * 32, kx = blockIdx.y * 32;
    int tx = threadIdx.x, ty = threadIdx.y;
#pragma unroll
    for (int r = ty; r < 32; r += 8)
        tile[r][tx] = W[(size_t)(kx + r) * Nd + nx + tx];
    __syncthreads();
#pragma unroll
    for (int r = ty; r < 32; r += 8) {
        float a = tile[tx][r];
        __nv_bfloat16 hi = __float2bfloat16(a);
        __nv_bfloat16 lo = __float2bfloat16(a - __bfloat162float(hi));
        size_t o = (size_t)(nx + r) * 1024 + kx + tx;
        Th[o] = hi; Tl[o] = lo;
    }
}

// ---------------------------------------------------------------------------
// bf16x3 mma.sync GEMM (as round 4) — MODE 1 now writes Q/K bf16 hi/lo + V fp32
// ---------------------------------------------------------------------------
#define STG_BYTES 65536
#define AHI_OFF 0
#define ALO_OFF 16384
#define BHI_OFF 32768
#define BLO_OFF 49152
#define TCG_SMEM (2*STG_BYTES)

__device__ __forceinline__ void load_stage(
    uint32_t sbase,
    const __nv_bfloat16* __restrict__ Ah, const __nv_bfloat16* __restrict__ Al,
    const __nv_bfloat16* __restrict__ Bh, const __nv_bfloat16* __restrict__ Bl,
    int m0, int n0, int k0, int tid)
{
#pragma unroll
    for (int j = 0; j < 4; j++) {
        int idx = tid + j * 256;
        int row = idx >> 3, c = idx & 7;
        uint32_t sw = row * 128 + ((c ^ (row & 7)) << 4);
        size_t ga = (size_t)(m0 + row) * 1024 + k0 + c * 8;
        size_t gb = (size_t)(n0 + row) * 1024 + k0 + c * 8;
        cp16(sbase + AHI_OFF + sw, Ah + ga);
        cp16(sbase + ALO_OFF + sw, Al + ga);
        cp16(sbase + BHI_OFF + sw, Bh + gb);
        cp16(sbase + BLO_OFF + sw, Bl + gb);
    }
}

template<int MODE>
__global__ __launch_bounds__(256) void tc_gemm(
    const __nv_bfloat16* __restrict__ Ah, const __nv_bfloat16* __restrict__ Al,
    const __nv_bfloat16* __restrict__ Bh, const __nv_bfloat16* __restrict__ Bl,
    const float* __restrict__ bias, float* __restrict__ Cout)
{
    extern __shared__ char smem[];
    uint32_t sb = smem_u32(smem);
    const int tid  = threadIdx.x;
    const int wid  = tid >> 5;
    const int lane = tid & 31;
    const int wm = wid & 1;
    const int wn = wid >> 1;
    const int m0 = blockIdx.y * 128;
    const int n0 = blockIdx.x * 128;

    float acc[4][4][4];
#pragma unroll
    for (int i = 0; i < 4; i++)
#pragma unroll
        for (int j = 0; j < 4; j++)
#pragma unroll
            for (int q = 0; q < 4; q++) acc[i][j][q] = 0.0f;

    load_stage(sb,             Ah, Al, Bh, Bl, m0, n0, 0,  tid); CP_COMMIT();
    load_stage(sb + STG_BYTES, Ah, Al, Bh, Bl, m0, n0, 64, tid); CP_COMMIT();

    const int a_row = wm * 64 + (lane & 15);
    const int a_c16 = (lane >> 4);
    const int b_row = wn * 32 + (lane & 7);
    const int b_c16 = ((lane >> 3) & 1);

    for (int it = 0; it < 16; it++) {
        const int s = it & 1;
        const uint32_t sbase = sb + s * STG_BYTES;
        if (it < 15) asm volatile("cp.async.wait_group 1;\n" ::: "memory");
        else         asm volatile("cp.async.wait_group 0;\n" ::: "memory");
        __syncthreads();

#pragma unroll
        for (int ks = 0; ks < 4; ks++) {
            uint32_t ahi[4][4], alo[4][4], bhi[4][2], blo[4][2];
#pragma unroll
            for (int mf = 0; mf < 4; mf++) {
                int row = a_row + mf * 16;
                int c16 = ks * 2 + a_c16;
                uint32_t ad = sbase + row * 128 + ((c16 ^ (row & 7)) << 4);
                ldsm4(ahi[mf][0], ahi[mf][1], ahi[mf][2], ahi[mf][3], ad + AHI_OFF);
                ldsm4(alo[mf][0], alo[mf][1], alo[mf][2], alo[mf][3], ad + ALO_OFF);
            }
#pragma unroll
            for (int nf = 0; nf < 4; nf++) {
                int row = b_row + nf * 8;
                int c16 = ks * 2 + b_c16;
                uint32_t bd = sbase + row * 128 + ((c16 ^ (row & 7)) << 4);
                ldsm2(bhi[nf][0], bhi[nf][1], bd + BHI_OFF);
                ldsm2(blo[nf][0], blo[nf][1], bd + BLO_OFF);
            }
#pragma unroll
            for (int mf = 0; mf < 4; mf++)
#pragma unroll
                for (int nf = 0; nf < 4; nf++) {
                    mma16816(acc[mf][nf], ahi[mf], bhi[nf]);
                    mma16816(acc[mf][nf], alo[mf], bhi[nf]);
                    mma16816(acc[mf][nf], ahi[mf], blo[nf]);
                }
        }
        __syncthreads();
        if (it + 2 < 16) {
            load_stage(sbase, Ah, Al, Bh, Bl, m0, n0, (it + 2) * 64, tid);
            CP_COMMIT();
        }
    }

    const int mbase = m0 + wm * 64 + (lane >> 2);
    const int nbase = n0 + wn * 32 + (lane & 3) * 2;
#pragma unroll
    for (int mf = 0; mf < 4; mf++) {
#pragma unroll
        for (int half = 0; half < 2; half++) {
            int m = mbase + mf * 16 + half * 8;
#pragma unroll
            for (int nf = 0; nf < 4; nf++) {
                int n = nbase + nf * 8;
                float v0 = acc[mf][nf][half*2+0] + bias[n];
                float v1 = acc[mf][nf][half*2+1] + bias[n+1];
                if (MODE == 0) {
                    *(float2*)(Cout + (size_t)m * Cn + n) = make_float2(v0, v1);
                } else {
                    int sec = n >> 10;
                    int c1  = n & 1023;
                    int h   = c1 >> 6, dd = c1 & 63;
                    int bq  = m >> 11, t = m & 2047;
                    size_t idx = ((size_t)((bq * Hn + h) * Tn + t)) * 64 + dd;
                    if (sec == 2) {
                        *(float2*)(g_V + idx) = make_float2(v0, v1);
                    } else {
                        if (sec == 0) { v0 *= 0.125f; v1 *= 0.125f; }
                        uint32_t hh = pkbf(v0, v1);
                        float f0 = __uint_as_float(hh << 16);
                        float f1 = __uint_as_float(hh & 0xffff0000u);
                        uint32_t ll = pkbf(v0 - f0, v1 - f1);
                        if (sec == 0) {
                            *(uint32_t*)(g_Qh + idx) = hh;
                            *(uint32_t*)(g_Ql + idx) = ll;
                        } else {
                            *(uint32_t*)(g_Kh + idx) = hh;
                            *(uint32_t*)(g_Kl + idx) = ll;
                        }
                    }
                }
            }
        }
    }
}

// ---------------------------------------------------------------------------
// z_max partial: grid (32 bh, 8 chunks), each block reduces 256 t-rows
// ---------------------------------------------------------------------------
__global__ __launch_bounds__(256) void zmax_part(const float* __restrict__ p_param)
{
    int bh = blockIdx.x, chunk = blockIdx.y;
    int b = bh >> 4, h = bh & 15;
    int dd = threadIdx.x & 63;
    int g  = threadIdx.x >> 6;
    int c  = h*64 + dd;
    float pv = clamp_p(p_param[c]);

    const float* vp = g_V + (size_t)bh * Tn * 64;
    float mx = -1e30f;
    for (int t = chunk*256 + g; t < (chunk+1)*256; t += 4) {
        float v = vp[t*64 + dd];
        float z = pv * logf(fmaxf(fabsf(v + 5.0f), 1e-10f));
        mx = fmaxf(mx, z);
    }
    __shared__ float red[256];
    red[threadIdx.x] = mx;
    __syncthreads();
    if (g == 0) {
        mx = fmaxf(fmaxf(red[dd], red[64+dd]), fmaxf(red[128+dd], red[192+dd]));
        g_zpart[chunk*(Bn*Cn) + b*Cn + c] = mx;
    }
}
__global__ __launch_bounds__(256) void zmax_reduce()
{
    int i = blockIdx.x * 256 + threadIdx.x;   // 0..2047
    float mx = -1e30f;
#pragma unroll
    for (int ch = 0; ch < 8; ch++) mx = fmaxf(mx, g_zpart[ch*(Bn*Cn) + i]);
    g_zmax[i] = mx;
}

// ---------------------------------------------------------------------------
// V transform: v -> exp(p*log(clip(|v+5|)) - zmax), written as bf16 hi/lo
// ---------------------------------------------------------------------------
__global__ __launch_bounds__(256) void vexp_kernel(const float* __restrict__ p_param)
{
    int i = blockIdx.x * 256 + threadIdx.x;
    int base = i * 2;
    int dd = base & 63;
    int bh = base >> 17;
    int h = bh & 15, b = bh >> 4;
    int c = h*64 + dd;
    float2 v2 = *(const float2*)(g_V + base);
    float pv0 = clamp_p(p_param[c]);
    float pv1 = clamp_p(p_param[c+1]);
    float z0 = pv0 * logf(fmaxf(fabsf(v2.x + 5.0f), 1e-10f)) - g_zmax[b*Cn + c];
    float z1 = pv1 * logf(fmaxf(fabsf(v2.y + 5.0f), 1e-10f)) - g_zmax[b*Cn + c + 1];
    float e0 = expf(z0), e1 = expf(z1);
    uint32_t hh = pkbf(e0, e1);
    float f0 = __uint_as_float(hh << 16);
    float f1 = __uint_as_float(hh & 0xffff0000u);
    uint32_t ll = pkbf(e0 - f0, e1 - f1);
    *(uint32_t*)(g_Vh + base) = hh;
    *(uint32_t*)(g_Vl + base) = ll;
}

// ---------------------------------------------------------------------------
// Tensor-core flash attention (causal), BQ=BK=128, 8 warps, each warp a
// 16q x 128kv strip. bf16x3 for S and O; P reused from S accumulator frags.
// ---------------------------------------------------------------------------
#define FAQ_H 0
#define FAQ_L 16384
#define FASTG0 32768
#define FASTG_SZ 65536
#define FKH 0
#define FKL 16384
#define FVH 32768
#define FVL 49152
#define FA_SMEM (32768 + 2*FASTG_SZ)   // 160 KB

__device__ __forceinline__ void fa_load_stage(uint32_t sbase, int bh, int kt, int tid)
{
    const __nv_bfloat16* srcs[4] = {g_Kh, g_Kl, g_Vh, g_Vl};
#pragma unroll
    for (int j = 0; j < 16; j++) {
        int idx = tid + j * 256;          // 0..4095
        int arr = idx >> 10;
        int rem = idx & 1023;
        int row = rem >> 3, c = rem & 7;
        uint32_t sw = arr * 16384 + row * 128 + ((c ^ (row & 7)) << 4);
        size_t g = ((size_t)bh * Tn + kt * 128 + row) * 64 + c * 8;
        cp16(sbase + sw, srcs[arr] + g);
    }
}

__global__ __launch_bounds__(256) void fa_kernel(const float* __restrict__ p_param)
{
    extern __shared__ char smem[];
    uint32_t sb = smem_u32(smem);
    const int tid  = threadIdx.x;
    const int w    = tid >> 5;
    const int lane = tid & 31;
    const int quad = lane >> 2;
    const int idq  = lane & 3;
    const int bh = blockIdx.y;
    const int b = bh >> 4, h = bh & 15;
    const int qt = (int)gridDim.x - 1 - (int)blockIdx.x;
    const int q0 = qt * 128;

    // ---- prologue: Q tile + first stages via cp.async ----
    {
        const __nv_bfloat16* qs[2] = {g_Qh, g_Ql};
#pragma unroll
        for (int j = 0; j < 8; j++) {
            int idx = tid + j * 256;      // 0..2047
            int arr = idx >> 10;
            int rem = idx & 1023;
            int row = rem >> 3, c = rem & 7;
            uint32_t sw = arr * 16384 + row * 128 + ((c ^ (row & 7)) << 4);
            size_t g = ((size_t)bh * Tn + q0 + row) * 64 + c * 8;
            cp16(sb + sw, qs[arr] + g);
        }
        fa_load_stage(sb + FASTG0, bh, 0, tid);
        CP_COMMIT();
        if (qt >= 1) fa_load_stage(sb + FASTG0 + FASTG_SZ, bh, 1, tid);
        CP_COMMIT();
    }

    uint32_t Qh[4][4], Ql[4][4];
    float Of[8][4];
    float m0 = -1e30f, m1 = -1e30f, l0 = 0.0f, l1 = 0.0f;
#pragma unroll
    for (int nf = 0; nf < 8; nf++)
#pragma unroll
        for (int q = 0; q < 4; q++) Of[nf][q] = 0.0f;

    for (int kt = 0; kt <= qt; kt++) {
        const uint32_t sbase = sb + FASTG0 + (kt & 1) * FASTG_SZ;
        if (kt < qt) asm volatile("cp.async.wait_group 1;\n" ::: "memory");
        else         asm volatile("cp.async.wait_group 0;\n" ::: "memory");
        __syncthreads();

        if (kt == 0) {
            // load Q fragments once (row = w*16 + lane&15, chunk = ks*2 + lane>>4)
            int row = w * 16 + (lane & 15);
#pragma unroll
            for (int ks = 0; ks < 4; ks++) {
                int c16 = ks * 2 + (lane >> 4);
                uint32_t sw = row * 128 + ((c16 ^ (row & 7)) << 4);
                ldsm4(Qh[ks][0], Qh[ks][1], Qh[ks][2], Qh[ks][3], sb + FAQ_H + sw);
                ldsm4(Ql[ks][0], Ql[ks][1], Ql[ks][2], Ql[ks][3], sb + FAQ_L + sw);
            }
        }

        // ---- S = Q K^T (16 x 128 strip per warp), bf16x3 ----
        float Sf[16][4];
#pragma unroll
        for (int nf = 0; nf < 16; nf++)
#pragma unroll
            for (int q = 0; q < 4; q++) Sf[nf][q] = 0.0f;

#pragma unroll
        for (int nf = 0; nf < 16; nf++) {
            int krow = nf * 8 + (lane & 7);
#pragma unroll
            for (int ks = 0; ks < 4; ks++) {
                int c16 = ks * 2 + ((lane >> 3) & 1);
                uint32_t sw = krow * 128 + ((c16 ^ (krow & 7)) << 4);
                uint32_t bhf[2], blf[2];
                ldsm2(bhf[0], bhf[1], sbase + FKH + sw);
                ldsm2(blf[0], blf[1], sbase + FKL + sw);
                mma16816(Sf[nf], Qh[ks], bhf);
                mma16816(Sf[nf], Ql[ks], bhf);
                mma16816(Sf[nf], Qh[ks], blf);
            }
        }

        // ---- causal mask on diagonal tile ----
        if (kt == qt) {
            int r0 = w * 16 + quad, r1 = r0 + 8;
#pragma unroll
            for (int nf = 0; nf < 16; nf++) {
                int c0 = nf * 8 + idq * 2;
                if (c0     > r0) Sf[nf][0] = -1e30f;
                if (c0 + 1 > r0) Sf[nf][1] = -1e30f;
                if (c0     > r1) Sf[nf][2] = -1e30f;
                if (c0 + 1 > r1) Sf[nf][3] = -1e30f;
            }
        }

        // ---- row max (in-warp: reduce over idq) ----
        float mx0 = -1e30f, mx1 = -1e30f;
#pragma unroll
        for (int nf = 0; nf < 16; nf++) {
            mx0 = fmaxf(mx0, fmaxf(Sf[nf][0], Sf[nf][1]));
            mx1 = fmaxf(mx1, fmaxf(Sf[nf][2], Sf[nf][3]));
        }
#pragma unroll
        for (int off = 1; off < 4; off <<= 1) {
            mx0 = fmaxf(mx0, __shfl_xor_sync(0xffffffffu, mx0, off));
            mx1 = fmaxf(mx1, __shfl_xor_sync(0xffffffffu, mx1, off));
        }
        mx0 = fmaxf(mx0, m0);
        mx1 = fmaxf(mx1, m1);
        float a0 = __expf(m0 - mx0), a1 = __expf(m1 - mx1);
        m0 = mx0; m1 = mx1;

        // ---- P = exp(S - m), row sums ----
        float s0 = 0.0f, s1 = 0.0f;
#pragma unroll
        for (int nf = 0; nf < 16; nf++) {
            Sf[nf][0] = __expf(Sf[nf][0] - mx0);
            Sf[nf][1] = __expf(Sf[nf][1] - mx0);
            Sf[nf][2] = __expf(Sf[nf][2] - mx1);
            Sf[nf][3] = __expf(Sf[nf][3] - mx1);
            s0 += Sf[nf][0] + Sf[nf][1];
            s1 += Sf[nf][2] + Sf[nf][3];
        }
#pragma unroll
        for (int off = 1; off < 4; off <<= 1) {
            s0 += __shfl_xor_sync(0xffffffffu, s0, off);
            s1 += __shfl_xor_sync(0xffffffffu, s1, off);
        }
        l0 = l0 * a0 + s0;
        l1 = l1 * a1 + s1;

        // ---- rescale O ----
#pragma unroll
        for (int nf = 0; nf < 8; nf++) {
            Of[nf][0] *= a0; Of[nf][1] *= a0;
            Of[nf][2] *= a1; Of[nf][3] *= a1;
        }

        // ---- O += P V  (P frags from S accumulators, bf16x3) ----
#pragma unroll
        for (int kf = 0; kf < 8; kf++) {
            uint32_t pha[4], pla[4];
#pragma unroll
            for (int half = 0; half < 2; half++) {       // frag 2kf, 2kf+1
                float* sp = Sf[2*kf + half];
                uint32_t u0 = pkbf(sp[0], sp[1]);
                uint32_t u1 = pkbf(sp[2], sp[3]);
                float f00 = __uint_as_float(u0 << 16), f01 = __uint_as_float(u0 & 0xffff0000u);
                float f10 = __uint_as_float(u1 << 16), f11 = __uint_as_float(u1 & 0xffff0000u);
                pha[half*2+0] = u0;                       // a0/a2: row r0
                pha[half*2+1] = u1;                       // a1/a3: row r1
                pla[half*2+0] = pkbf(sp[0] - f00, sp[1] - f01);
                pla[half*2+1] = pkbf(sp[2] - f10, sp[3] - f11);
            }
            int vrow = kf * 16 + (lane & 15);
#pragma unroll
            for (int nf = 0; nf < 8; nf++) {
                uint32_t sw = vrow * 128 + ((nf ^ (vrow & 7)) << 4);
                uint32_t vh[2], vl[2];
                ldsm2t(vh[0], vh[1], sbase + FVH + sw);
                ldsm2t(vl[0], vl[1], sbase + FVL + sw);
                mma16816(Of[nf], pha, vh);
                mma16816(Of[nf], pla, vh);
                mma16816(Of[nf], pha, vl);
            }
        }

        __syncthreads();
        if (kt + 2 <= qt) {
            fa_load_stage(sbase, bh, kt + 2, tid);
            CP_COMMIT();
        }
    }

    // ---- epilogue: mean = O/l; y = exp((zmax + log(mean))/p) - 5 ----
    const int t0 = q0 + w * 16 + quad;
    const int t1 = t0 + 8;
    float linv0 = 1.0f / l0, linv1 = 1.0f / l1;
#pragma unroll
    for (int nf = 0; nf < 8; nf++) {
        int d0 = nf * 8 + idq * 2;
        int cg = h * 64 + d0;
        float pv0 = clamp_p(p_param[cg]);
        float pv1 = clamp_p(p_param[cg + 1]);
        float zm0 = g_zmax[b*Cn + cg];
        float zm1 = g_zmax[b*Cn + cg + 1];
        float y00 = expf((zm0 + logf(Of[nf][0] * linv0)) / pv0) - 5.0f;
        float y01 = expf((zm1 + logf(Of[nf][1] * linv0)) / pv1) - 5.0f;
        float y10 = expf((zm0 + logf(Of[nf][2] * linv1)) / pv0) - 5.0f;
        float y11 = expf((zm1 + logf(Of[nf][3] * linv1)) / pv1) - 5.0f;
        *(float2*)(g_Y + (size_t)(b*Tn + t0)*Cn + cg) = make_float2(y00, y01);
        *(float2*)(g_Y + (size_t)(b*Tn + t1)*Cn + cg) = make_float2(y10, y11);
    }
}

// ---------------------------------------------------------------------------

extern "C" void kernel_launch(void* const* d_in, const int* in_sizes, int n_in,
                              void* d_out, int out_size)
{
    const float* x       = (const float*)d_in[0];
    const float* w_attn  = (const float*)d_in[1];
    const float* b_attn  = (const float*)d_in[2];
    const float* w_proj  = (const float*)d_in[3];
    const float* b_proj  = (const float*)d_in[4];
    const float* p_param = (const float*)d_in[5];
    float* out = (float*)d_out;

    void *yptr, *ah, *al, *bth, *btl;
    cudaGetSymbolAddress(&yptr, g_Y);
    cudaGetSymbolAddress(&ah,  gA_hi);
    cudaGetSymbolAddress(&al,  gA_lo);
    cudaGetSymbolAddress(&bth, gBT_hi);
    cudaGetSymbolAddress(&btl, gBT_lo);

    cudaFuncSetAttribute(fa_kernel, cudaFuncAttributeMaxDynamicSharedMemorySize, FA_SMEM);
    cudaFuncSetAttribute(tc_gemm<0>, cudaFuncAttributeMaxDynamicSharedMemorySize, TCG_SMEM);
    cudaFuncSetAttribute(tc_gemm<1>, cudaFuncAttributeMaxDynamicSharedMemorySize, TCG_SMEM);

    // 1) split x; transpose+split w_attn
    split_bf16<<<Mn*Cn/1024, 256>>>(x, (__nv_bfloat16*)ah, (__nv_bfloat16*)al);
    transpose_split<<<dim3(3072/32, Cn/32), dim3(32,8)>>>(
        w_attn, (__nv_bfloat16*)bth, (__nv_bfloat16*)btl, 3072);

    // 2) QKV GEMM + bf16 hi/lo head-major scatter (Q pre-scaled)
    tc_gemm<1><<<dim3(3072/128, Mn/128), 256, TCG_SMEM>>>(
        (const __nv_bfloat16*)ah, (const __nv_bfloat16*)al,
        (const __nv_bfloat16*)bth, (const __nv_bfloat16*)btl, b_attn, nullptr);

    // 3) z_max (partial + reduce) + V power transform -> bf16 hi/lo
    zmax_part<<<dim3(BHn, 8), 256>>>(p_param);
    zmax_reduce<<<(Bn*Cn)/256, 256>>>();
    vexp_kernel<<<(BHn*Tn*Dn)/512, 256>>>(p_param);

    // 4) tensor-core causal flash attention + fused epilogue
    fa_kernel<<<dim3(Tn/128, BHn), 256, FA_SMEM>>>(p_param);

    // 5) split Y; transpose+split w_proj; proj GEMM
    split_bf16<<<Mn*Cn/1024, 256>>>((const float*)yptr, (__nv_bfloat16*)ah, (__nv_bfloat16*)al);
    transpose_split<<<dim3(Cn/32, Cn/32), dim3(32,8)>>>(
        w_proj, (__nv_bfloat16*)bth, (__nv_bfloat16*)btl, Cn);
    tc_gemm<0><<<dim3(Cn/128, Mn/128), 256, TCG_SMEM>>>(
        (const __nv_bfloat16*)ah, (const __nv_bfloat16*)al,
        (const __nv_bfloat16*)bth, (const __nv_bfloat16*)btl, b_proj, out);
}

// round 6
// speedup vs baseline: 3.4661x; 1.0660x over previous
#include <cuda_runtime.h>
#include <cuda_bf16.h>
#include <math.h>
#include <stdint.h>

#define Bn 2
#define Tn 2048
#define Cn 1024
#define Hn 16
#define Dn 64
#define Mn (Bn*Tn)          // 4096
#define BHn (Bn*Hn)         // 32

typedef unsigned long long ull;

// ---------------- device scratch ----------------
__device__ __nv_bfloat16 g_Qh[BHn*Tn*Dn];   // head-major, pre-scaled by 0.125
__device__ __nv_bfloat16 g_Ql[BHn*Tn*Dn];
__device__ __nv_bfloat16 g_Kh[BHn*Tn*Dn];
__device__ __nv_bfloat16 g_Kl[BHn*Tn*Dn];
__device__ float         g_V [BHn*Tn*Dn];   // raw v (fp32) for zmax
__device__ __nv_bfloat16 g_Vh[BHn*Tn*Dn];
__device__ __nv_bfloat16 g_Vl[BHn*Tn*Dn];
__device__ float g_zmax[Bn*Cn];
__device__ float g_zpart[16*Bn*Cn];
__device__ __nv_bfloat16 gA_hi[Mn*Cn];      // A operand (x split, then Y from FA)
__device__ __nv_bfloat16 gA_lo[Mn*Cn];
__device__ __nv_bfloat16 gBT_hi[3*Cn*Cn];
__device__ __nv_bfloat16 gBT_lo[3*Cn*Cn];

__device__ __forceinline__ float clamp_p(float pp) {
    float sgn = (pp >= 0.0f) ? 1.0f : -1.0f;
    return sgn * fminf(fmaxf(fabsf(pp), 1e-4f), 1e3f);
}

// ---------------- ptx helpers ----------------
__device__ __forceinline__ uint32_t smem_u32(const void* p) {
    uint32_t a;
    asm("{ .reg .u64 t; cvta.to.shared.u64 t, %1; cvt.u32.u64 %0, t; }" : "=r"(a) : "l"(p));
    return a;
}
__device__ __forceinline__ void cp16(uint32_t dst, const void* src) {
    asm volatile("cp.async.cg.shared.global [%0], [%1], 16;\n" :: "r"(dst), "l"(src));
}
#define CP_COMMIT() asm volatile("cp.async.commit_group;\n" ::: "memory")

__device__ __forceinline__ void ldsm4(uint32_t& r0, uint32_t& r1, uint32_t& r2, uint32_t& r3,
                                      uint32_t addr) {
    asm volatile("ldmatrix.sync.aligned.m8n8.x4.shared.b16 {%0,%1,%2,%3}, [%4];"
                 : "=r"(r0), "=r"(r1), "=r"(r2), "=r"(r3) : "r"(addr));
}
__device__ __forceinline__ void ldsm4t(uint32_t& r0, uint32_t& r1, uint32_t& r2, uint32_t& r3,
                                       uint32_t addr) {
    asm volatile("ldmatrix.sync.aligned.m8n8.x4.trans.shared.b16 {%0,%1,%2,%3}, [%4];"
                 : "=r"(r0), "=r"(r1), "=r"(r2), "=r"(r3) : "r"(addr));
}
__device__ __forceinline__ void mma16816(float* c, const uint32_t* a, const uint32_t* b) {
    asm volatile(
        "mma.sync.aligned.m16n8k16.row.col.f32.bf16.bf16.f32 "
        "{%0,%1,%2,%3}, {%4,%5,%6,%7}, {%8,%9}, {%0,%1,%2,%3};"
        : "+f"(c[0]), "+f"(c[1]), "+f"(c[2]), "+f"(c[3])
        : "r"(a[0]), "r"(a[1]), "r"(a[2]), "r"(a[3]), "r"(b[0]), "r"(b[1]));
}
__device__ __forceinline__ uint32_t pkbf(float lo, float hi) {
    uint32_t r;
    asm("cvt.rn.bf16x2.f32 %0, %1, %2;" : "=r"(r) : "f"(hi), "f"(lo));
    return r;
}

// ---------------------------------------------------------------------------
// split: fp32 -> bf16 hi/lo
// ---------------------------------------------------------------------------
__global__ __launch_bounds__(256) void split_bf16(
    const float* __restrict__ A, __nv_bfloat16* __restrict__ Ah, __nv_bfloat16* __restrict__ Al)
{
    int i = blockIdx.x * 256 + threadIdx.x;
    float4 a = ((const float4*)A)[i];
    uint32_t h0 = pkbf(a.x, a.y), h1 = pkbf(a.z, a.w);
    float f0 = __uint_as_float(h0 << 16), f1 = __uint_as_float(h0 & 0xffff0000u);
    float f2 = __uint_as_float(h1 << 16), f3 = __uint_as_float(h1 & 0xffff0000u);
    uint32_t l0 = pkbf(a.x - f0, a.y - f1), l1 = pkbf(a.z - f2, a.w - f3);
    ((uint32_t*)Ah)[2*i]   = h0;
    ((uint32_t*)Ah)[2*i+1] = h1;
    ((uint32_t*)Al)[2*i]   = l0;
    ((uint32_t*)Al)[2*i+1] = l1;
}

// ---------------------------------------------------------------------------
// transpose + split: W[K=1024][Nd] -> Th/Tl[Nd][1024] (bf16)
// ---------------------------------------------------------------------------
__global__ void transpose_split(const float* __restrict__ W,
                                __nv_bfloat16* __restrict__ Th,
                                __nv_bfloat16* __restrict__ Tl, int Nd)
{
    __shared__ float tile[32][33];
    int nx = blockIdx.x * 32, kx = blockIdx.y * 32;
    int tx = threadIdx.x, ty = threadIdx.y;
#pragma unroll
    for (int r = ty; r < 32; r += 8)
        tile[r][tx] = W[(size_t)(kx + r) * Nd + nx + tx];
    __syncthreads();
#pragma unroll
    for (int r = ty; r < 32; r += 8) {
        float a = tile[tx][r];
        __nv_bfloat16 hi = __float2bfloat16(a);
        __nv_bfloat16 lo = __float2bfloat16(a - __bfloat162float(hi));
        size_t o = (size_t)(nx + r) * 1024 + kx + tx;
        Th[o] = hi; Tl[o] = lo;
    }
}

// ---------------------------------------------------------------------------
// bf16x3 mma.sync GEMM: CTA 256x128, warp tile 64x64 (4x2 warps), BK=64,
// cp.async double buffer. MODE 0: out+bias. MODE 1: QKV scatter.
// ---------------------------------------------------------------------------
#define AHI_OFF 0
#define ALO_OFF 32768
#define BHI_OFF 65536
#define BLO_OFF 81920
#define STG_BYTES 98304
#define TCG_SMEM (2*STG_BYTES)   // 192 KB

__device__ __forceinline__ void load_stage(
    uint32_t sbase,
    const __nv_bfloat16* __restrict__ Ah, const __nv_bfloat16* __restrict__ Al,
    const __nv_bfloat16* __restrict__ Bh, const __nv_bfloat16* __restrict__ Bl,
    int m0, int n0, int k0, int tid)
{
#pragma unroll
    for (int j = 0; j < 8; j++) {          // A: 256 rows x 8 chunks
        int idx = tid + j * 256;
        int row = idx >> 3, c = idx & 7;
        uint32_t sw = row * 128 + ((c ^ (row & 7)) << 4);
        size_t ga = (size_t)(m0 + row) * 1024 + k0 + c * 8;
        cp16(sbase + AHI_OFF + sw, Ah + ga);
        cp16(sbase + ALO_OFF + sw, Al + ga);
    }
#pragma unroll
    for (int j = 0; j < 4; j++) {          // B: 128 rows x 8 chunks
        int idx = tid + j * 256;
        int row = idx >> 3, c = idx & 7;
        uint32_t sw = row * 128 + ((c ^ (row & 7)) << 4);
        size_t gb = (size_t)(n0 + row) * 1024 + k0 + c * 8;
        cp16(sbase + BHI_OFF + sw, Bh + gb);
        cp16(sbase + BLO_OFF + sw, Bl + gb);
    }
}

template<int MODE>
__global__ __launch_bounds__(256) void tc_gemm(
    const __nv_bfloat16* __restrict__ Ah, const __nv_bfloat16* __restrict__ Al,
    const __nv_bfloat16* __restrict__ Bh, const __nv_bfloat16* __restrict__ Bl,
    const float* __restrict__ bias, float* __restrict__ Cout)
{
    extern __shared__ char smem[];
    uint32_t sb = smem_u32(smem);
    const int tid  = threadIdx.x;
    const int wid  = tid >> 5;
    const int lane = tid & 31;
    const int wm = wid >> 1;       // 4 warp-rows of 64
    const int wn = wid & 1;        // 2 warp-cols of 64
    const int m0 = blockIdx.y * 256;
    const int n0 = blockIdx.x * 128;

    float acc[4][8][4];
#pragma unroll
    for (int i = 0; i < 4; i++)
#pragma unroll
        for (int j = 0; j < 8; j++)
#pragma unroll
            for (int q = 0; q < 4; q++) acc[i][j][q] = 0.0f;

    load_stage(sb,             Ah, Al, Bh, Bl, m0, n0, 0,  tid); CP_COMMIT();
    load_stage(sb + STG_BYTES, Ah, Al, Bh, Bl, m0, n0, 64, tid); CP_COMMIT();

    const int a_row = wm * 64 + (lane & 15);
    const int a_c16 = (lane >> 4);
    const int b_row = wn * 64 + ((lane >> 4) << 3) + (lane & 7);
    const int b_cof = ((lane >> 3) & 1);

    for (int it = 0; it < 16; it++) {
        const int s = it & 1;
        const uint32_t sbase = sb + s * STG_BYTES;
        if (it < 15) asm volatile("cp.async.wait_group 1;\n" ::: "memory");
        else         asm volatile("cp.async.wait_group 0;\n" ::: "memory");
        __syncthreads();

#pragma unroll
        for (int ks = 0; ks < 4; ks++) {
            uint32_t ahi[4][4], alo[4][4];
#pragma unroll
            for (int mf = 0; mf < 4; mf++) {
                int row = a_row + mf * 16;
                int c16 = ks * 2 + a_c16;
                uint32_t ad = sbase + row * 128 + ((c16 ^ (row & 7)) << 4);
                ldsm4(ahi[mf][0], ahi[mf][1], ahi[mf][2], ahi[mf][3], ad + AHI_OFF);
                ldsm4(alo[mf][0], alo[mf][1], alo[mf][2], alo[mf][3], ad + ALO_OFF);
            }
#pragma unroll
            for (int nf2 = 0; nf2 < 4; nf2++) {
                int row = b_row + nf2 * 16;
                int c16 = ks * 2 + b_cof;
                uint32_t bd = sbase + row * 128 + ((c16 ^ (row & 7)) << 4);
                uint32_t bh4[4], bl4[4];
                ldsm4(bh4[0], bh4[1], bh4[2], bh4[3], bd + BHI_OFF);
                ldsm4(bl4[0], bl4[1], bl4[2], bl4[3], bd + BLO_OFF);
#pragma unroll
                for (int mf = 0; mf < 4; mf++) {
                    mma16816(acc[mf][2*nf2],   ahi[mf], bh4);
                    mma16816(acc[mf][2*nf2],   alo[mf], bh4);
                    mma16816(acc[mf][2*nf2],   ahi[mf], bl4);
                    mma16816(acc[mf][2*nf2+1], ahi[mf], bh4 + 2);
                    mma16816(acc[mf][2*nf2+1], alo[mf], bh4 + 2);
                    mma16816(acc[mf][2*nf2+1], ahi[mf], bl4 + 2);
                }
            }
        }
        __syncthreads();
        if (it + 2 < 16) {
            load_stage(sbase, Ah, Al, Bh, Bl, m0, n0, (it + 2) * 64, tid);
            CP_COMMIT();
        }
    }

    const int mbase = m0 + wm * 64 + (lane >> 2);
    const int nbase = n0 + wn * 64 + (lane & 3) * 2;
#pragma unroll
    for (int mf = 0; mf < 4; mf++) {
#pragma unroll
        for (int half = 0; half < 2; half++) {
            int m = mbase + mf * 16 + half * 8;
#pragma unroll
            for (int nf = 0; nf < 8; nf++) {
                int n = nbase + nf * 8;
                float v0 = acc[mf][nf][half*2+0] + bias[n];
                float v1 = acc[mf][nf][half*2+1] + bias[n+1];
                if (MODE == 0) {
                    *(float2*)(Cout + (size_t)m * Cn + n) = make_float2(v0, v1);
                } else {
                    int sec = n >> 10;
                    int c1  = n & 1023;
                    int h   = c1 >> 6, dd = c1 & 63;
                    int bq  = m >> 11, t = m & 2047;
                    size_t idx = ((size_t)((bq * Hn + h) * Tn + t)) * 64 + dd;
                    if (sec == 2) {
                        *(float2*)(g_V + idx) = make_float2(v0, v1);
                    } else {
                        if (sec == 0) { v0 *= 0.125f; v1 *= 0.125f; }
                        uint32_t hh = pkbf(v0, v1);
                        float f0 = __uint_as_float(hh << 16);
                        float f1 = __uint_as_float(hh & 0xffff0000u);
                        uint32_t ll = pkbf(v0 - f0, v1 - f1);
                        if (sec == 0) {
                            *(uint32_t*)(g_Qh + idx) = hh;
                            *(uint32_t*)(g_Ql + idx) = ll;
                        } else {
                            *(uint32_t*)(g_Kh + idx) = hh;
                            *(uint32_t*)(g_Kl + idx) = ll;
                        }
                    }
                }
            }
        }
    }
}

// ---------------------------------------------------------------------------
// z_max partial: grid (32 bh, 16 chunks of 128 t), float4 over d
// ---------------------------------------------------------------------------
__global__ __launch_bounds__(256) void zmax_part(const float* __restrict__ p_param)
{
    int bh = blockIdx.x, chunk = blockIdx.y;
    int b = bh >> 4, h = bh & 15;
    int d4 = threadIdx.x & 15;
    int g  = threadIdx.x >> 4;
    int c  = h*64 + d4*4;
    float4 pv;
    pv.x = clamp_p(p_param[c+0]); pv.y = clamp_p(p_param[c+1]);
    pv.z = clamp_p(p_param[c+2]); pv.w = clamp_p(p_param[c+3]);

    const float* vp = g_V + (size_t)bh * Tn * 64;
    float4 mx = make_float4(-1e30f, -1e30f, -1e30f, -1e30f);
    for (int t = chunk*128 + g; t < (chunk+1)*128; t += 16) {
        float4 v = *(const float4*)(vp + t*64 + d4*4);
        mx.x = fmaxf(mx.x, pv.x * logf(fmaxf(fabsf(v.x + 5.0f), 1e-10f)));
        mx.y = fmaxf(mx.y, pv.y * logf(fmaxf(fabsf(v.y + 5.0f), 1e-10f)));
        mx.z = fmaxf(mx.z, pv.z * logf(fmaxf(fabsf(v.z + 5.0f), 1e-10f)));
        mx.w = fmaxf(mx.w, pv.w * logf(fmaxf(fabsf(v.w + 5.0f), 1e-10f)));
    }
    __shared__ float4 red[256];
    red[threadIdx.x] = mx;
    __syncthreads();
    if (threadIdx.x < 16) {
        float4 m = red[threadIdx.x];
#pragma unroll
        for (int gg = 1; gg < 16; gg++) {
            float4 o = red[gg*16 + threadIdx.x];
            m.x = fmaxf(m.x, o.x); m.y = fmaxf(m.y, o.y);
            m.z = fmaxf(m.z, o.z); m.w = fmaxf(m.w, o.w);
        }
        *(float4*)(g_zpart + chunk*(Bn*Cn) + b*Cn + h*64 + threadIdx.x*4) = m;
    }
}
__global__ __launch_bounds__(256) void zmax_reduce()
{
    int i = blockIdx.x * 256 + threadIdx.x;
    float mx = -1e30f;
#pragma unroll
    for (int ch = 0; ch < 16; ch++) mx = fmaxf(mx, g_zpart[ch*(Bn*Cn) + i]);
    g_zmax[i] = mx;
}

// ---------------------------------------------------------------------------
// V transform -> bf16 hi/lo (float4 per thread)
// ---------------------------------------------------------------------------
__global__ __launch_bounds__(256) void vexp_kernel(const float* __restrict__ p_param)
{
    int i = blockIdx.x * 256 + threadIdx.x;
    int base = i * 4;
    int dd = base & 63;
    int bh = base >> 17;
    int h = bh & 15, b = bh >> 4;
    int c = h*64 + dd;
    float4 v = *(const float4*)(g_V + base);
    float e[4];
    const float vs[4] = {v.x, v.y, v.z, v.w};
#pragma unroll
    for (int j = 0; j < 4; j++) {
        float pvj = clamp_p(p_param[c + j]);
        float z = pvj * logf(fmaxf(fabsf(vs[j] + 5.0f), 1e-10f)) - g_zmax[b*Cn + c + j];
        e[j] = expf(z);
    }
    uint32_t h0 = pkbf(e[0], e[1]), h1 = pkbf(e[2], e[3]);
    float f0 = __uint_as_float(h0 << 16), f1 = __uint_as_float(h0 & 0xffff0000u);
    float f2 = __uint_as_float(h1 << 16), f3 = __uint_as_float(h1 & 0xffff0000u);
    uint32_t l0 = pkbf(e[0]-f0, e[1]-f1), l1 = pkbf(e[2]-f2, e[3]-f3);
    ((uint2*)g_Vh)[i] = make_uint2(h0, h1);
    ((uint2*)g_Vl)[i] = make_uint2(l0, l1);
}

// ---------------------------------------------------------------------------
// Tensor-core flash attention (causal), BQ=BK=128, 8 warps, 16q x 128kv strip
// per warp; bf16x3; P from S accumulator frags; ldsm4-paired loads.
// Epilogue writes Y as bf16 hi/lo into gA_hi/gA_lo.
// ---------------------------------------------------------------------------
#define FAQ_H 0
#define FAQ_L 16384
#define FASTG0 32768
#define FASTG_SZ 65536
#define FKH 0
#define FKL 16384
#define FVH 32768
#define FVL 49152
#define FA_SMEM (32768 + 2*FASTG_SZ)   // 160 KB

__device__ __forceinline__ void fa_load_stage(uint32_t sbase, int bh, int kt, int tid)
{
    const __nv_bfloat16* srcs[4] = {g_Kh, g_Kl, g_Vh, g_Vl};
#pragma unroll
    for (int j = 0; j < 16; j++) {
        int idx = tid + j * 256;
        int arr = idx >> 10;
        int rem = idx & 1023;
        int row = rem >> 3, c = rem & 7;
        uint32_t sw = arr * 16384 + row * 128 + ((c ^ (row & 7)) << 4);
        size_t g = ((size_t)bh * Tn + kt * 128 + row) * 64 + c * 8;
        cp16(sbase + sw, srcs[arr] + g);
    }
}

__global__ __launch_bounds__(256) void fa_kernel(const float* __restrict__ p_param)
{
    extern __shared__ char smem[];
    uint32_t sb = smem_u32(smem);
    const int tid  = threadIdx.x;
    const int w    = tid >> 5;
    const int lane = tid & 31;
    const int quad = lane >> 2;
    const int idq  = lane & 3;
    const int bh = blockIdx.y;
    const int b = bh >> 4, h = bh & 15;
    const int qt = (int)gridDim.x - 1 - (int)blockIdx.x;
    const int q0 = qt * 128;

    {
        const __nv_bfloat16* qs[2] = {g_Qh, g_Ql};
#pragma unroll
        for (int j = 0; j < 8; j++) {
            int idx = tid + j * 256;
            int arr = idx >> 10;
            int rem = idx & 1023;
            int row = rem >> 3, c = rem & 7;
            uint32_t sw = arr * 16384 + row * 128 + ((c ^ (row & 7)) << 4);
            size_t g = ((size_t)bh * Tn + q0 + row) * 64 + c * 8;
            cp16(sb + sw, qs[arr] + g);
        }
        fa_load_stage(sb + FASTG0, bh, 0, tid);
        CP_COMMIT();
        if (qt >= 1) fa_load_stage(sb + FASTG0 + FASTG_SZ, bh, 1, tid);
        CP_COMMIT();
    }

    uint32_t Qh[4][4], Ql[4][4];
    float Of[8][4];
    float m0 = -1e30f, m1 = -1e30f, l0 = 0.0f, l1 = 0.0f;
#pragma unroll
    for (int nf = 0; nf < 8; nf++)
#pragma unroll
        for (int q = 0; q < 4; q++) Of[nf][q] = 0.0f;

    const int k_row = ((lane >> 4) << 3) + (lane & 7);   // + nf2*16
    const int k_cof = ((lane >> 3) & 1);                 // + ks*2
    const int v_row = (lane & 15);                       // + kf*16
    const int v_cof = (lane >> 4);                       // + nf2*2

    for (int kt = 0; kt <= qt; kt++) {
        const uint32_t sbase = sb + FASTG0 + (kt & 1) * FASTG_SZ;
        if (kt < qt) asm volatile("cp.async.wait_group 1;\n" ::: "memory");
        else         asm volatile("cp.async.wait_group 0;\n" ::: "memory");
        __syncthreads();

        if (kt == 0) {
            int row = w * 16 + (lane & 15);
#pragma unroll
            for (int ks = 0; ks < 4; ks++) {
                int c16 = ks * 2 + (lane >> 4);
                uint32_t sw = row * 128 + ((c16 ^ (row & 7)) << 4);
                ldsm4(Qh[ks][0], Qh[ks][1], Qh[ks][2], Qh[ks][3], sb + FAQ_H + sw);
                ldsm4(Ql[ks][0], Ql[ks][1], Ql[ks][2], Ql[ks][3], sb + FAQ_L + sw);
            }
        }

        // ---- S = Q K^T (16 x 128 strip), ldsm4-paired K ----
        float Sf[16][4];
#pragma unroll
        for (int nf = 0; nf < 16; nf++)
#pragma unroll
            for (int q = 0; q < 4; q++) Sf[nf][q] = 0.0f;

#pragma unroll
        for (int nf2 = 0; nf2 < 8; nf2++) {
            int krow = nf2 * 16 + k_row;
#pragma unroll
            for (int ks = 0; ks < 4; ks++) {
                int c16 = ks * 2 + k_cof;
                uint32_t sw = krow * 128 + ((c16 ^ (krow & 7)) << 4);
                uint32_t kh[4], kl[4];
                ldsm4(kh[0], kh[1], kh[2], kh[3], sbase + FKH + sw);
                ldsm4(kl[0], kl[1], kl[2], kl[3], sbase + FKL + sw);
                mma16816(Sf[2*nf2],   Qh[ks], kh);
                mma16816(Sf[2*nf2],   Ql[ks], kh);
                mma16816(Sf[2*nf2],   Qh[ks], kl);
                mma16816(Sf[2*nf2+1], Qh[ks], kh + 2);
                mma16816(Sf[2*nf2+1], Ql[ks], kh + 2);
                mma16816(Sf[2*nf2+1], Qh[ks], kl + 2);
            }
        }

        if (kt == qt) {
            int r0 = w * 16 + quad, r1 = r0 + 8;
#pragma unroll
            for (int nf = 0; nf < 16; nf++) {
                int c0 = nf * 8 + idq * 2;
                if (c0     > r0) Sf[nf][0] = -1e30f;
                if (c0 + 1 > r0) Sf[nf][1] = -1e30f;
                if (c0     > r1) Sf[nf][2] = -1e30f;
                if (c0 + 1 > r1) Sf[nf][3] = -1e30f;
            }
        }

        float mx0 = -1e30f, mx1 = -1e30f;
#pragma unroll
        for (int nf = 0; nf < 16; nf++) {
            mx0 = fmaxf(mx0, fmaxf(Sf[nf][0], Sf[nf][1]));
            mx1 = fmaxf(mx1, fmaxf(Sf[nf][2], Sf[nf][3]));
        }
#pragma unroll
        for (int off = 1; off < 4; off <<= 1) {
            mx0 = fmaxf(mx0, __shfl_xor_sync(0xffffffffu, mx0, off));
            mx1 = fmaxf(mx1, __shfl_xor_sync(0xffffffffu, mx1, off));
        }
        mx0 = fmaxf(mx0, m0);
        mx1 = fmaxf(mx1, m1);
        float a0 = __expf(m0 - mx0), a1 = __expf(m1 - mx1);
        m0 = mx0; m1 = mx1;

        float s0 = 0.0f, s1 = 0.0f;
#pragma unroll
        for (int nf = 0; nf < 16; nf++) {
            Sf[nf][0] = __expf(Sf[nf][0] - mx0);
            Sf[nf][1] = __expf(Sf[nf][1] - mx0);
            Sf[nf][2] = __expf(Sf[nf][2] - mx1);
            Sf[nf][3] = __expf(Sf[nf][3] - mx1);
            s0 += Sf[nf][0] + Sf[nf][1];
            s1 += Sf[nf][2] + Sf[nf][3];
        }
#pragma unroll
        for (int off = 1; off < 4; off <<= 1) {
            s0 += __shfl_xor_sync(0xffffffffu, s0, off);
            s1 += __shfl_xor_sync(0xffffffffu, s1, off);
        }
        l0 = l0 * a0 + s0;
        l1 = l1 * a1 + s1;

#pragma unroll
        for (int nf = 0; nf < 8; nf++) {
            Of[nf][0] *= a0; Of[nf][1] *= a0;
            Of[nf][2] *= a1; Of[nf][3] *= a1;
        }

        // ---- O += P V, ldsm4t-paired V ----
#pragma unroll
        for (int kf = 0; kf < 8; kf++) {
            uint32_t pha[4], pla[4];
#pragma unroll
            for (int half = 0; half < 2; half++) {
                float* sp = Sf[2*kf + half];
                uint32_t u0 = pkbf(sp[0], sp[1]);
                uint32_t u1 = pkbf(sp[2], sp[3]);
                float f00 = __uint_as_float(u0 << 16), f01 = __uint_as_float(u0 & 0xffff0000u);
                float f10 = __uint_as_float(u1 << 16), f11 = __uint_as_float(u1 & 0xffff0000u);
                pha[half*2+0] = u0;
                pha[half*2+1] = u1;
                pla[half*2+0] = pkbf(sp[0] - f00, sp[1] - f01);
                pla[half*2+1] = pkbf(sp[2] - f10, sp[3] - f11);
            }
            int vrow = kf * 16 + v_row;
#pragma unroll
            for (int nf2 = 0; nf2 < 4; nf2++) {
                int c16 = nf2 * 2 + v_cof;
                uint32_t sw = vrow * 128 + ((c16 ^ (vrow & 7)) << 4);
                uint32_t vh[4], vl[4];
                ldsm4t(vh[0], vh[1], vh[2], vh[3], sbase + FVH + sw);
                ldsm4t(vl[0], vl[1], vl[2], vl[3], sbase + FVL + sw);
                mma16816(Of[2*nf2],   pha, vh);
                mma16816(Of[2*nf2],   pla, vh);
                mma16816(Of[2*nf2],   pha, vl);
                mma16816(Of[2*nf2+1], pha, vh + 2);
                mma16816(Of[2*nf2+1], pla, vh + 2);
                mma16816(Of[2*nf2+1], pha, vl + 2);
            }
        }

        __syncthreads();
        if (kt + 2 <= qt) {
            fa_load_stage(sbase, bh, kt + 2, tid);
            CP_COMMIT();
        }
    }

    // ---- epilogue: y = exp((zmax + log(O/l))/p) - 5, write bf16 hi/lo ----
    const int t0 = q0 + w * 16 + quad;
    const int t1 = t0 + 8;
    float linv0 = 1.0f / l0, linv1 = 1.0f / l1;
#pragma unroll
    for (int nf = 0; nf < 8; nf++) {
        int d0 = nf * 8 + idq * 2;
        int cg = h * 64 + d0;
        float pv0 = clamp_p(p_param[cg]);
        float pv1 = clamp_p(p_param[cg + 1]);
        float zm0 = g_zmax[b*Cn + cg];
        float zm1 = g_zmax[b*Cn + cg + 1];
        float y00 = expf((zm0 + logf(Of[nf][0] * linv0)) / pv0) - 5.0f;
        float y01 = expf((zm1 + logf(Of[nf][1] * linv0)) / pv1) - 5.0f;
        float y10 = expf((zm0 + logf(Of[nf][2] * linv1)) / pv0) - 5.0f;
        float y11 = expf((zm1 + logf(Of[nf][3] * linv1)) / pv1) - 5.0f;
        uint32_t h0 = pkbf(y00, y01);
        float f00 = __uint_as_float(h0 << 16), f01 = __uint_as_float(h0 & 0xffff0000u);
        uint32_t l0p = pkbf(y00 - f00, y01 - f01);
        uint32_t h1 = pkbf(y10, y11);
        float f10 = __uint_as_float(h1 << 16), f11 = __uint_as_float(h1 & 0xffff0000u);
        uint32_t l1p = pkbf(y10 - f10, y11 - f11);
        size_t i0 = ((size_t)(b*Tn + t0)*Cn + cg) >> 1;
        size_t i1 = ((size_t)(b*Tn + t1)*Cn + cg) >> 1;
        ((uint32_t*)gA_hi)[i0] = h0;
        ((uint32_t*)gA_lo)[i0] = l0p;
        ((uint32_t*)gA_hi)[i1] = h1;
        ((uint32_t*)gA_lo)[i1] = l1p;
    }
}

// ---------------------------------------------------------------------------

extern "C" void kernel_launch(void* const* d_in, const int* in_sizes, int n_in,
                              void* d_out, int out_size)
{
    const float* x       = (const float*)d_in[0];
    const float* w_attn  = (const float*)d_in[1];
    const float* b_attn  = (const float*)d_in[2];
    const float* w_proj  = (const float*)d_in[3];
    const float* b_proj  = (const float*)d_in[4];
    const float* p_param = (const float*)d_in[5];
    float* out = (float*)d_out;

    void *ah, *al, *bth, *btl;
    cudaGetSymbolAddress(&ah,  gA_hi);
    cudaGetSymbolAddress(&al,  gA_lo);
    cudaGetSymbolAddress(&bth, gBT_hi);
    cudaGetSymbolAddress(&btl, gBT_lo);

    cudaFuncSetAttribute(fa_kernel, cudaFuncAttributeMaxDynamicSharedMemorySize, FA_SMEM);
    cudaFuncSetAttribute(tc_gemm<0>, cudaFuncAttributeMaxDynamicSharedMemorySize, TCG_SMEM);
    cudaFuncSetAttribute(tc_gemm<1>, cudaFuncAttributeMaxDynamicSharedMemorySize, TCG_SMEM);

    // 1) split x; transpose+split w_attn
    split_bf16<<<Mn*Cn/1024, 256>>>(x, (__nv_bfloat16*)ah, (__nv_bfloat16*)al);
    transpose_split<<<dim3(3072/32, Cn/32), dim3(32,8)>>>(
        w_attn, (__nv_bfloat16*)bth, (__nv_bfloat16*)btl, 3072);

    // 2) QKV GEMM + bf16 hi/lo head-major scatter (Q pre-scaled)
    tc_gemm<1><<<dim3(3072/128, Mn/256), 256, TCG_SMEM>>>(
        (const __nv_bfloat16*)ah, (const __nv_bfloat16*)al,
        (const __nv_bfloat16*)bth, (const __nv_bfloat16*)btl, b_attn, nullptr);

    // 3) z_max (partial + reduce) + V transform -> bf16 hi/lo
    zmax_part<<<dim3(BHn, 16), 256>>>(p_param);
    zmax_reduce<<<(Bn*Cn)/256, 256>>>();
    vexp_kernel<<<(BHn*Tn*Dn)/1024, 256>>>(p_param);

    // 4) tensor-core causal FA; epilogue writes Y as bf16 hi/lo into gA
    fa_kernel<<<dim3(Tn/128, BHn), 256, FA_SMEM>>>(p_param);

    // 5) transpose+split w_proj; proj GEMM (A = Y bf16 from FA)
    transpose_split<<<dim3(Cn/32, Cn/32), dim3(32,8)>>>(
        w_proj, (__nv_bfloat16*)bth, (__nv_bfloat16*)btl, Cn);
    tc_gemm<0><<<dim3(Cn/128, Mn/256), 256, TCG_SMEM>>>(
        (const __nv_bfloat16*)ah, (const __nv_bfloat16*)al,
        (const __nv_bfloat16*)bth, (const __nv_bfloat16*)btl, b_proj, out);
}

// round 7
// speedup vs baseline: 4.0834x; 1.1781x over previous
#include <cuda_runtime.h>
#include <cuda_bf16.h>
#include <cuda_fp16.h>
#include <math.h>
#include <stdint.h>

#define Bn 2
#define Tn 2048
#define Cn 1024
#define Hn 16
#define Dn 64
#define Mn (Bn*Tn)          // 4096
#define BHn (Bn*Hn)         // 32

typedef unsigned long long ull;

// ---------------- device scratch ----------------
__device__ __nv_bfloat16 g_Qh[BHn*Tn*Dn];   // head-major, pre-scaled by 0.125
__device__ __nv_bfloat16 g_Ql[BHn*Tn*Dn];
__device__ __nv_bfloat16 g_Kh[BHn*Tn*Dn];
__device__ __nv_bfloat16 g_Kl[BHn*Tn*Dn];
__device__ float         g_V [BHn*Tn*Dn];   // raw v (fp32) for zmax
__device__ __nv_bfloat16 g_Vh[BHn*Tn*Dn];
__device__ __nv_bfloat16 g_Vl[BHn*Tn*Dn];
__device__ float g_zmax[Bn*Cn];
__device__ float g_zpart[16*Bn*Cn];
__device__ __half gA_hi[Mn*Cn];             // fp16 A operand (x split, then Y from FA)
__device__ __half gA_lo[Mn*Cn];
__device__ __half gBT_hi[3*Cn*Cn];          // fp16 weights^T (hi only)

__device__ __forceinline__ float clamp_p(float pp) {
    float sgn = (pp >= 0.0f) ? 1.0f : -1.0f;
    return sgn * fminf(fmaxf(fabsf(pp), 1e-4f), 1e3f);
}

// ---------------- ptx helpers ----------------
__device__ __forceinline__ uint32_t smem_u32(const void* p) {
    uint32_t a;
    asm("{ .reg .u64 t; cvta.to.shared.u64 t, %1; cvt.u32.u64 %0, t; }" : "=r"(a) : "l"(p));
    return a;
}
__device__ __forceinline__ void cp16(uint32_t dst, const void* src) {
    asm volatile("cp.async.cg.shared.global [%0], [%1], 16;\n" :: "r"(dst), "l"(src));
}
#define CP_COMMIT() asm volatile("cp.async.commit_group;\n" ::: "memory")

__device__ __forceinline__ void ldsm4(uint32_t& r0, uint32_t& r1, uint32_t& r2, uint32_t& r3,
                                      uint32_t addr) {
    asm volatile("ldmatrix.sync.aligned.m8n8.x4.shared.b16 {%0,%1,%2,%3}, [%4];"
                 : "=r"(r0), "=r"(r1), "=r"(r2), "=r"(r3) : "r"(addr));
}
__device__ __forceinline__ void ldsm4t(uint32_t& r0, uint32_t& r1, uint32_t& r2, uint32_t& r3,
                                       uint32_t addr) {
    asm volatile("ldmatrix.sync.aligned.m8n8.x4.trans.shared.b16 {%0,%1,%2,%3}, [%4];"
                 : "=r"(r0), "=r"(r1), "=r"(r2), "=r"(r3) : "r"(addr));
}
__device__ __forceinline__ void mma16816(float* c, const uint32_t* a, const uint32_t* b) {
    asm volatile(
        "mma.sync.aligned.m16n8k16.row.col.f32.bf16.bf16.f32 "
        "{%0,%1,%2,%3}, {%4,%5,%6,%7}, {%8,%9}, {%0,%1,%2,%3};"
        : "+f"(c[0]), "+f"(c[1]), "+f"(c[2]), "+f"(c[3])
        : "r"(a[0]), "r"(a[1]), "r"(a[2]), "r"(a[3]), "r"(b[0]), "r"(b[1]));
}
__device__ __forceinline__ void mma16816h(float* c, const uint32_t* a, const uint32_t* b) {
    asm volatile(
        "mma.sync.aligned.m16n8k16.row.col.f32.f16.f16.f32 "
        "{%0,%1,%2,%3}, {%4,%5,%6,%7}, {%8,%9}, {%0,%1,%2,%3};"
        : "+f"(c[0]), "+f"(c[1]), "+f"(c[2]), "+f"(c[3])
        : "r"(a[0]), "r"(a[1]), "r"(a[2]), "r"(a[3]), "r"(b[0]), "r"(b[1]));
}
__device__ __forceinline__ uint32_t pkbf(float lo, float hi) {
    uint32_t r;
    asm("cvt.rn.bf16x2.f32 %0, %1, %2;" : "=r"(r) : "f"(hi), "f"(lo));
    return r;
}
__device__ __forceinline__ uint32_t pkhf(float lo, float hi) {
    uint32_t r;
    asm("cvt.rn.f16x2.f32 %0, %1, %2;" : "=r"(r) : "f"(hi), "f"(lo));
    return r;
}
__device__ __forceinline__ float2 unpkhf(uint32_t u) {
    __half2 h = *reinterpret_cast<__half2*>(&u);
    return __half22float2(h);
}

// ---------------------------------------------------------------------------
// split: fp32 -> fp16 hi/lo
// ---------------------------------------------------------------------------
__global__ __launch_bounds__(256) void split_fp16(
    const float* __restrict__ A, __half* __restrict__ Ah, __half* __restrict__ Al)
{
    int i = blockIdx.x * 256 + threadIdx.x;
    float4 a = ((const float4*)A)[i];
    uint32_t h0 = pkhf(a.x, a.y), h1 = pkhf(a.z, a.w);
    float2 u0 = unpkhf(h0), u1 = unpkhf(h1);
    uint32_t l0 = pkhf(a.x - u0.x, a.y - u0.y);
    uint32_t l1 = pkhf(a.z - u1.x, a.w - u1.y);
    ((uint32_t*)Ah)[2*i]   = h0;
    ((uint32_t*)Ah)[2*i+1] = h1;
    ((uint32_t*)Al)[2*i]   = l0;
    ((uint32_t*)Al)[2*i+1] = l1;
}

// ---------------------------------------------------------------------------
// transpose: W[K=1024][Nd] -> Th[Nd][1024] (fp16 hi only)
// ---------------------------------------------------------------------------
__global__ void transpose_h(const float* __restrict__ W,
                            __half* __restrict__ Th, int Nd)
{
    __shared__ float tile[32][33];
    int nx = blockIdx.x * 32, kx = blockIdx.y * 32;
    int tx = threadIdx.x, ty = threadIdx.y;
#pragma unroll
    for (int r = ty; r < 32; r += 8)
        tile[r][tx] = W[(size_t)(kx + r) * Nd + nx + tx];
    __syncthreads();
#pragma unroll
    for (int r = ty; r < 32; r += 8) {
        size_t o = (size_t)(nx + r) * 1024 + kx + tx;
        Th[o] = __float2half_rn(tile[tx][r]);
    }
}

// ---------------------------------------------------------------------------
// fp16x2 mma.sync GEMM: CTA 256x128, warp tile 64x64 (4x2 warps), BK=64,
// cp.async double buffer. D = (Ah+Al) @ Bh^T.
// MODE 0: out+bias. MODE 1: QKV scatter (Q/K bf16 hi/lo, V fp32).
// ---------------------------------------------------------------------------
#define AHI_OFF 0
#define ALO_OFF 32768
#define BHI_OFF 65536
#define STG_BYTES 81920
#define TCG_SMEM (2*STG_BYTES)   // 160 KB

__device__ __forceinline__ void load_stage(
    uint32_t sbase,
    const __half* __restrict__ Ah, const __half* __restrict__ Al,
    const __half* __restrict__ Bh,
    int m0, int n0, int k0, int tid)
{
#pragma unroll
    for (int j = 0; j < 8; j++) {          // A: 256 rows x 8 chunks
        int idx = tid + j * 256;
        int row = idx >> 3, c = idx & 7;
        uint32_t sw = row * 128 + ((c ^ (row & 7)) << 4);
        size_t ga = (size_t)(m0 + row) * 1024 + k0 + c * 8;
        cp16(sbase + AHI_OFF + sw, Ah + ga);
        cp16(sbase + ALO_OFF + sw, Al + ga);
    }
#pragma unroll
    for (int j = 0; j < 4; j++) {          // B: 128 rows x 8 chunks (hi only)
        int idx = tid + j * 256;
        int row = idx >> 3, c = idx & 7;
        uint32_t sw = row * 128 + ((c ^ (row & 7)) << 4);
        size_t gb = (size_t)(n0 + row) * 1024 + k0 + c * 8;
        cp16(sbase + BHI_OFF + sw, Bh + gb);
    }
}

template<int MODE>
__global__ __launch_bounds__(256) void tc_gemm(
    const __half* __restrict__ Ah, const __half* __restrict__ Al,
    const __half* __restrict__ Bh,
    const float* __restrict__ bias, float* __restrict__ Cout)
{
    extern __shared__ char smem[];
    uint32_t sb = smem_u32(smem);
    const int tid  = threadIdx.x;
    const int wid  = tid >> 5;
    const int lane = tid & 31;
    const int wm = wid >> 1;       // 4 warp-rows of 64
    const int wn = wid & 1;        // 2 warp-cols of 64
    const int m0 = blockIdx.y * 256;
    const int n0 = blockIdx.x * 128;

    float acc[4][8][4];
#pragma unroll
    for (int i = 0; i < 4; i++)
#pragma unroll
        for (int j = 0; j < 8; j++)
#pragma unroll
            for (int q = 0; q < 4; q++) acc[i][j][q] = 0.0f;

    load_stage(sb,             Ah, Al, Bh, m0, n0, 0,  tid); CP_COMMIT();
    load_stage(sb + STG_BYTES, Ah, Al, Bh, m0, n0, 64, tid); CP_COMMIT();

    const int a_row = wm * 64 + (lane & 15);
    const int a_c16 = (lane >> 4);
    const int b_row = wn * 64 + ((lane >> 4) << 3) + (lane & 7);
    const int b_cof = ((lane >> 3) & 1);

    for (int it = 0; it < 16; it++) {
        const int s = it & 1;
        const uint32_t sbase = sb + s * STG_BYTES;
        if (it < 15) asm volatile("cp.async.wait_group 1;\n" ::: "memory");
        else         asm volatile("cp.async.wait_group 0;\n" ::: "memory");
        __syncthreads();

#pragma unroll
        for (int ks = 0; ks < 4; ks++) {
            uint32_t ahi[4][4], alo[4][4];
#pragma unroll
            for (int mf = 0; mf < 4; mf++) {
                int row = a_row + mf * 16;
                int c16 = ks * 2 + a_c16;
                uint32_t ad = sbase + row * 128 + ((c16 ^ (row & 7)) << 4);
                ldsm4(ahi[mf][0], ahi[mf][1], ahi[mf][2], ahi[mf][3], ad + AHI_OFF);
                ldsm4(alo[mf][0], alo[mf][1], alo[mf][2], alo[mf][3], ad + ALO_OFF);
            }
#pragma unroll
            for (int nf2 = 0; nf2 < 4; nf2++) {
                int row = b_row + nf2 * 16;
                int c16 = ks * 2 + b_cof;
                uint32_t bd = sbase + row * 128 + ((c16 ^ (row & 7)) << 4);
                uint32_t bh4[4];
                ldsm4(bh4[0], bh4[1], bh4[2], bh4[3], bd + BHI_OFF);
#pragma unroll
                for (int mf = 0; mf < 4; mf++) {
                    mma16816h(acc[mf][2*nf2],   ahi[mf], bh4);
                    mma16816h(acc[mf][2*nf2],   alo[mf], bh4);
                    mma16816h(acc[mf][2*nf2+1], ahi[mf], bh4 + 2);
                    mma16816h(acc[mf][2*nf2+1], alo[mf], bh4 + 2);
                }
            }
        }
        __syncthreads();
        if (it + 2 < 16) {
            load_stage(sbase, Ah, Al, Bh, m0, n0, (it + 2) * 64, tid);
            CP_COMMIT();
        }
    }

    const int mbase = m0 + wm * 64 + (lane >> 2);
    const int nbase = n0 + wn * 64 + (lane & 3) * 2;
#pragma unroll
    for (int mf = 0; mf < 4; mf++) {
#pragma unroll
        for (int half = 0; half < 2; half++) {
            int m = mbase + mf * 16 + half * 8;
#pragma unroll
            for (int nf = 0; nf < 8; nf++) {
                int n = nbase + nf * 8;
                float v0 = acc[mf][nf][half*2+0] + bias[n];
                float v1 = acc[mf][nf][half*2+1] + bias[n+1];
                if (MODE == 0) {
                    *(float2*)(Cout + (size_t)m * Cn + n) = make_float2(v0, v1);
                } else {
                    int sec = n >> 10;
                    int c1  = n & 1023;
                    int h   = c1 >> 6, dd = c1 & 63;
                    int bq  = m >> 11, t = m & 2047;
                    size_t idx = ((size_t)((bq * Hn + h) * Tn + t)) * 64 + dd;
                    if (sec == 2) {
                        *(float2*)(g_V + idx) = make_float2(v0, v1);
                    } else {
                        if (sec == 0) { v0 *= 0.125f; v1 *= 0.125f; }
                        uint32_t hh = pkbf(v0, v1);
                        float f0 = __uint_as_float(hh << 16);
                        float f1 = __uint_as_float(hh & 0xffff0000u);
                        uint32_t ll = pkbf(v0 - f0, v1 - f1);
                        if (sec == 0) {
                            *(uint32_t*)(g_Qh + idx) = hh;
                            *(uint32_t*)(g_Ql + idx) = ll;
                        } else {
                            *(uint32_t*)(g_Kh + idx) = hh;
                            *(uint32_t*)(g_Kl + idx) = ll;
                        }
                    }
                }
            }
        }
    }
}

// ---------------------------------------------------------------------------
// z_max partial: grid (32 bh, 16 chunks of 128 t), float4 over d
// ---------------------------------------------------------------------------
__global__ __launch_bounds__(256) void zmax_part(const float* __restrict__ p_param)
{
    int bh = blockIdx.x, chunk = blockIdx.y;
    int b = bh >> 4, h = bh & 15;
    int d4 = threadIdx.x & 15;
    int g  = threadIdx.x >> 4;
    int c  = h*64 + d4*4;
    float4 pv;
    pv.x = clamp_p(p_param[c+0]); pv.y = clamp_p(p_param[c+1]);
    pv.z = clamp_p(p_param[c+2]); pv.w = clamp_p(p_param[c+3]);

    const float* vp = g_V + (size_t)bh * Tn * 64;
    float4 mx = make_float4(-1e30f, -1e30f, -1e30f, -1e30f);
    for (int t = chunk*128 + g; t < (chunk+1)*128; t += 16) {
        float4 v = *(const float4*)(vp + t*64 + d4*4);
        mx.x = fmaxf(mx.x, pv.x * logf(fmaxf(fabsf(v.x + 5.0f), 1e-10f)));
        mx.y = fmaxf(mx.y, pv.y * logf(fmaxf(fabsf(v.y + 5.0f), 1e-10f)));
        mx.z = fmaxf(mx.z, pv.z * logf(fmaxf(fabsf(v.z + 5.0f), 1e-10f)));
        mx.w = fmaxf(mx.w, pv.w * logf(fmaxf(fabsf(v.w + 5.0f), 1e-10f)));
    }
    __shared__ float4 red[256];
    red[threadIdx.x] = mx;
    __syncthreads();
    if (threadIdx.x < 16) {
        float4 m = red[threadIdx.x];
#pragma unroll
        for (int gg = 1; gg < 16; gg++) {
            float4 o = red[gg*16 + threadIdx.x];
            m.x = fmaxf(m.x, o.x); m.y = fmaxf(m.y, o.y);
            m.z = fmaxf(m.z, o.z); m.w = fmaxf(m.w, o.w);
        }
        *(float4*)(g_zpart + chunk*(Bn*Cn) + b*Cn + h*64 + threadIdx.x*4) = m;
    }
}
__global__ __launch_bounds__(256) void zmax_reduce()
{
    int i = blockIdx.x * 256 + threadIdx.x;
    float mx = -1e30f;
#pragma unroll
    for (int ch = 0; ch < 16; ch++) mx = fmaxf(mx, g_zpart[ch*(Bn*Cn) + i]);
    g_zmax[i] = mx;
}

// ---------------------------------------------------------------------------
// V transform -> bf16 hi/lo (float4 per thread)
// ---------------------------------------------------------------------------
__global__ __launch_bounds__(256) void vexp_kernel(const float* __restrict__ p_param)
{
    int i = blockIdx.x * 256 + threadIdx.x;
    int base = i * 4;
    int dd = base & 63;
    int bh = base >> 17;
    int h = bh & 15, b = bh >> 4;
    int c = h*64 + dd;
    float4 v = *(const float4*)(g_V + base);
    float e[4];
    const float vs[4] = {v.x, v.y, v.z, v.w};
#pragma unroll
    for (int j = 0; j < 4; j++) {
        float pvj = clamp_p(p_param[c + j]);
        float z = pvj * logf(fmaxf(fabsf(vs[j] + 5.0f), 1e-10f)) - g_zmax[b*Cn + c + j];
        e[j] = expf(z);
    }
    uint32_t h0 = pkbf(e[0], e[1]), h1 = pkbf(e[2], e[3]);
    float f0 = __uint_as_float(h0 << 16), f1 = __uint_as_float(h0 & 0xffff0000u);
    float f2 = __uint_as_float(h1 << 16), f3 = __uint_as_float(h1 & 0xffff0000u);
    uint32_t l0 = pkbf(e[0]-f0, e[1]-f1), l1 = pkbf(e[2]-f2, e[3]-f3);
    ((uint2*)g_Vh)[i] = make_uint2(h0, h1);
    ((uint2*)g_Vl)[i] = make_uint2(l0, l1);
}

// ---------------------------------------------------------------------------
// Tensor-core flash attention (causal), BQ=BK=128, 8 warps, 16q x 128kv strip
// per warp; bf16x3; P from S accumulator frags; ldsm4-paired loads.
// Epilogue writes Y as fp16 hi/lo into gA_hi/gA_lo.
// ---------------------------------------------------------------------------
#define FAQ_H 0
#define FAQ_L 16384
#define FASTG0 32768
#define FASTG_SZ 65536
#define FKH 0
#define FKL 16384
#define FVH 32768
#define FVL 49152
#define FA_SMEM (32768 + 2*FASTG_SZ)   // 160 KB

__device__ __forceinline__ void fa_load_stage(uint32_t sbase, int bh, int kt, int tid)
{
    const __nv_bfloat16* srcs[4] = {g_Kh, g_Kl, g_Vh, g_Vl};
#pragma unroll
    for (int j = 0; j < 16; j++) {
        int idx = tid + j * 256;
        int arr = idx >> 10;
        int rem = idx & 1023;
        int row = rem >> 3, c = rem & 7;
        uint32_t sw = arr * 16384 + row * 128 + ((c ^ (row & 7)) << 4);
        size_t g = ((size_t)bh * Tn + kt * 128 + row) * 64 + c * 8;
        cp16(sbase + sw, srcs[arr] + g);
    }
}

__global__ __launch_bounds__(256) void fa_kernel(const float* __restrict__ p_param)
{
    extern __shared__ char smem[];
    uint32_t sb = smem_u32(smem);
    const int tid  = threadIdx.x;
    const int w    = tid >> 5;
    const int lane = tid & 31;
    const int quad = lane >> 2;
    const int idq  = lane & 3;
    const int bh = blockIdx.y;
    const int b = bh >> 4, h = bh & 15;
    const int qt = (int)gridDim.x - 1 - (int)blockIdx.x;
    const int q0 = qt * 128;

    {
        const __nv_bfloat16* qs[2] = {g_Qh, g_Ql};
#pragma unroll
        for (int j = 0; j < 8; j++) {
            int idx = tid + j * 256;
            int arr = idx >> 10;
            int rem = idx & 1023;
            int row = rem >> 3, c = rem & 7;
            uint32_t sw = arr * 16384 + row * 128 + ((c ^ (row & 7)) << 4);
            size_t g = ((size_t)bh * Tn + q0 + row) * 64 + c * 8;
            cp16(sb + sw, qs[arr] + g);
        }
        fa_load_stage(sb + FASTG0, bh, 0, tid);
        CP_COMMIT();
        if (qt >= 1) fa_load_stage(sb + FASTG0 + FASTG_SZ, bh, 1, tid);
        CP_COMMIT();
    }

    uint32_t Qh[4][4], Ql[4][4];
    float Of[8][4];
    float m0 = -1e30f, m1 = -1e30f, l0 = 0.0f, l1 = 0.0f;
#pragma unroll
    for (int nf = 0; nf < 8; nf++)
#pragma unroll
        for (int q = 0; q < 4; q++) Of[nf][q] = 0.0f;

    const int k_row = ((lane >> 4) << 3) + (lane & 7);
    const int k_cof = ((lane >> 3) & 1);
    const int v_row = (lane & 15);
    const int v_cof = (lane >> 4);

    for (int kt = 0; kt <= qt; kt++) {
        const uint32_t sbase = sb + FASTG0 + (kt & 1) * FASTG_SZ;
        if (kt < qt) asm volatile("cp.async.wait_group 1;\n" ::: "memory");
        else         asm volatile("cp.async.wait_group 0;\n" ::: "memory");
        __syncthreads();

        if (kt == 0) {
            int row = w * 16 + (lane & 15);
#pragma unroll
            for (int ks = 0; ks < 4; ks++) {
                int c16 = ks * 2 + (lane >> 4);
                uint32_t sw = row * 128 + ((c16 ^ (row & 7)) << 4);
                ldsm4(Qh[ks][0], Qh[ks][1], Qh[ks][2], Qh[ks][3], sb + FAQ_H + sw);
                ldsm4(Ql[ks][0], Ql[ks][1], Ql[ks][2], Ql[ks][3], sb + FAQ_L + sw);
            }
        }

        float Sf[16][4];
#pragma unroll
        for (int nf = 0; nf < 16; nf++)
#pragma unroll
            for (int q = 0; q < 4; q++) Sf[nf][q] = 0.0f;

#pragma unroll
        for (int nf2 = 0; nf2 < 8; nf2++) {
            int krow = nf2 * 16 + k_row;
#pragma unroll
            for (int ks = 0; ks < 4; ks++) {
                int c16 = ks * 2 + k_cof;
                uint32_t sw = krow * 128 + ((c16 ^ (krow & 7)) << 4);
                uint32_t kh[4], kl[4];
                ldsm4(kh[0], kh[1], kh[2], kh[3], sbase + FKH + sw);
                ldsm4(kl[0], kl[1], kl[2], kl[3], sbase + FKL + sw);
                mma16816(Sf[2*nf2],   Qh[ks], kh);
                mma16816(Sf[2*nf2],   Ql[ks], kh);
                mma16816(Sf[2*nf2],   Qh[ks], kl);
                mma16816(Sf[2*nf2+1], Qh[ks], kh + 2);
                mma16816(Sf[2*nf2+1], Ql[ks], kh + 2);
                mma16816(Sf[2*nf2+1], Qh[ks], kl + 2);
            }
        }

        if (kt == qt) {
            int r0 = w * 16 + quad, r1 = r0 + 8;
#pragma unroll
            for (int nf = 0; nf < 16; nf++) {
                int c0 = nf * 8 + idq * 2;
                if (c0     > r0) Sf[nf][0] = -1e30f;
                if (c0 + 1 > r0) Sf[nf][1] = -1e30f;
                if (c0     > r1) Sf[nf][2] = -1e30f;
                if (c0 + 1 > r1) Sf[nf][3] = -1e30f;
            }
        }

        float mx0 = -1e30f, mx1 = -1e30f;
#pragma unroll
        for (int nf = 0; nf < 16; nf++) {
            mx0 = fmaxf(mx0, fmaxf(Sf[nf][0], Sf[nf][1]));
            mx1 = fmaxf(mx1, fmaxf(Sf[nf][2], Sf[nf][3]));
        }
#pragma unroll
        for (int off = 1; off < 4; off <<= 1) {
            mx0 = fmaxf(mx0, __shfl_xor_sync(0xffffffffu, mx0, off));
            mx1 = fmaxf(mx1, __shfl_xor_sync(0xffffffffu, mx1, off));
        }
        mx0 = fmaxf(mx0, m0);
        mx1 = fmaxf(mx1, m1);
        float a0 = __expf(m0 - mx0), a1 = __expf(m1 - mx1);
        m0 = mx0; m1 = mx1;

        float s0 = 0.0f, s1 = 0.0f;
#pragma unroll
        for (int nf = 0; nf < 16; nf++) {
            Sf[nf][0] = __expf(Sf[nf][0] - mx0);
            Sf[nf][1] = __expf(Sf[nf][1] - mx0);
            Sf[nf][2] = __expf(Sf[nf][2] - mx1);
            Sf[nf][3] = __expf(Sf[nf][3] - mx1);
            s0 += Sf[nf][0] + Sf[nf][1];
            s1 += Sf[nf][2] + Sf[nf][3];
        }
#pragma unroll
        for (int off = 1; off < 4; off <<= 1) {
            s0 += __shfl_xor_sync(0xffffffffu, s0, off);
            s1 += __shfl_xor_sync(0xffffffffu, s1, off);
        }
        l0 = l0 * a0 + s0;
        l1 = l1 * a1 + s1;

#pragma unroll
        for (int nf = 0; nf < 8; nf++) {
            Of[nf][0] *= a0; Of[nf][1] *= a0;
            Of[nf][2] *= a1; Of[nf][3] *= a1;
        }

#pragma unroll
        for (int kf = 0; kf < 8; kf++) {
            uint32_t pha[4], pla[4];
#pragma unroll
            for (int half = 0; half < 2; half++) {
                float* sp = Sf[2*kf + half];
                uint32_t u0 = pkbf(sp[0], sp[1]);
                uint32_t u1 = pkbf(sp[2], sp[3]);
                float f00 = __uint_as_float(u0 << 16), f01 = __uint_as_float(u0 & 0xffff0000u);
                float f10 = __uint_as_float(u1 << 16), f11 = __uint_as_float(u1 & 0xffff0000u);
                pha[half*2+0] = u0;
                pha[half*2+1] = u1;
                pla[half*2+0] = pkbf(sp[0] - f00, sp[1] - f01);
                pla[half*2+1] = pkbf(sp[2] - f10, sp[3] - f11);
            }
            int vrow = kf * 16 + v_row;
#pragma unroll
            for (int nf2 = 0; nf2 < 4; nf2++) {
                int c16 = nf2 * 2 + v_cof;
                uint32_t sw = vrow * 128 + ((c16 ^ (vrow & 7)) << 4);
                uint32_t vh[4], vl[4];
                ldsm4t(vh[0], vh[1], vh[2], vh[3], sbase + FVH + sw);
                ldsm4t(vl[0], vl[1], vl[2], vl[3], sbase + FVL + sw);
                mma16816(Of[2*nf2],   pha, vh);
                mma16816(Of[2*nf2],   pla, vh);
                mma16816(Of[2*nf2],   pha, vl);
                mma16816(Of[2*nf2+1], pha, vh + 2);
                mma16816(Of[2*nf2+1], pla, vh + 2);
                mma16816(Of[2*nf2+1], pha, vl + 2);
            }
        }

        __syncthreads();
        if (kt + 2 <= qt) {
            fa_load_stage(sbase, bh, kt + 2, tid);
            CP_COMMIT();
        }
    }

    // ---- epilogue: y = exp((zmax + log(O/l))/p) - 5, write fp16 hi/lo ----
    const int t0 = q0 + w * 16 + quad;
    const int t1 = t0 + 8;
    float linv0 = 1.0f / l0, linv1 = 1.0f / l1;
#pragma unroll
    for (int nf = 0; nf < 8; nf++) {
        int d0 = nf * 8 + idq * 2;
        int cg = h * 64 + d0;
        float pv0 = clamp_p(p_param[cg]);
        float pv1 = clamp_p(p_param[cg + 1]);
        float zm0 = g_zmax[b*Cn + cg];
        float zm1 = g_zmax[b*Cn + cg + 1];
        float y00 = expf((zm0 + logf(Of[nf][0] * linv0)) / pv0) - 5.0f;
        float y01 = expf((zm1 + logf(Of[nf][1] * linv0)) / pv1) - 5.0f;
        float y10 = expf((zm0 + logf(Of[nf][2] * linv1)) / pv0) - 5.0f;
        float y11 = expf((zm1 + logf(Of[nf][3] * linv1)) / pv1) - 5.0f;
        uint32_t h0 = pkhf(y00, y01);
        float2 u0 = unpkhf(h0);
        uint32_t l0p = pkhf(y00 - u0.x, y01 - u0.y);
        uint32_t h1 = pkhf(y10, y11);
        float2 u1 = unpkhf(h1);
        uint32_t l1p = pkhf(y10 - u1.x, y11 - u1.y);
        size_t i0 = ((size_t)(b*Tn + t0)*Cn + cg) >> 1;
        size_t i1 = ((size_t)(b*Tn + t1)*Cn + cg) >> 1;
        ((uint32_t*)gA_hi)[i0] = h0;
        ((uint32_t*)gA_lo)[i0] = l0p;
        ((uint32_t*)gA_hi)[i1] = h1;
        ((uint32_t*)gA_lo)[i1] = l1p;
    }
}

// ---------------------------------------------------------------------------

extern "C" void kernel_launch(void* const* d_in, const int* in_sizes, int n_in,
                              void* d_out, int out_size)
{
    const float* x       = (const float*)d_in[0];
    const float* w_attn  = (const float*)d_in[1];
    const float* b_attn  = (const float*)d_in[2];
    const float* w_proj  = (const float*)d_in[3];
    const float* b_proj  = (const float*)d_in[4];
    const float* p_param = (const float*)d_in[5];
    float* out = (float*)d_out;

    void *ah, *al, *bth;
    cudaGetSymbolAddress(&ah,  gA_hi);
    cudaGetSymbolAddress(&al,  gA_lo);
    cudaGetSymbolAddress(&bth, gBT_hi);

    cudaFuncSetAttribute(fa_kernel, cudaFuncAttributeMaxDynamicSharedMemorySize, FA_SMEM);
    cudaFuncSetAttribute(tc_gemm<0>, cudaFuncAttributeMaxDynamicSharedMemorySize, TCG_SMEM);
    cudaFuncSetAttribute(tc_gemm<1>, cudaFuncAttributeMaxDynamicSharedMemorySize, TCG_SMEM);

    // 1) split x (fp16 hi/lo); transpose w_attn (fp16 hi)
    split_fp16<<<Mn*Cn/1024, 256>>>(x, (__half*)ah, (__half*)al);
    transpose_h<<<dim3(3072/32, Cn/32), dim3(32,8)>>>(w_attn, (__half*)bth, 3072);

    // 2) QKV GEMM (fp16x2) + bf16 hi/lo head-major scatter (Q pre-scaled)
    tc_gemm<1><<<dim3(3072/128, Mn/256), 256, TCG_SMEM>>>(
        (const __half*)ah, (const __half*)al, (const __half*)bth, b_attn, nullptr);

    // 3) z_max (partial + reduce) + V transform -> bf16 hi/lo
    zmax_part<<<dim3(BHn, 16), 256>>>(p_param);
    zmax_reduce<<<(Bn*Cn)/256, 256>>>();
    vexp_kernel<<<(BHn*Tn*Dn)/1024, 256>>>(p_param);

    // 4) tensor-core causal FA (bf16x3); epilogue writes Y fp16 hi/lo into gA
    fa_kernel<<<dim3(Tn/128, BHn), 256, FA_SMEM>>>(p_param);

    // 5) transpose w_proj (fp16 hi); proj GEMM (fp16x2)
    transpose_h<<<dim3(Cn/32, Cn/32), dim3(32,8)>>>(w_proj, (__half*)bth, Cn);
    tc_gemm<0><<<dim3(Cn/128, Mn/256), 256, TCG_SMEM>>>(
        (const __half*)ah, (const __half*)al, (const __half*)bth, b_proj, out);
}

// round 8
// speedup vs baseline: 4.2952x; 1.0519x over previous
#include <cuda_runtime.h>
#include <cuda_bf16.h>
#include <cuda_fp16.h>
#include <math.h>
#include <stdint.h>

#define Bn 2
#define Tn 2048
#define Cn 1024
#define Hn 16
#define Dn 64
#define Mn (Bn*Tn)          // 4096
#define BHn (Bn*Hn)         // 32

typedef unsigned long long ull;

// ---------------- device scratch ----------------
__device__ __nv_bfloat16 g_Qh[BHn*Tn*Dn];   // head-major, pre-scaled by 0.125
__device__ __nv_bfloat16 g_Ql[BHn*Tn*Dn];
__device__ __nv_bfloat16 g_Kh[BHn*Tn*Dn];
__device__ __nv_bfloat16 g_Kl[BHn*Tn*Dn];
__device__ float         g_V [BHn*Tn*Dn];   // raw v (fp32) for zmax
__device__ __nv_bfloat16 g_Vh[BHn*Tn*Dn];
__device__ __nv_bfloat16 g_Vl[BHn*Tn*Dn];
__device__ float g_zmax[Bn*Cn];
__device__ float g_zpart[16*Bn*Cn];
__device__ __half gA_hi[Mn*Cn];             // fp16 A operand (x split, then Y from FA)
__device__ __half gA_lo[Mn*Cn];
__device__ __half gBT_hi[3*Cn*Cn];          // fp16 weights^T (hi only)

__device__ __forceinline__ float clamp_p(float pp) {
    float sgn = (pp >= 0.0f) ? 1.0f : -1.0f;
    return sgn * fminf(fmaxf(fabsf(pp), 1e-4f), 1e3f);
}

// ---------------- ptx helpers ----------------
__device__ __forceinline__ uint32_t smem_u32(const void* p) {
    uint32_t a;
    asm("{ .reg .u64 t; cvta.to.shared.u64 t, %1; cvt.u32.u64 %0, t; }" : "=r"(a) : "l"(p));
    return a;
}
__device__ __forceinline__ void cp16(uint32_t dst, const void* src) {
    asm volatile("cp.async.cg.shared.global [%0], [%1], 16;\n" :: "r"(dst), "l"(src));
}
#define CP_COMMIT() asm volatile("cp.async.commit_group;\n" ::: "memory")

__device__ __forceinline__ void ldsm4(uint32_t& r0, uint32_t& r1, uint32_t& r2, uint32_t& r3,
                                      uint32_t addr) {
    asm volatile("ldmatrix.sync.aligned.m8n8.x4.shared.b16 {%0,%1,%2,%3}, [%4];"
                 : "=r"(r0), "=r"(r1), "=r"(r2), "=r"(r3) : "r"(addr));
}
__device__ __forceinline__ void ldsm4t(uint32_t& r0, uint32_t& r1, uint32_t& r2, uint32_t& r3,
                                       uint32_t addr) {
    asm volatile("ldmatrix.sync.aligned.m8n8.x4.trans.shared.b16 {%0,%1,%2,%3}, [%4];"
                 : "=r"(r0), "=r"(r1), "=r"(r2), "=r"(r3) : "r"(addr));
}
__device__ __forceinline__ void mma16816(float* c, const uint32_t* a, const uint32_t* b) {
    asm volatile(
        "mma.sync.aligned.m16n8k16.row.col.f32.bf16.bf16.f32 "
        "{%0,%1,%2,%3}, {%4,%5,%6,%7}, {%8,%9}, {%0,%1,%2,%3};"
        : "+f"(c[0]), "+f"(c[1]), "+f"(c[2]), "+f"(c[3])
        : "r"(a[0]), "r"(a[1]), "r"(a[2]), "r"(a[3]), "r"(b[0]), "r"(b[1]));
}
__device__ __forceinline__ void mma16816h(float* c, const uint32_t* a, const uint32_t* b) {
    asm volatile(
        "mma.sync.aligned.m16n8k16.row.col.f32.f16.f16.f32 "
        "{%0,%1,%2,%3}, {%4,%5,%6,%7}, {%8,%9}, {%0,%1,%2,%3};"
        : "+f"(c[0]), "+f"(c[1]), "+f"(c[2]), "+f"(c[3])
        : "r"(a[0]), "r"(a[1]), "r"(a[2]), "r"(a[3]), "r"(b[0]), "r"(b[1]));
}
__device__ __forceinline__ uint32_t pkbf(float lo, float hi) {
    uint32_t r;
    asm("cvt.rn.bf16x2.f32 %0, %1, %2;" : "=r"(r) : "f"(hi), "f"(lo));
    return r;
}
__device__ __forceinline__ uint32_t pkhf(float lo, float hi) {
    uint32_t r;
    asm("cvt.rn.f16x2.f32 %0, %1, %2;" : "=r"(r) : "f"(hi), "f"(lo));
    return r;
}
__device__ __forceinline__ float2 unpkhf(uint32_t u) {
    __half2 h = *reinterpret_cast<__half2*>(&u);
    return __half22float2(h);
}

// ---------------------------------------------------------------------------
// split: fp32 -> fp16 hi/lo
// ---------------------------------------------------------------------------
__global__ __launch_bounds__(256) void split_fp16(
    const float* __restrict__ A, __half* __restrict__ Ah, __half* __restrict__ Al)
{
    int i = blockIdx.x * 256 + threadIdx.x;
    float4 a = ((const float4*)A)[i];
    uint32_t h0 = pkhf(a.x, a.y), h1 = pkhf(a.z, a.w);
    float2 u0 = unpkhf(h0), u1 = unpkhf(h1);
    uint32_t l0 = pkhf(a.x - u0.x, a.y - u0.y);
    uint32_t l1 = pkhf(a.z - u1.x, a.w - u1.y);
    ((uint32_t*)Ah)[2*i]   = h0;
    ((uint32_t*)Ah)[2*i+1] = h1;
    ((uint32_t*)Al)[2*i]   = l0;
    ((uint32_t*)Al)[2*i+1] = l1;
}

// ---------------------------------------------------------------------------
// transpose: W[K=1024][Nd] -> Th[Nd][1024] (fp16 hi only)
// ---------------------------------------------------------------------------
__global__ void transpose_h(const float* __restrict__ W,
                            __half* __restrict__ Th, int Nd)
{
    __shared__ float tile[32][33];
    int nx = blockIdx.x * 32, kx = blockIdx.y * 32;
    int tx = threadIdx.x, ty = threadIdx.y;
#pragma unroll
    for (int r = ty; r < 32; r += 8)
        tile[r][tx] = W[(size_t)(kx + r) * Nd + nx + tx];
    __syncthreads();
#pragma unroll
    for (int r = ty; r < 32; r += 8) {
        size_t o = (size_t)(nx + r) * 1024 + kx + tx;
        Th[o] = __float2half_rn(tile[tx][r]);
    }
}

// ---------------------------------------------------------------------------
// fp16x2 mma.sync GEMM: CTA 256x128, warp tile 64x64 (4x2 warps), BK=64,
// cp.async double buffer. D = (Ah+Al) @ Bh^T.
// ---------------------------------------------------------------------------
#define AHI_OFF 0
#define ALO_OFF 32768
#define BHI_OFF 65536
#define STG_BYTES 81920
#define TCG_SMEM (2*STG_BYTES)   // 160 KB

__device__ __forceinline__ void load_stage(
    uint32_t sbase,
    const __half* __restrict__ Ah, const __half* __restrict__ Al,
    const __half* __restrict__ Bh,
    int m0, int n0, int k0, int tid)
{
#pragma unroll
    for (int j = 0; j < 8; j++) {
        int idx = tid + j * 256;
        int row = idx >> 3, c = idx & 7;
        uint32_t sw = row * 128 + ((c ^ (row & 7)) << 4);
        size_t ga = (size_t)(m0 + row) * 1024 + k0 + c * 8;
        cp16(sbase + AHI_OFF + sw, Ah + ga);
        cp16(sbase + ALO_OFF + sw, Al + ga);
    }
#pragma unroll
    for (int j = 0; j < 4; j++) {
        int idx = tid + j * 256;
        int row = idx >> 3, c = idx & 7;
        uint32_t sw = row * 128 + ((c ^ (row & 7)) << 4);
        size_t gb = (size_t)(n0 + row) * 1024 + k0 + c * 8;
        cp16(sbase + BHI_OFF + sw, Bh + gb);
    }
}

template<int MODE>
__global__ __launch_bounds__(256) void tc_gemm(
    const __half* __restrict__ Ah, const __half* __restrict__ Al,
    const __half* __restrict__ Bh,
    const float* __restrict__ bias, float* __restrict__ Cout)
{
    extern __shared__ char smem[];
    uint32_t sb = smem_u32(smem);
    const int tid  = threadIdx.x;
    const int wid  = tid >> 5;
    const int lane = tid & 31;
    const int wm = wid >> 1;
    const int wn = wid & 1;
    const int m0 = blockIdx.y * 256;
    const int n0 = blockIdx.x * 128;

    float acc[4][8][4];
#pragma unroll
    for (int i = 0; i < 4; i++)
#pragma unroll
        for (int j = 0; j < 8; j++)
#pragma unroll
            for (int q = 0; q < 4; q++) acc[i][j][q] = 0.0f;

    load_stage(sb,             Ah, Al, Bh, m0, n0, 0,  tid); CP_COMMIT();
    load_stage(sb + STG_BYTES, Ah, Al, Bh, m0, n0, 64, tid); CP_COMMIT();

    const int a_row = wm * 64 + (lane & 15);
    const int a_c16 = (lane >> 4);
    const int b_row = wn * 64 + ((lane >> 4) << 3) + (lane & 7);
    const int b_cof = ((lane >> 3) & 1);

    for (int it = 0; it < 16; it++) {
        const int s = it & 1;
        const uint32_t sbase = sb + s * STG_BYTES;
        if (it < 15) asm volatile("cp.async.wait_group 1;\n" ::: "memory");
        else         asm volatile("cp.async.wait_group 0;\n" ::: "memory");
        __syncthreads();

#pragma unroll
        for (int ks = 0; ks < 4; ks++) {
            uint32_t ahi[4][4], alo[4][4];
#pragma unroll
            for (int mf = 0; mf < 4; mf++) {
                int row = a_row + mf * 16;
                int c16 = ks * 2 + a_c16;
                uint32_t ad = sbase + row * 128 + ((c16 ^ (row & 7)) << 4);
                ldsm4(ahi[mf][0], ahi[mf][1], ahi[mf][2], ahi[mf][3], ad + AHI_OFF);
                ldsm4(alo[mf][0], alo[mf][1], alo[mf][2], alo[mf][3], ad + ALO_OFF);
            }
#pragma unroll
            for (int nf2 = 0; nf2 < 4; nf2++) {
                int row = b_row + nf2 * 16;
                int c16 = ks * 2 + b_cof;
                uint32_t bd = sbase + row * 128 + ((c16 ^ (row & 7)) << 4);
                uint32_t bh4[4];
                ldsm4(bh4[0], bh4[1], bh4[2], bh4[3], bd + BHI_OFF);
#pragma unroll
                for (int mf = 0; mf < 4; mf++) {
                    mma16816h(acc[mf][2*nf2],   ahi[mf], bh4);
                    mma16816h(acc[mf][2*nf2],   alo[mf], bh4);
                    mma16816h(acc[mf][2*nf2+1], ahi[mf], bh4 + 2);
                    mma16816h(acc[mf][2*nf2+1], alo[mf], bh4 + 2);
                }
            }
        }
        __syncthreads();
        if (it + 2 < 16) {
            load_stage(sbase, Ah, Al, Bh, m0, n0, (it + 2) * 64, tid);
            CP_COMMIT();
        }
    }

    const int mbase = m0 + wm * 64 + (lane >> 2);
    const int nbase = n0 + wn * 64 + (lane & 3) * 2;
#pragma unroll
    for (int mf = 0; mf < 4; mf++) {
#pragma unroll
        for (int half = 0; half < 2; half++) {
            int m = mbase + mf * 16 + half * 8;
#pragma unroll
            for (int nf = 0; nf < 8; nf++) {
                int n = nbase + nf * 8;
                float v0 = acc[mf][nf][half*2+0] + bias[n];
                float v1 = acc[mf][nf][half*2+1] + bias[n+1];
                if (MODE == 0) {
                    *(float2*)(Cout + (size_t)m * Cn + n) = make_float2(v0, v1);
                } else {
                    int sec = n >> 10;
                    int c1  = n & 1023;
                    int h   = c1 >> 6, dd = c1 & 63;
                    int bq  = m >> 11, t = m & 2047;
                    size_t idx = ((size_t)((bq * Hn + h) * Tn + t)) * 64 + dd;
                    if (sec == 2) {
                        *(float2*)(g_V + idx) = make_float2(v0, v1);
                    } else {
                        if (sec == 0) { v0 *= 0.125f; v1 *= 0.125f; }
                        uint32_t hh = pkbf(v0, v1);
                        float f0 = __uint_as_float(hh << 16);
                        float f1 = __uint_as_float(hh & 0xffff0000u);
                        uint32_t ll = pkbf(v0 - f0, v1 - f1);
                        if (sec == 0) {
                            *(uint32_t*)(g_Qh + idx) = hh;
                            *(uint32_t*)(g_Ql + idx) = ll;
                        } else {
                            *(uint32_t*)(g_Kh + idx) = hh;
                            *(uint32_t*)(g_Kl + idx) = ll;
                        }
                    }
                }
            }
        }
    }
}

// ---------------------------------------------------------------------------
// z_max partial + reduce
// ---------------------------------------------------------------------------
__global__ __launch_bounds__(256) void zmax_part(const float* __restrict__ p_param)
{
    int bh = blockIdx.x, chunk = blockIdx.y;
    int b = bh >> 4, h = bh & 15;
    int d4 = threadIdx.x & 15;
    int g  = threadIdx.x >> 4;
    int c  = h*64 + d4*4;
    float4 pv;
    pv.x = clamp_p(p_param[c+0]); pv.y = clamp_p(p_param[c+1]);
    pv.z = clamp_p(p_param[c+2]); pv.w = clamp_p(p_param[c+3]);

    const float* vp = g_V + (size_t)bh * Tn * 64;
    float4 mx = make_float4(-1e30f, -1e30f, -1e30f, -1e30f);
    for (int t = chunk*128 + g; t < (chunk+1)*128; t += 16) {
        float4 v = *(const float4*)(vp + t*64 + d4*4);
        mx.x = fmaxf(mx.x, pv.x * logf(fmaxf(fabsf(v.x + 5.0f), 1e-10f)));
        mx.y = fmaxf(mx.y, pv.y * logf(fmaxf(fabsf(v.y + 5.0f), 1e-10f)));
        mx.z = fmaxf(mx.z, pv.z * logf(fmaxf(fabsf(v.z + 5.0f), 1e-10f)));
        mx.w = fmaxf(mx.w, pv.w * logf(fmaxf(fabsf(v.w + 5.0f), 1e-10f)));
    }
    __shared__ float4 red[256];
    red[threadIdx.x] = mx;
    __syncthreads();
    if (threadIdx.x < 16) {
        float4 m = red[threadIdx.x];
#pragma unroll
        for (int gg = 1; gg < 16; gg++) {
            float4 o = red[gg*16 + threadIdx.x];
            m.x = fmaxf(m.x, o.x); m.y = fmaxf(m.y, o.y);
            m.z = fmaxf(m.z, o.z); m.w = fmaxf(m.w, o.w);
        }
        *(float4*)(g_zpart + chunk*(Bn*Cn) + b*Cn + h*64 + threadIdx.x*4) = m;
    }
}
__global__ __launch_bounds__(256) void zmax_reduce()
{
    int i = blockIdx.x * 256 + threadIdx.x;
    float mx = -1e30f;
#pragma unroll
    for (int ch = 0; ch < 16; ch++) mx = fmaxf(mx, g_zpart[ch*(Bn*Cn) + i]);
    g_zmax[i] = mx;
}

// ---------------------------------------------------------------------------
// V transform -> bf16 hi/lo (float4 per thread)
// ---------------------------------------------------------------------------
__global__ __launch_bounds__(256) void vexp_kernel(const float* __restrict__ p_param)
{
    int i = blockIdx.x * 256 + threadIdx.x;
    int base = i * 4;
    int dd = base & 63;
    int bh = base >> 17;
    int h = bh & 15, b = bh >> 4;
    int c = h*64 + dd;
    float4 v = *(const float4*)(g_V + base);
    float e[4];
    const float vs[4] = {v.x, v.y, v.z, v.w};
#pragma unroll
    for (int j = 0; j < 4; j++) {
        float pvj = clamp_p(p_param[c + j]);
        float z = pvj * logf(fmaxf(fabsf(vs[j] + 5.0f), 1e-10f)) - g_zmax[b*Cn + c + j];
        e[j] = expf(z);
    }
    uint32_t h0 = pkbf(e[0], e[1]), h1 = pkbf(e[2], e[3]);
    float f0 = __uint_as_float(h0 << 16), f1 = __uint_as_float(h0 & 0xffff0000u);
    float f2 = __uint_as_float(h1 << 16), f3 = __uint_as_float(h1 & 0xffff0000u);
    uint32_t l0 = pkbf(e[0]-f0, e[1]-f1), l1 = pkbf(e[2]-f2, e[3]-f3);
    ((uint2*)g_Vh)[i] = make_uint2(h0, h1);
    ((uint2*)g_Vl)[i] = make_uint2(l0, l1);
}

// ---------------------------------------------------------------------------
// Tensor-core flash attention (causal), BQ=BK=64, 4 warps (128 threads),
// 80 KB smem -> 2 CTAs/SM for softmax/HMMA overlap. bf16x3; P from S frags.
// Epilogue writes Y as fp16 hi/lo into gA_hi/gA_lo.
// ---------------------------------------------------------------------------
#define FAQ_H 0
#define FAQ_L 8192
#define FASTG0 16384
#define FASTG_SZ 32768
#define FKH 0
#define FKL 8192
#define FVH 16384
#define FVL 24576
#define FA_SMEM (16384 + 2*FASTG_SZ)   // 80 KB

__device__ __forceinline__ void fa_load_stage(uint32_t sbase, int bh, int kt, int tid)
{
    const __nv_bfloat16* srcs[4] = {g_Kh, g_Kl, g_Vh, g_Vl};
#pragma unroll
    for (int j = 0; j < 16; j++) {
        int idx = tid + j * 128;          // 0..2047 16B-chunks
        int arr = idx >> 9;
        int rem = idx & 511;
        int row = rem >> 3, c = rem & 7;
        uint32_t sw = arr * 8192 + row * 128 + ((c ^ (row & 7)) << 4);
        size_t g = ((size_t)bh * Tn + kt * 64 + row) * 64 + c * 8;
        cp16(sbase + sw, srcs[arr] + g);
    }
}

__global__ __launch_bounds__(128) void fa_kernel(const float* __restrict__ p_param)
{
    extern __shared__ char smem[];
    uint32_t sb = smem_u32(smem);
    const int tid  = threadIdx.x;
    const int w    = tid >> 5;            // 0..3
    const int lane = tid & 31;
    const int quad = lane >> 2;
    const int idq  = lane & 3;
    const int bh = blockIdx.y;
    const int b = bh >> 4, h = bh & 15;
    const int qt = (int)gridDim.x - 1 - (int)blockIdx.x;   // heavy first
    const int q0 = qt * 64;

    // ---- prologue: Q tile (64x64 hi/lo) + first stages ----
    {
        const __nv_bfloat16* qs[2] = {g_Qh, g_Ql};
#pragma unroll
        for (int j = 0; j < 8; j++) {
            int idx = tid + j * 128;      // 0..1023
            int arr = idx >> 9;
            int rem = idx & 511;
            int row = rem >> 3, c = rem & 7;
            uint32_t sw = arr * 8192 + row * 128 + ((c ^ (row & 7)) << 4);
            size_t g = ((size_t)bh * Tn + q0 + row) * 64 + c * 8;
            cp16(sb + sw, qs[arr] + g);
        }
        fa_load_stage(sb + FASTG0, bh, 0, tid);
        CP_COMMIT();
        if (qt >= 1) fa_load_stage(sb + FASTG0 + FASTG_SZ, bh, 1, tid);
        CP_COMMIT();
    }

    uint32_t Qh[4][4], Ql[4][4];
    float Of[8][4];
    float m0 = -1e30f, m1 = -1e30f, l0 = 0.0f, l1 = 0.0f;
#pragma unroll
    for (int nf = 0; nf < 8; nf++)
#pragma unroll
        for (int q = 0; q < 4; q++) Of[nf][q] = 0.0f;

    const int k_row = ((lane >> 4) << 3) + (lane & 7);   // + nf2*16
    const int k_cof = ((lane >> 3) & 1);                 // + ks*2
    const int v_row = (lane & 15);                       // + kf*16
    const int v_cof = (lane >> 4);                       // + nf2*2

    for (int kt = 0; kt <= qt; kt++) {
        const uint32_t sbase = sb + FASTG0 + (kt & 1) * FASTG_SZ;
        if (kt < qt) asm volatile("cp.async.wait_group 1;\n" ::: "memory");
        else         asm volatile("cp.async.wait_group 0;\n" ::: "memory");
        __syncthreads();

        if (kt == 0) {
            int row = w * 16 + (lane & 15);
#pragma unroll
            for (int ks = 0; ks < 4; ks++) {
                int c16 = ks * 2 + (lane >> 4);
                uint32_t sw = row * 128 + ((c16 ^ (row & 7)) << 4);
                ldsm4(Qh[ks][0], Qh[ks][1], Qh[ks][2], Qh[ks][3], sb + FAQ_H + sw);
                ldsm4(Ql[ks][0], Ql[ks][1], Ql[ks][2], Ql[ks][3], sb + FAQ_L + sw);
            }
        }

        // ---- S = Q K^T (16 x 64 strip per warp), bf16x3 ----
        float Sf[8][4];
#pragma unroll
        for (int nf = 0; nf < 8; nf++)
#pragma unroll
            for (int q = 0; q < 4; q++) Sf[nf][q] = 0.0f;

#pragma unroll
        for (int nf2 = 0; nf2 < 4; nf2++) {
            int krow = nf2 * 16 + k_row;
#pragma unroll
            for (int ks = 0; ks < 4; ks++) {
                int c16 = ks * 2 + k_cof;
                uint32_t sw = krow * 128 + ((c16 ^ (krow & 7)) << 4);
                uint32_t kh[4], kl[4];
                ldsm4(kh[0], kh[1], kh[2], kh[3], sbase + FKH + sw);
                ldsm4(kl[0], kl[1], kl[2], kl[3], sbase + FKL + sw);
                mma16816(Sf[2*nf2],   Qh[ks], kh);
                mma16816(Sf[2*nf2],   Ql[ks], kh);
                mma16816(Sf[2*nf2],   Qh[ks], kl);
                mma16816(Sf[2*nf2+1], Qh[ks], kh + 2);
                mma16816(Sf[2*nf2+1], Ql[ks], kh + 2);
                mma16816(Sf[2*nf2+1], Qh[ks], kl + 2);
            }
        }

        // ---- causal mask on diagonal tile ----
        if (kt == qt) {
            int r0 = w * 16 + quad, r1 = r0 + 8;
#pragma unroll
            for (int nf = 0; nf < 8; nf++) {
                int c0 = nf * 8 + idq * 2;
                if (c0     > r0) Sf[nf][0] = -1e30f;
                if (c0 + 1 > r0) Sf[nf][1] = -1e30f;
                if (c0     > r1) Sf[nf][2] = -1e30f;
                if (c0 + 1 > r1) Sf[nf][3] = -1e30f;
            }
        }

        // ---- softmax (register, 2 rows/thread, quad shuffles) ----
        float mx0 = -1e30f, mx1 = -1e30f;
#pragma unroll
        for (int nf = 0; nf < 8; nf++) {
            mx0 = fmaxf(mx0, fmaxf(Sf[nf][0], Sf[nf][1]));
            mx1 = fmaxf(mx1, fmaxf(Sf[nf][2], Sf[nf][3]));
        }
#pragma unroll
        for (int off = 1; off < 4; off <<= 1) {
            mx0 = fmaxf(mx0, __shfl_xor_sync(0xffffffffu, mx0, off));
            mx1 = fmaxf(mx1, __shfl_xor_sync(0xffffffffu, mx1, off));
        }
        mx0 = fmaxf(mx0, m0);
        mx1 = fmaxf(mx1, m1);
        float a0 = __expf(m0 - mx0), a1 = __expf(m1 - mx1);
        m0 = mx0; m1 = mx1;

        float s0 = 0.0f, s1 = 0.0f;
#pragma unroll
        for (int nf = 0; nf < 8; nf++) {
            Sf[nf][0] = __expf(Sf[nf][0] - mx0);
            Sf[nf][1] = __expf(Sf[nf][1] - mx0);
            Sf[nf][2] = __expf(Sf[nf][2] - mx1);
            Sf[nf][3] = __expf(Sf[nf][3] - mx1);
            s0 += Sf[nf][0] + Sf[nf][1];
            s1 += Sf[nf][2] + Sf[nf][3];
        }
#pragma unroll
        for (int off = 1; off < 4; off <<= 1) {
            s0 += __shfl_xor_sync(0xffffffffu, s0, off);
            s1 += __shfl_xor_sync(0xffffffffu, s1, off);
        }
        l0 = l0 * a0 + s0;
        l1 = l1 * a1 + s1;

#pragma unroll
        for (int nf = 0; nf < 8; nf++) {
            Of[nf][0] *= a0; Of[nf][1] *= a0;
            Of[nf][2] *= a1; Of[nf][3] *= a1;
        }

        // ---- O += P V (P from S frags, bf16x3, ldsm4t V) ----
#pragma unroll
        for (int kf = 0; kf < 4; kf++) {
            uint32_t pha[4], pla[4];
#pragma unroll
            for (int half = 0; half < 2; half++) {
                float* sp = Sf[2*kf + half];
                uint32_t u0 = pkbf(sp[0], sp[1]);
                uint32_t u1 = pkbf(sp[2], sp[3]);
                float f00 = __uint_as_float(u0 << 16), f01 = __uint_as_float(u0 & 0xffff0000u);
                float f10 = __uint_as_float(u1 << 16), f11 = __uint_as_float(u1 & 0xffff0000u);
                pha[half*2+0] = u0;
                pha[half*2+1] = u1;
                pla[half*2+0] = pkbf(sp[0] - f00, sp[1] - f01);
                pla[half*2+1] = pkbf(sp[2] - f10, sp[3] - f11);
            }
            int vrow = kf * 16 + v_row;
#pragma unroll
            for (int nf2 = 0; nf2 < 4; nf2++) {
                int c16 = nf2 * 2 + v_cof;
                uint32_t sw = vrow * 128 + ((c16 ^ (vrow & 7)) << 4);
                uint32_t vh[4], vl[4];
                ldsm4t(vh[0], vh[1], vh[2], vh[3], sbase + FVH + sw);
                ldsm4t(vl[0], vl[1], vl[2], vl[3], sbase + FVL + sw);
                mma16816(Of[2*nf2],   pha, vh);
                mma16816(Of[2*nf2],   pla, vh);
                mma16816(Of[2*nf2],   pha, vl);
                mma16816(Of[2*nf2+1], pha, vh + 2);
                mma16816(Of[2*nf2+1], pla, vh + 2);
                mma16816(Of[2*nf2+1], pha, vl + 2);
            }
        }

        __syncthreads();
        if (kt + 2 <= qt) {
            fa_load_stage(sbase, bh, kt + 2, tid);
            CP_COMMIT();
        }
    }

    // ---- epilogue: y = exp((zmax + log(O/l))/p) - 5, write fp16 hi/lo ----
    const int t0 = q0 + w * 16 + quad;
    const int t1 = t0 + 8;
    float linv0 = 1.0f / l0, linv1 = 1.0f / l1;
#pragma unroll
    for (int nf = 0; nf < 8; nf++) {
        int d0 = nf * 8 + idq * 2;
        int cg = h * 64 + d0;
        float pv0 = clamp_p(p_param[cg]);
        float pv1 = clamp_p(p_param[cg + 1]);
        float zm0 = g_zmax[b*Cn + cg];
        float zm1 = g_zmax[b*Cn + cg + 1];
        float y00 = expf((zm0 + logf(Of[nf][0] * linv0)) / pv0) - 5.0f;
        float y01 = expf((zm1 + logf(Of[nf][1] * linv0)) / pv1) - 5.0f;
        float y10 = expf((zm0 + logf(Of[nf][2] * linv1)) / pv0) - 5.0f;
        float y11 = expf((zm1 + logf(Of[nf][3] * linv1)) / pv1) - 5.0f;
        uint32_t h0 = pkhf(y00, y01);
        float2 u0 = unpkhf(h0);
        uint32_t l0p = pkhf(y00 - u0.x, y01 - u0.y);
        uint32_t h1 = pkhf(y10, y11);
        float2 u1 = unpkhf(h1);
        uint32_t l1p = pkhf(y10 - u1.x, y11 - u1.y);
        size_t i0 = ((size_t)(b*Tn + t0)*Cn + cg) >> 1;
        size_t i1 = ((size_t)(b*Tn + t1)*Cn + cg) >> 1;
        ((uint32_t*)gA_hi)[i0] = h0;
        ((uint32_t*)gA_lo)[i0] = l0p;
        ((uint32_t*)gA_hi)[i1] = h1;
        ((uint32_t*)gA_lo)[i1] = l1p;
    }
}

// ---------------------------------------------------------------------------

extern "C" void kernel_launch(void* const* d_in, const int* in_sizes, int n_in,
                              void* d_out, int out_size)
{
    const float* x       = (const float*)d_in[0];
    const float* w_attn  = (const float*)d_in[1];
    const float* b_attn  = (const float*)d_in[2];
    const float* w_proj  = (const float*)d_in[3];
    const float* b_proj  = (const float*)d_in[4];
    const float* p_param = (const float*)d_in[5];
    float* out = (float*)d_out;

    void *ah, *al, *bth;
    cudaGetSymbolAddress(&ah,  gA_hi);
    cudaGetSymbolAddress(&al,  gA_lo);
    cudaGetSymbolAddress(&bth, gBT_hi);

    cudaFuncSetAttribute(fa_kernel, cudaFuncAttributeMaxDynamicSharedMemorySize, FA_SMEM);
    cudaFuncSetAttribute(tc_gemm<0>, cudaFuncAttributeMaxDynamicSharedMemorySize, TCG_SMEM);
    cudaFuncSetAttribute(tc_gemm<1>, cudaFuncAttributeMaxDynamicSharedMemorySize, TCG_SMEM);

    // 1) split x (fp16 hi/lo); transpose w_attn (fp16 hi)
    split_fp16<<<Mn*Cn/1024, 256>>>(x, (__half*)ah, (__half*)al);
    transpose_h<<<dim3(3072/32, Cn/32), dim3(32,8)>>>(w_attn, (__half*)bth, 3072);

    // 2) QKV GEMM (fp16x2) + bf16 hi/lo head-major scatter (Q pre-scaled)
    tc_gemm<1><<<dim3(3072/128, Mn/256), 256, TCG_SMEM>>>(
        (const __half*)ah, (const __half*)al, (const __half*)bth, b_attn, nullptr);

    // 3) z_max (partial + reduce) + V transform -> bf16 hi/lo
    zmax_part<<<dim3(BHn, 16), 256>>>(p_param);
    zmax_reduce<<<(Bn*Cn)/256, 256>>>();
    vexp_kernel<<<(BHn*Tn*Dn)/1024, 256>>>(p_param);

    // 4) tensor-core causal FA (BQ=BK=64, 2 CTAs/SM); Y -> gA fp16 hi/lo
    fa_kernel<<<dim3(Tn/64, BHn), 128, FA_SMEM>>>(p_param);

    // 5) transpose w_proj (fp16 hi); proj GEMM (fp16x2)
    transpose_h<<<dim3(Cn/32, Cn/32), dim3(32,8)>>>(w_proj, (__half*)bth, Cn);
    tc_gemm<0><<<dim3(Cn/128, Mn/256), 256, TCG_SMEM>>>(
        (const __half*)ah, (const __half*)al, (const __half*)bth, b_proj, out);
}

// round 9
// speedup vs baseline: 4.8645x; 1.1325x over previous
#include <cuda_runtime.h>
#include <cuda_bf16.h>
#include <cuda_fp16.h>
#include <math.h>
#include <stdint.h>

#define Bn 2
#define Tn 2048
#define Cn 1024
#define Hn 16
#define Dn 64
#define Mn (Bn*Tn)          // 4096
#define BHn (Bn*Hn)         // 32

typedef unsigned long long ull;

// ---------------- device scratch ----------------
__device__ __half         g_Qh[BHn*Tn*Dn];  // head-major, pre-scaled by 0.125 (fp16 hi)
__device__ __half         g_Ql[BHn*Tn*Dn];  // fp16 lo
__device__ __half         g_Kh[BHn*Tn*Dn];  // fp16 hi only
__device__ float          g_V [BHn*Tn*Dn];  // raw v (fp32) for zmax
__device__ __nv_bfloat16  g_Vh[BHn*Tn*Dn];  // exp(z-zmax) bf16 hi/lo
__device__ __nv_bfloat16  g_Vl[BHn*Tn*Dn];
__device__ float g_zmax[Bn*Cn];
__device__ float g_zpart[16*Bn*Cn];
__device__ __half gA_hi[Mn*Cn];             // fp16 A operand (x split, then Y from FA)
__device__ __half gA_lo[Mn*Cn];
__device__ __half gBT_hi[3*Cn*Cn];          // fp16 weights^T (hi only)

__device__ __forceinline__ float clamp_p(float pp) {
    float sgn = (pp >= 0.0f) ? 1.0f : -1.0f;
    return sgn * fminf(fmaxf(fabsf(pp), 1e-4f), 1e3f);
}

// ---------------- ptx helpers ----------------
__device__ __forceinline__ uint32_t smem_u32(const void* p) {
    uint32_t a;
    asm("{ .reg .u64 t; cvta.to.shared.u64 t, %1; cvt.u32.u64 %0, t; }" : "=r"(a) : "l"(p));
    return a;
}
__device__ __forceinline__ void cp16(uint32_t dst, const void* src) {
    asm volatile("cp.async.cg.shared.global [%0], [%1], 16;\n" :: "r"(dst), "l"(src));
}
#define CP_COMMIT() asm volatile("cp.async.commit_group;\n" ::: "memory")

__device__ __forceinline__ void ldsm4(uint32_t& r0, uint32_t& r1, uint32_t& r2, uint32_t& r3,
                                      uint32_t addr) {
    asm volatile("ldmatrix.sync.aligned.m8n8.x4.shared.b16 {%0,%1,%2,%3}, [%4];"
                 : "=r"(r0), "=r"(r1), "=r"(r2), "=r"(r3) : "r"(addr));
}
__device__ __forceinline__ void ldsm4t(uint32_t& r0, uint32_t& r1, uint32_t& r2, uint32_t& r3,
                                       uint32_t addr) {
    asm volatile("ldmatrix.sync.aligned.m8n8.x4.trans.shared.b16 {%0,%1,%2,%3}, [%4];"
                 : "=r"(r0), "=r"(r1), "=r"(r2), "=r"(r3) : "r"(addr));
}
__device__ __forceinline__ void mma16816(float* c, const uint32_t* a, const uint32_t* b) {
    asm volatile(
        "mma.sync.aligned.m16n8k16.row.col.f32.bf16.bf16.f32 "
        "{%0,%1,%2,%3}, {%4,%5,%6,%7}, {%8,%9}, {%0,%1,%2,%3};"
        : "+f"(c[0]), "+f"(c[1]), "+f"(c[2]), "+f"(c[3])
        : "r"(a[0]), "r"(a[1]), "r"(a[2]), "r"(a[3]), "r"(b[0]), "r"(b[1]));
}
__device__ __forceinline__ void mma16816h(float* c, const uint32_t* a, const uint32_t* b) {
    asm volatile(
        "mma.sync.aligned.m16n8k16.row.col.f32.f16.f16.f32 "
        "{%0,%1,%2,%3}, {%4,%5,%6,%7}, {%8,%9}, {%0,%1,%2,%3};"
        : "+f"(c[0]), "+f"(c[1]), "+f"(c[2]), "+f"(c[3])
        : "r"(a[0]), "r"(a[1]), "r"(a[2]), "r"(a[3]), "r"(b[0]), "r"(b[1]));
}
__device__ __forceinline__ uint32_t pkbf(float lo, float hi) {
    uint32_t r;
    asm("cvt.rn.bf16x2.f32 %0, %1, %2;" : "=r"(r) : "f"(hi), "f"(lo));
    return r;
}
__device__ __forceinline__ uint32_t pkhf(float lo, float hi) {
    uint32_t r;
    asm("cvt.rn.f16x2.f32 %0, %1, %2;" : "=r"(r) : "f"(hi), "f"(lo));
    return r;
}
__device__ __forceinline__ float2 unpkhf(uint32_t u) {
    __half2 h = *reinterpret_cast<__half2*>(&u);
    return __half22float2(h);
}

// ---------------------------------------------------------------------------
// split: fp32 -> fp16 hi/lo
// ---------------------------------------------------------------------------
__global__ __launch_bounds__(256) void split_fp16(
    const float* __restrict__ A, __half* __restrict__ Ah, __half* __restrict__ Al)
{
    int i = blockIdx.x * 256 + threadIdx.x;
    float4 a = ((const float4*)A)[i];
    uint32_t h0 = pkhf(a.x, a.y), h1 = pkhf(a.z, a.w);
    float2 u0 = unpkhf(h0), u1 = unpkhf(h1);
    uint32_t l0 = pkhf(a.x - u0.x, a.y - u0.y);
    uint32_t l1 = pkhf(a.z - u1.x, a.w - u1.y);
    ((uint32_t*)Ah)[2*i]   = h0;
    ((uint32_t*)Ah)[2*i+1] = h1;
    ((uint32_t*)Al)[2*i]   = l0;
    ((uint32_t*)Al)[2*i+1] = l1;
}

// ---------------------------------------------------------------------------
// transpose: W[K=1024][Nd] -> Th[Nd][1024] (fp16 hi only)
// ---------------------------------------------------------------------------
__global__ void transpose_h(const float* __restrict__ W,
                            __half* __restrict__ Th, int Nd)
{
    __shared__ float tile[32][33];
    int nx = blockIdx.x * 32, kx = blockIdx.y * 32;
    int tx = threadIdx.x, ty = threadIdx.y;
#pragma unroll
    for (int r = ty; r < 32; r += 8)
        tile[r][tx] = W[(size_t)(kx + r) * Nd + nx + tx];
    __syncthreads();
#pragma unroll
    for (int r = ty; r < 32; r += 8) {
        size_t o = (size_t)(nx + r) * 1024 + kx + tx;
        Th[o] = __float2half_rn(tile[tx][r]);
    }
}

// ---------------------------------------------------------------------------
// fp16x2 mma.sync GEMM: CTA 128x128, warp tile 64x32 (2x4 warps), BK=64,
// cp.async double buffer, 96 KB smem -> 2 CTAs/SM. D = (Ah+Al) @ Bh^T.
// ---------------------------------------------------------------------------
#define G_AHI 0
#define G_ALO 16384
#define G_BHI 32768
#define G_STG 49152
#define TCG_SMEM (2*G_STG)   // 96 KB

__device__ __forceinline__ void load_stage(
    uint32_t sbase,
    const __half* __restrict__ Ah, const __half* __restrict__ Al,
    const __half* __restrict__ Bh,
    int m0, int n0, int k0, int tid)
{
#pragma unroll
    for (int j = 0; j < 4; j++) {          // A: 128 rows x 8 chunks (hi+lo)
        int idx = tid + j * 256;
        int row = idx >> 3, c = idx & 7;
        uint32_t sw = row * 128 + ((c ^ (row & 7)) << 4);
        size_t ga = (size_t)(m0 + row) * 1024 + k0 + c * 8;
        cp16(sbase + G_AHI + sw, Ah + ga);
        cp16(sbase + G_ALO + sw, Al + ga);
    }
#pragma unroll
    for (int j = 0; j < 4; j++) {          // B: 128 rows x 8 chunks (hi only)
        int idx = tid + j * 256;
        int row = idx >> 3, c = idx & 7;
        uint32_t sw = row * 128 + ((c ^ (row & 7)) << 4);
        size_t gb = (size_t)(n0 + row) * 1024 + k0 + c * 8;
        cp16(sbase + G_BHI + sw, Bh + gb);
    }
}

template<int MODE>
__global__ __launch_bounds__(256, 2) void tc_gemm(
    const __half* __restrict__ Ah, const __half* __restrict__ Al,
    const __half* __restrict__ Bh,
    const float* __restrict__ bias, float* __restrict__ Cout)
{
    extern __shared__ char smem[];
    uint32_t sb = smem_u32(smem);
    const int tid  = threadIdx.x;
    const int wid  = tid >> 5;
    const int lane = tid & 31;
    const int wm = wid & 1;        // 2 warp-rows of 64
    const int wn = wid >> 1;       // 4 warp-cols of 32
    const int m0 = blockIdx.y * 128;
    const int n0 = blockIdx.x * 128;

    float acc[4][4][4];
#pragma unroll
    for (int i = 0; i < 4; i++)
#pragma unroll
        for (int j = 0; j < 4; j++)
#pragma unroll
            for (int q = 0; q < 4; q++) acc[i][j][q] = 0.0f;

    load_stage(sb,         Ah, Al, Bh, m0, n0, 0,  tid); CP_COMMIT();
    load_stage(sb + G_STG, Ah, Al, Bh, m0, n0, 64, tid); CP_COMMIT();

    const int a_row = wm * 64 + (lane & 15);
    const int a_c16 = (lane >> 4);
    const int b_row = wn * 32 + ((lane >> 4) << 3) + (lane & 7);
    const int b_cof = ((lane >> 3) & 1);

    for (int it = 0; it < 16; it++) {
        const int s = it & 1;
        const uint32_t sbase = sb + s * G_STG;
        if (it < 15) asm volatile("cp.async.wait_group 1;\n" ::: "memory");
        else         asm volatile("cp.async.wait_group 0;\n" ::: "memory");
        __syncthreads();

#pragma unroll
        for (int ks = 0; ks < 4; ks++) {
            uint32_t ahi[4][4], alo[4][4];
#pragma unroll
            for (int mf = 0; mf < 4; mf++) {
                int row = a_row + mf * 16;
                int c16 = ks * 2 + a_c16;
                uint32_t ad = sbase + row * 128 + ((c16 ^ (row & 7)) << 4);
                ldsm4(ahi[mf][0], ahi[mf][1], ahi[mf][2], ahi[mf][3], ad + G_AHI);
                ldsm4(alo[mf][0], alo[mf][1], alo[mf][2], alo[mf][3], ad + G_ALO);
            }
#pragma unroll
            for (int nf2 = 0; nf2 < 2; nf2++) {
                int row = b_row + nf2 * 16;
                int c16 = ks * 2 + b_cof;
                uint32_t bd = sbase + row * 128 + ((c16 ^ (row & 7)) << 4);
                uint32_t bh4[4];
                ldsm4(bh4[0], bh4[1], bh4[2], bh4[3], bd + G_BHI);
#pragma unroll
                for (int mf = 0; mf < 4; mf++) {
                    mma16816h(acc[mf][2*nf2],   ahi[mf], bh4);
                    mma16816h(acc[mf][2*nf2],   alo[mf], bh4);
                    mma16816h(acc[mf][2*nf2+1], ahi[mf], bh4 + 2);
                    mma16816h(acc[mf][2*nf2+1], alo[mf], bh4 + 2);
                }
            }
        }
        __syncthreads();
        if (it + 2 < 16) {
            load_stage(sbase, Ah, Al, Bh, m0, n0, (it + 2) * 64, tid);
            CP_COMMIT();
        }
    }

    const int mbase = m0 + wm * 64 + (lane >> 2);
    const int nbase = n0 + wn * 32 + (lane & 3) * 2;
#pragma unroll
    for (int mf = 0; mf < 4; mf++) {
#pragma unroll
        for (int half = 0; half < 2; half++) {
            int m = mbase + mf * 16 + half * 8;
#pragma unroll
            for (int nf = 0; nf < 4; nf++) {
                int n = nbase + nf * 8;
                float v0 = acc[mf][nf][half*2+0] + bias[n];
                float v1 = acc[mf][nf][half*2+1] + bias[n+1];
                if (MODE == 0) {
                    *(float2*)(Cout + (size_t)m * Cn + n) = make_float2(v0, v1);
                } else {
                    int sec = n >> 10;
                    int c1  = n & 1023;
                    int h   = c1 >> 6, dd = c1 & 63;
                    int bq  = m >> 11, t = m & 2047;
                    size_t idx = ((size_t)((bq * Hn + h) * Tn + t)) * 64 + dd;
                    if (sec == 2) {
                        *(float2*)(g_V + idx) = make_float2(v0, v1);
                    } else if (sec == 1) {
                        *(uint32_t*)(g_Kh + idx) = pkhf(v0, v1);
                    } else {
                        v0 *= 0.125f; v1 *= 0.125f;
                        uint32_t hh = pkhf(v0, v1);
                        float2 u = unpkhf(hh);
                        uint32_t ll = pkhf(v0 - u.x, v1 - u.y);
                        *(uint32_t*)(g_Qh + idx) = hh;
                        *(uint32_t*)(g_Ql + idx) = ll;
                    }
                }
            }
        }
    }
}

// ---------------------------------------------------------------------------
// z_max partial + reduce
// ---------------------------------------------------------------------------
__global__ __launch_bounds__(256) void zmax_part(const float* __restrict__ p_param)
{
    int bh = blockIdx.x, chunk = blockIdx.y;
    int b = bh >> 4, h = bh & 15;
    int d4 = threadIdx.x & 15;
    int g  = threadIdx.x >> 4;
    int c  = h*64 + d4*4;
    float4 pv;
    pv.x = clamp_p(p_param[c+0]); pv.y = clamp_p(p_param[c+1]);
    pv.z = clamp_p(p_param[c+2]); pv.w = clamp_p(p_param[c+3]);

    const float* vp = g_V + (size_t)bh * Tn * 64;
    float4 mx = make_float4(-1e30f, -1e30f, -1e30f, -1e30f);
    for (int t = chunk*128 + g; t < (chunk+1)*128; t += 16) {
        float4 v = *(const float4*)(vp + t*64 + d4*4);
        mx.x = fmaxf(mx.x, pv.x * logf(fmaxf(fabsf(v.x + 5.0f), 1e-10f)));
        mx.y = fmaxf(mx.y, pv.y * logf(fmaxf(fabsf(v.y + 5.0f), 1e-10f)));
        mx.z = fmaxf(mx.z, pv.z * logf(fmaxf(fabsf(v.z + 5.0f), 1e-10f)));
        mx.w = fmaxf(mx.w, pv.w * logf(fmaxf(fabsf(v.w + 5.0f), 1e-10f)));
    }
    __shared__ float4 red[256];
    red[threadIdx.x] = mx;
    __syncthreads();
    if (threadIdx.x < 16) {
        float4 m = red[threadIdx.x];
#pragma unroll
        for (int gg = 1; gg < 16; gg++) {
            float4 o = red[gg*16 + threadIdx.x];
            m.x = fmaxf(m.x, o.x); m.y = fmaxf(m.y, o.y);
            m.z = fmaxf(m.z, o.z); m.w = fmaxf(m.w, o.w);
        }
        *(float4*)(g_zpart + chunk*(Bn*Cn) + b*Cn + h*64 + threadIdx.x*4) = m;
    }
}
__global__ __launch_bounds__(256) void zmax_reduce()
{
    int i = blockIdx.x * 256 + threadIdx.x;
    float mx = -1e30f;
#pragma unroll
    for (int ch = 0; ch < 16; ch++) mx = fmaxf(mx, g_zpart[ch*(Bn*Cn) + i]);
    g_zmax[i] = mx;
}

// ---------------------------------------------------------------------------
// V transform -> bf16 hi/lo (float4 per thread)
// ---------------------------------------------------------------------------
__global__ __launch_bounds__(256) void vexp_kernel(const float* __restrict__ p_param)
{
    int i = blockIdx.x * 256 + threadIdx.x;
    int base = i * 4;
    int dd = base & 63;
    int bh = base >> 17;
    int h = bh & 15, b = bh >> 4;
    int c = h*64 + dd;
    float4 v = *(const float4*)(g_V + base);
    float e[4];
    const float vs[4] = {v.x, v.y, v.z, v.w};
#pragma unroll
    for (int j = 0; j < 4; j++) {
        float pvj = clamp_p(p_param[c + j]);
        float z = pvj * logf(fmaxf(fabsf(vs[j] + 5.0f), 1e-10f)) - g_zmax[b*Cn + c + j];
        e[j] = expf(z);
    }
    uint32_t h0 = pkbf(e[0], e[1]), h1 = pkbf(e[2], e[3]);
    float f0 = __uint_as_float(h0 << 16), f1 = __uint_as_float(h0 & 0xffff0000u);
    float f2 = __uint_as_float(h1 << 16), f3 = __uint_as_float(h1 & 0xffff0000u);
    uint32_t l0 = pkbf(e[0]-f0, e[1]-f1), l1 = pkbf(e[2]-f2, e[3]-f3);
    ((uint2*)g_Vh)[i] = make_uint2(h0, h1);
    ((uint2*)g_Vl)[i] = make_uint2(l0, l1);
}

// ---------------------------------------------------------------------------
// Tensor-core flash attention (causal), BQ=BK=64, 4 warps, 64 KB smem
// -> 2+ CTAs/SM. S = fp16 2-term (Qh+Ql)·Kh; P·V bf16 3-term.
// Epilogue writes Y as fp16 hi/lo into gA_hi/gA_lo.
// ---------------------------------------------------------------------------
#define FAQ_H 0
#define FAQ_L 8192
#define FASTG0 16384
#define FASTG_SZ 24576
#define FKH 0
#define FVH 8192
#define FVL 16384
#define FA_SMEM (16384 + 2*FASTG_SZ)   // 64 KB

__device__ __forceinline__ void fa_load_stage(uint32_t sbase, int bh, int kt, int tid)
{
    const char* srcs[3] = {(const char*)g_Kh, (const char*)g_Vh, (const char*)g_Vl};
#pragma unroll
    for (int j = 0; j < 12; j++) {
        int idx = tid + j * 128;          // 0..1535 16B-chunks
        int arr = idx >> 9;               // 0..2
        int rem = idx & 511;
        int row = rem >> 3, c = rem & 7;
        uint32_t sw = arr * 8192 + row * 128 + ((c ^ (row & 7)) << 4);
        size_t gb = (((size_t)bh * Tn + kt * 64 + row) * 64 + c * 8) * 2;
        cp16(sbase + sw, srcs[arr] + gb);
    }
}

__global__ __launch_bounds__(128) void fa_kernel(const float* __restrict__ p_param)
{
    extern __shared__ char smem[];
    uint32_t sb = smem_u32(smem);
    const int tid  = threadIdx.x;
    const int w    = tid >> 5;
    const int lane = tid & 31;
    const int quad = lane >> 2;
    const int idq  = lane & 3;
    const int bh = blockIdx.y;
    const int b = bh >> 4, h = bh & 15;
    const int qt = (int)gridDim.x - 1 - (int)blockIdx.x;   // heavy first
    const int q0 = qt * 64;

    // ---- prologue: Q tile (fp16 hi/lo) + first stages ----
    {
        const char* qs[2] = {(const char*)g_Qh, (const char*)g_Ql};
#pragma unroll
        for (int j = 0; j < 8; j++) {
            int idx = tid + j * 128;
            int arr = idx >> 9;
            int rem = idx & 511;
            int row = rem >> 3, c = rem & 7;
            uint32_t sw = arr * 8192 + row * 128 + ((c ^ (row & 7)) << 4);
            size_t gb = (((size_t)bh * Tn + q0 + row) * 64 + c * 8) * 2;
            cp16(sb + sw, qs[arr] + gb);
        }
        fa_load_stage(sb + FASTG0, bh, 0, tid);
        CP_COMMIT();
        if (qt >= 1) fa_load_stage(sb + FASTG0 + FASTG_SZ, bh, 1, tid);
        CP_COMMIT();
    }

    uint32_t Qh[4][4], Ql[4][4];
    float Of[8][4];
    float m0 = -1e30f, m1 = -1e30f, l0 = 0.0f, l1 = 0.0f;
#pragma unroll
    for (int nf = 0; nf < 8; nf++)
#pragma unroll
        for (int q = 0; q < 4; q++) Of[nf][q] = 0.0f;

    const int k_row = ((lane >> 4) << 3) + (lane & 7);   // + nf2*16
    const int k_cof = ((lane >> 3) & 1);                 // + ks*2
    const int v_row = (lane & 15);                       // + kf*16
    const int v_cof = (lane >> 4);                       // + nf2*2

    for (int kt = 0; kt <= qt; kt++) {
        const uint32_t sbase = sb + FASTG0 + (kt & 1) * FASTG_SZ;
        if (kt < qt) asm volatile("cp.async.wait_group 1;\n" ::: "memory");
        else         asm volatile("cp.async.wait_group 0;\n" ::: "memory");
        __syncthreads();

        if (kt == 0) {
            int row = w * 16 + (lane & 15);
#pragma unroll
            for (int ks = 0; ks < 4; ks++) {
                int c16 = ks * 2 + (lane >> 4);
                uint32_t sw = row * 128 + ((c16 ^ (row & 7)) << 4);
                ldsm4(Qh[ks][0], Qh[ks][1], Qh[ks][2], Qh[ks][3], sb + FAQ_H + sw);
                ldsm4(Ql[ks][0], Ql[ks][1], Ql[ks][2], Ql[ks][3], sb + FAQ_L + sw);
            }
        }

        // ---- S = (Qh+Ql) Kh^T  (fp16, 2 terms) ----
        float Sf[8][4];
#pragma unroll
        for (int nf = 0; nf < 8; nf++)
#pragma unroll
            for (int q = 0; q < 4; q++) Sf[nf][q] = 0.0f;

#pragma unroll
        for (int nf2 = 0; nf2 < 4; nf2++) {
            int krow = nf2 * 16 + k_row;
#pragma unroll
            for (int ks = 0; ks < 4; ks++) {
                int c16 = ks * 2 + k_cof;
                uint32_t sw = krow * 128 + ((c16 ^ (krow & 7)) << 4);
                uint32_t kh[4];
                ldsm4(kh[0], kh[1], kh[2], kh[3], sbase + FKH + sw);
                mma16816h(Sf[2*nf2],   Qh[ks], kh);
                mma16816h(Sf[2*nf2],   Ql[ks], kh);
                mma16816h(Sf[2*nf2+1], Qh[ks], kh + 2);
                mma16816h(Sf[2*nf2+1], Ql[ks], kh + 2);
            }
        }

        // ---- causal mask on diagonal tile ----
        if (kt == qt) {
            int r0 = w * 16 + quad, r1 = r0 + 8;
#pragma unroll
            for (int nf = 0; nf < 8; nf++) {
                int c0 = nf * 8 + idq * 2;
                if (c0     > r0) Sf[nf][0] = -1e30f;
                if (c0 + 1 > r0) Sf[nf][1] = -1e30f;
                if (c0     > r1) Sf[nf][2] = -1e30f;
                if (c0 + 1 > r1) Sf[nf][3] = -1e30f;
            }
        }

        // ---- softmax (register, 2 rows/thread, quad shuffles) ----
        float mx0 = -1e30f, mx1 = -1e30f;
#pragma unroll
        for (int nf = 0; nf < 8; nf++) {
            mx0 = fmaxf(mx0, fmaxf(Sf[nf][0], Sf[nf][1]));
            mx1 = fmaxf(mx1, fmaxf(Sf[nf][2], Sf[nf][3]));
        }
#pragma unroll
        for (int off = 1; off < 4; off <<= 1) {
            mx0 = fmaxf(mx0, __shfl_xor_sync(0xffffffffu, mx0, off));
            mx1 = fmaxf(mx1, __shfl_xor_sync(0xffffffffu, mx1, off));
        }
        mx0 = fmaxf(mx0, m0);
        mx1 = fmaxf(mx1, m1);
        float a0 = __expf(m0 - mx0), a1 = __expf(m1 - mx1);
        m0 = mx0; m1 = mx1;

        float s0 = 0.0f, s1 = 0.0f;
#pragma unroll
        for (int nf = 0; nf < 8; nf++) {
            Sf[nf][0] = __expf(Sf[nf][0] - mx0);
            Sf[nf][1] = __expf(Sf[nf][1] - mx0);
            Sf[nf][2] = __expf(Sf[nf][2] - mx1);
            Sf[nf][3] = __expf(Sf[nf][3] - mx1);
            s0 += Sf[nf][0] + Sf[nf][1];
            s1 += Sf[nf][2] + Sf[nf][3];
        }
#pragma unroll
        for (int off = 1; off < 4; off <<= 1) {
            s0 += __shfl_xor_sync(0xffffffffu, s0, off);
            s1 += __shfl_xor_sync(0xffffffffu, s1, off);
        }
        l0 = l0 * a0 + s0;
        l1 = l1 * a1 + s1;

#pragma unroll
        for (int nf = 0; nf < 8; nf++) {
            Of[nf][0] *= a0; Of[nf][1] *= a0;
            Of[nf][2] *= a1; Of[nf][3] *= a1;
        }

        // ---- O += P V (P from S frags, bf16x3, ldsm4t V) ----
#pragma unroll
        for (int kf = 0; kf < 4; kf++) {
            uint32_t pha[4], pla[4];
#pragma unroll
            for (int half = 0; half < 2; half++) {
                float* sp = Sf[2*kf + half];
                uint32_t u0 = pkbf(sp[0], sp[1]);
                uint32_t u1 = pkbf(sp[2], sp[3]);
                float f00 = __uint_as_float(u0 << 16), f01 = __uint_as_float(u0 & 0xffff0000u);
                float f10 = __uint_as_float(u1 << 16), f11 = __uint_as_float(u1 & 0xffff0000u);
                pha[half*2+0] = u0;
                pha[half*2+1] = u1;
                pla[half*2+0] = pkbf(sp[0] - f00, sp[1] - f01);
                pla[half*2+1] = pkbf(sp[2] - f10, sp[3] - f11);
            }
            int vrow = kf * 16 + v_row;
#pragma unroll
            for (int nf2 = 0; nf2 < 4; nf2++) {
                int c16 = nf2 * 2 + v_cof;
                uint32_t sw = vrow * 128 + ((c16 ^ (vrow & 7)) << 4);
                uint32_t vh[4], vl[4];
                ldsm4t(vh[0], vh[1], vh[2], vh[3], sbase + FVH + sw);
                ldsm4t(vl[0], vl[1], vl[2], vl[3], sbase + FVL + sw);
                mma16816(Of[2*nf2],   pha, vh);
                mma16816(Of[2*nf2],   pla, vh);
                mma16816(Of[2*nf2],   pha, vl);
                mma16816(Of[2*nf2+1], pha, vh + 2);
                mma16816(Of[2*nf2+1], pla, vh + 2);
                mma16816(Of[2*nf2+1], pha, vl + 2);
            }
        }

        __syncthreads();
        if (kt + 2 <= qt) {
            fa_load_stage(sbase, bh, kt + 2, tid);
            CP_COMMIT();
        }
    }

    // ---- epilogue: y = exp((zmax + log(O/l))/p) - 5, write fp16 hi/lo ----
    const int t0 = q0 + w * 16 + quad;
    const int t1 = t0 + 8;
    float linv0 = 1.0f / l0, linv1 = 1.0f / l1;
#pragma unroll
    for (int nf = 0; nf < 8; nf++) {
        int d0 = nf * 8 + idq * 2;
        int cg = h * 64 + d0;
        float pv0 = clamp_p(p_param[cg]);
        float pv1 = clamp_p(p_param[cg + 1]);
        float zm0 = g_zmax[b*Cn + cg];
        float zm1 = g_zmax[b*Cn + cg + 1];
        float y00 = expf((zm0 + logf(Of[nf][0] * linv0)) / pv0) - 5.0f;
        float y01 = expf((zm1 + logf(Of[nf][1] * linv0)) / pv1) - 5.0f;
        float y10 = expf((zm0 + logf(Of[nf][2] * linv1)) / pv0) - 5.0f;
        float y11 = expf((zm1 + logf(Of[nf][3] * linv1)) / pv1) - 5.0f;
        uint32_t h0 = pkhf(y00, y01);
        float2 u0 = unpkhf(h0);
        uint32_t l0p = pkhf(y00 - u0.x, y01 - u0.y);
        uint32_t h1 = pkhf(y10, y11);
        float2 u1 = unpkhf(h1);
        uint32_t l1p = pkhf(y10 - u1.x, y11 - u1.y);
        size_t i0 = ((size_t)(b*Tn + t0)*Cn + cg) >> 1;
        size_t i1 = ((size_t)(b*Tn + t1)*Cn + cg) >> 1;
        ((uint32_t*)gA_hi)[i0] = h0;
        ((uint32_t*)gA_lo)[i0] = l0p;
        ((uint32_t*)gA_hi)[i1] = h1;
        ((uint32_t*)gA_lo)[i1] = l1p;
    }
}

// ---------------------------------------------------------------------------

extern "C" void kernel_launch(void* const* d_in, const int* in_sizes, int n_in,
                              void* d_out, int out_size)
{
    const float* x       = (const float*)d_in[0];
    const float* w_attn  = (const float*)d_in[1];
    const float* b_attn  = (const float*)d_in[2];
    const float* w_proj  = (const float*)d_in[3];
    const float* b_proj  = (const float*)d_in[4];
    const float* p_param = (const float*)d_in[5];
    float* out = (float*)d_out;

    void *ah, *al, *bth;
    cudaGetSymbolAddress(&ah,  gA_hi);
    cudaGetSymbolAddress(&al,  gA_lo);
    cudaGetSymbolAddress(&bth, gBT_hi);

    cudaFuncSetAttribute(fa_kernel, cudaFuncAttributeMaxDynamicSharedMemorySize, FA_SMEM);
    cudaFuncSetAttribute(tc_gemm<0>, cudaFuncAttributeMaxDynamicSharedMemorySize, TCG_SMEM);
    cudaFuncSetAttribute(tc_gemm<1>, cudaFuncAttributeMaxDynamicSharedMemorySize, TCG_SMEM);

    // 1) split x (fp16 hi/lo); transpose w_attn (fp16 hi)
    split_fp16<<<Mn*Cn/1024, 256>>>(x, (__half*)ah, (__half*)al);
    transpose_h<<<dim3(3072/32, Cn/32), dim3(32,8)>>>(w_attn, (__half*)bth, 3072);

    // 2) QKV GEMM (fp16x2, 2 CTA/SM) + head-major scatter (Q fp16 hi/lo, K fp16 hi, V fp32)
    tc_gemm<1><<<dim3(3072/128, Mn/128), 256, TCG_SMEM>>>(
        (const __half*)ah, (const __half*)al, (const __half*)bth, b_attn, nullptr);

    // 3) z_max (partial + reduce) + V transform -> bf16 hi/lo
    zmax_part<<<dim3(BHn, 16), 256>>>(p_param);
    zmax_reduce<<<(Bn*Cn)/256, 256>>>();
    vexp_kernel<<<(BHn*Tn*Dn)/1024, 256>>>(p_param);

    // 4) tensor-core causal FA (fp16 2-term QK, bf16x3 PV); Y -> gA fp16 hi/lo
    fa_kernel<<<dim3(Tn/64, BHn), 128, FA_SMEM>>>(p_param);

    // 5) transpose w_proj (fp16 hi); proj GEMM (fp16x2)
    transpose_h<<<dim3(Cn/32, Cn/32), dim3(32,8)>>>(w_proj, (__half*)bth, Cn);
    tc_gemm<0><<<dim3(Cn/128, Mn/128), 256, TCG_SMEM>>>(
        (const __half*)ah, (const __half*)al, (const __half*)bth, b_proj, out);
}

// round 10
// speedup vs baseline: 5.7797x; 1.1881x over previous
#include <cuda_runtime.h>
#include <cuda_bf16.h>
#include <cuda_fp16.h>
#include <math.h>
#include <stdint.h>

#define Bn 2
#define Tn 2048
#define Cn 1024
#define Hn 16
#define Dn 64
#define Mn (Bn*Tn)          // 4096
#define BHn (Bn*Hn)         // 32

typedef unsigned long long ull;

// ---------------- device scratch ----------------
__device__ __half         g_Qh[BHn*Tn*Dn];  // head-major, pre-scaled by 0.125 (fp16 hi)
__device__ __half         g_Ql[BHn*Tn*Dn];  // fp16 lo
__device__ __half         g_Kh[BHn*Tn*Dn];  // fp16 hi only
__device__ float          g_V [BHn*Tn*Dn];  // raw v (fp32) for zmax
__device__ __nv_bfloat16  g_Vh[BHn*Tn*Dn];  // exp(z-zmax) bf16 hi/lo
__device__ __nv_bfloat16  g_Vl[BHn*Tn*Dn];
__device__ float g_zmax[Bn*Cn];
__device__ float g_zpart[16*Bn*Cn];
__device__ __half gA_hi[Mn*Cn];             // fp16 A operand (x conv, then Y from FA)
__device__ __half gA_lo[Mn*Cn];             // lo only used for Y (proj GEMM)
__device__ __half gBT_hi[3*Cn*Cn];          // fp16 weights^T (hi only)

__device__ __forceinline__ float clamp_p(float pp) {
    float sgn = (pp >= 0.0f) ? 1.0f : -1.0f;
    return sgn * fminf(fmaxf(fabsf(pp), 1e-4f), 1e3f);
}

// ---------------- ptx helpers ----------------
__device__ __forceinline__ uint32_t smem_u32(const void* p) {
    uint32_t a;
    asm("{ .reg .u64 t; cvta.to.shared.u64 t, %1; cvt.u32.u64 %0, t; }" : "=r"(a) : "l"(p));
    return a;
}
__device__ __forceinline__ void cp16(uint32_t dst, const void* src) {
    asm volatile("cp.async.cg.shared.global [%0], [%1], 16;\n" :: "r"(dst), "l"(src));
}
#define CP_COMMIT() asm volatile("cp.async.commit_group;\n" ::: "memory")

__device__ __forceinline__ void ldsm4(uint32_t& r0, uint32_t& r1, uint32_t& r2, uint32_t& r3,
                                      uint32_t addr) {
    asm volatile("ldmatrix.sync.aligned.m8n8.x4.shared.b16 {%0,%1,%2,%3}, [%4];"
                 : "=r"(r0), "=r"(r1), "=r"(r2), "=r"(r3) : "r"(addr));
}
__device__ __forceinline__ void ldsm4t(uint32_t& r0, uint32_t& r1, uint32_t& r2, uint32_t& r3,
                                       uint32_t addr) {
    asm volatile("ldmatrix.sync.aligned.m8n8.x4.trans.shared.b16 {%0,%1,%2,%3}, [%4];"
                 : "=r"(r0), "=r"(r1), "=r"(r2), "=r"(r3) : "r"(addr));
}
__device__ __forceinline__ void mma16816(float* c, const uint32_t* a, const uint32_t* b) {
    asm volatile(
        "mma.sync.aligned.m16n8k16.row.col.f32.bf16.bf16.f32 "
        "{%0,%1,%2,%3}, {%4,%5,%6,%7}, {%8,%9}, {%0,%1,%2,%3};"
        : "+f"(c[0]), "+f"(c[1]), "+f"(c[2]), "+f"(c[3])
        : "r"(a[0]), "r"(a[1]), "r"(a[2]), "r"(a[3]), "r"(b[0]), "r"(b[1]));
}
__device__ __forceinline__ void mma16816h(float* c, const uint32_t* a, const uint32_t* b) {
    asm volatile(
        "mma.sync.aligned.m16n8k16.row.col.f32.f16.f16.f32 "
        "{%0,%1,%2,%3}, {%4,%5,%6,%7}, {%8,%9}, {%0,%1,%2,%3};"
        : "+f"(c[0]), "+f"(c[1]), "+f"(c[2]), "+f"(c[3])
        : "r"(a[0]), "r"(a[1]), "r"(a[2]), "r"(a[3]), "r"(b[0]), "r"(b[1]));
}
__device__ __forceinline__ uint32_t pkbf(float lo, float hi) {
    uint32_t r;
    asm("cvt.rn.bf16x2.f32 %0, %1, %2;" : "=r"(r) : "f"(hi), "f"(lo));
    return r;
}
__device__ __forceinline__ uint32_t pkhf(float lo, float hi) {
    uint32_t r;
    asm("cvt.rn.f16x2.f32 %0, %1, %2;" : "=r"(r) : "f"(hi), "f"(lo));
    return r;
}
__device__ __forceinline__ float2 unpkhf(uint32_t u) {
    __half2 h = *reinterpret_cast<__half2*>(&u);
    return __half22float2(h);
}

// ---------------------------------------------------------------------------
// convert: fp32 -> fp16 (hi only, for QKV A operand)
// ---------------------------------------------------------------------------
__global__ __launch_bounds__(256) void conv_fp16(
    const float* __restrict__ A, __half* __restrict__ Ah)
{
    int i = blockIdx.x * 256 + threadIdx.x;
    float4 a = ((const float4*)A)[i];
    ((uint2*)Ah)[i] = make_uint2(pkhf(a.x, a.y), pkhf(a.z, a.w));
}

// ---------------------------------------------------------------------------
// transpose: W[K=1024][Nd] -> Th[Nd][1024] (fp16 hi only)
// ---------------------------------------------------------------------------
__global__ void transpose_h(const float* __restrict__ W,
                            __half* __restrict__ Th, int Nd)
{
    __shared__ float tile[32][33];
    int nx = blockIdx.x * 32, kx = blockIdx.y * 32;
    int tx = threadIdx.x, ty = threadIdx.y;
#pragma unroll
    for (int r = ty; r < 32; r += 8)
        tile[r][tx] = W[(size_t)(kx + r) * Nd + nx + tx];
    __syncthreads();
#pragma unroll
    for (int r = ty; r < 32; r += 8) {
        size_t o = (size_t)(nx + r) * 1024 + kx + tx;
        Th[o] = __float2half_rn(tile[tx][r]);
    }
}

// ---------------------------------------------------------------------------
// fp16 mma.sync GEMM: CTA 128x128, warp tile 64x32 (2x4 warps), BK=64,
// cp.async double buffer. MODE 1 (QKV): single-term A (hi only), 64 KB smem.
// MODE 0 (proj): 2-term A = (Ah+Al), 96 KB smem. D = A @ Bh^T.
// ---------------------------------------------------------------------------
template<int MODE>
__device__ __forceinline__ void load_stage(
    uint32_t sbase,
    const __half* __restrict__ Ah, const __half* __restrict__ Al,
    const __half* __restrict__ Bh,
    int m0, int n0, int k0, int tid)
{
    constexpr uint32_t BOFF = (MODE == 0) ? 32768u : 16384u;
#pragma unroll
    for (int j = 0; j < 4; j++) {          // A: 128 rows x 8 chunks
        int idx = tid + j * 256;
        int row = idx >> 3, c = idx & 7;
        uint32_t sw = row * 128 + ((c ^ (row & 7)) << 4);
        size_t ga = (size_t)(m0 + row) * 1024 + k0 + c * 8;
        cp16(sbase + sw, Ah + ga);
        if (MODE == 0) cp16(sbase + 16384 + sw, Al + ga);
    }
#pragma unroll
    for (int j = 0; j < 4; j++) {          // B: 128 rows x 8 chunks (hi only)
        int idx = tid + j * 256;
        int row = idx >> 3, c = idx & 7;
        uint32_t sw = row * 128 + ((c ^ (row & 7)) << 4);
        size_t gb = (size_t)(n0 + row) * 1024 + k0 + c * 8;
        cp16(sbase + BOFF + sw, Bh + gb);
    }
}

template<int MODE>
__global__ __launch_bounds__(256, 2) void tc_gemm(
    const __half* __restrict__ Ah, const __half* __restrict__ Al,
    const __half* __restrict__ Bh,
    const float* __restrict__ bias, float* __restrict__ Cout)
{
    constexpr uint32_t BOFF  = (MODE == 0) ? 32768u : 16384u;
    constexpr uint32_t G_STG = (MODE == 0) ? 49152u : 32768u;

    extern __shared__ char smem[];
    uint32_t sb = smem_u32(smem);
    const int tid  = threadIdx.x;
    const int wid  = tid >> 5;
    const int lane = tid & 31;
    const int wm = wid & 1;        // 2 warp-rows of 64
    const int wn = wid >> 1;       // 4 warp-cols of 32
    const int m0 = blockIdx.y * 128;
    const int n0 = blockIdx.x * 128;

    float acc[4][4][4];
#pragma unroll
    for (int i = 0; i < 4; i++)
#pragma unroll
        for (int j = 0; j < 4; j++)
#pragma unroll
            for (int q = 0; q < 4; q++) acc[i][j][q] = 0.0f;

    load_stage<MODE>(sb,         Ah, Al, Bh, m0, n0, 0,  tid); CP_COMMIT();
    load_stage<MODE>(sb + G_STG, Ah, Al, Bh, m0, n0, 64, tid); CP_COMMIT();

    const int a_row = wm * 64 + (lane & 15);
    const int a_c16 = (lane >> 4);
    const int b_row = wn * 32 + ((lane >> 4) << 3) + (lane & 7);
    const int b_cof = ((lane >> 3) & 1);

    for (int it = 0; it < 16; it++) {
        const int s = it & 1;
        const uint32_t sbase = sb + s * G_STG;
        if (it < 15) asm volatile("cp.async.wait_group 1;\n" ::: "memory");
        else         asm volatile("cp.async.wait_group 0;\n" ::: "memory");
        __syncthreads();

#pragma unroll
        for (int ks = 0; ks < 4; ks++) {
            uint32_t ahi[4][4], alo[4][4];
#pragma unroll
            for (int mf = 0; mf < 4; mf++) {
                int row = a_row + mf * 16;
                int c16 = ks * 2 + a_c16;
                uint32_t ad = sbase + row * 128 + ((c16 ^ (row & 7)) << 4);
                ldsm4(ahi[mf][0], ahi[mf][1], ahi[mf][2], ahi[mf][3], ad);
                if (MODE == 0)
                    ldsm4(alo[mf][0], alo[mf][1], alo[mf][2], alo[mf][3], ad + 16384);
            }
#pragma unroll
            for (int nf2 = 0; nf2 < 2; nf2++) {
                int row = b_row + nf2 * 16;
                int c16 = ks * 2 + b_cof;
                uint32_t bd = sbase + BOFF + row * 128 + ((c16 ^ (row & 7)) << 4);
                uint32_t bh4[4];
                ldsm4(bh4[0], bh4[1], bh4[2], bh4[3], bd);
#pragma unroll
                for (int mf = 0; mf < 4; mf++) {
                    mma16816h(acc[mf][2*nf2],   ahi[mf], bh4);
                    mma16816h(acc[mf][2*nf2+1], ahi[mf], bh4 + 2);
                    if (MODE == 0) {
                        mma16816h(acc[mf][2*nf2],   alo[mf], bh4);
                        mma16816h(acc[mf][2*nf2+1], alo[mf], bh4 + 2);
                    }
                }
            }
        }
        __syncthreads();
        if (it + 2 < 16) {
            load_stage<MODE>(sbase, Ah, Al, Bh, m0, n0, (it + 2) * 64, tid);
            CP_COMMIT();
        }
    }

    const int mbase = m0 + wm * 64 + (lane >> 2);
    const int nbase = n0 + wn * 32 + (lane & 3) * 2;
#pragma unroll
    for (int mf = 0; mf < 4; mf++) {
#pragma unroll
        for (int half = 0; half < 2; half++) {
            int m = mbase + mf * 16 + half * 8;
#pragma unroll
            for (int nf = 0; nf < 4; nf++) {
                int n = nbase + nf * 8;
                float v0 = acc[mf][nf][half*2+0] + bias[n];
                float v1 = acc[mf][nf][half*2+1] + bias[n+1];
                if (MODE == 0) {
                    *(float2*)(Cout + (size_t)m * Cn + n) = make_float2(v0, v1);
                } else {
                    int sec = n >> 10;
                    int c1  = n & 1023;
                    int h   = c1 >> 6, dd = c1 & 63;
                    int bq  = m >> 11, t = m & 2047;
                    size_t idx = ((size_t)((bq * Hn + h) * Tn + t)) * 64 + dd;
                    if (sec == 2) {
                        *(float2*)(g_V + idx) = make_float2(v0, v1);
                    } else if (sec == 1) {
                        *(uint32_t*)(g_Kh + idx) = pkhf(v0, v1);
                    } else {
                        v0 *= 0.125f; v1 *= 0.125f;
                        uint32_t hh = pkhf(v0, v1);
                        float2 u = unpkhf(hh);
                        uint32_t ll = pkhf(v0 - u.x, v1 - u.y);
                        *(uint32_t*)(g_Qh + idx) = hh;
                        *(uint32_t*)(g_Ql + idx) = ll;
                    }
                }
            }
        }
    }
}

// ---------------------------------------------------------------------------
// z_max partial + reduce
// ---------------------------------------------------------------------------
__global__ __launch_bounds__(256) void zmax_part(const float* __restrict__ p_param)
{
    int bh = blockIdx.x, chunk = blockIdx.y;
    int b = bh >> 4, h = bh & 15;
    int d4 = threadIdx.x & 15;
    int g  = threadIdx.x >> 4;
    int c  = h*64 + d4*4;
    float4 pv;
    pv.x = clamp_p(p_param[c+0]); pv.y = clamp_p(p_param[c+1]);
    pv.z = clamp_p(p_param[c+2]); pv.w = clamp_p(p_param[c+3]);

    const float* vp = g_V + (size_t)bh * Tn * 64;
    float4 mx = make_float4(-1e30f, -1e30f, -1e30f, -1e30f);
    for (int t = chunk*128 + g; t < (chunk+1)*128; t += 16) {
        float4 v = *(const float4*)(vp + t*64 + d4*4);
        mx.x = fmaxf(mx.x, pv.x * logf(fmaxf(fabsf(v.x + 5.0f), 1e-10f)));
        mx.y = fmaxf(mx.y, pv.y * logf(fmaxf(fabsf(v.y + 5.0f), 1e-10f)));
        mx.z = fmaxf(mx.z, pv.z * logf(fmaxf(fabsf(v.z + 5.0f), 1e-10f)));
        mx.w = fmaxf(mx.w, pv.w * logf(fmaxf(fabsf(v.w + 5.0f), 1e-10f)));
    }
    __shared__ float4 red[256];
    red[threadIdx.x] = mx;
    __syncthreads();
    if (threadIdx.x < 16) {
        float4 m = red[threadIdx.x];
#pragma unroll
        for (int gg = 1; gg < 16; gg++) {
            float4 o = red[gg*16 + threadIdx.x];
            m.x = fmaxf(m.x, o.x); m.y = fmaxf(m.y, o.y);
            m.z = fmaxf(m.z, o.z); m.w = fmaxf(m.w, o.w);
        }
        *(float4*)(g_zpart + chunk*(Bn*Cn) + b*Cn + h*64 + threadIdx.x*4) = m;
    }
}
__global__ __launch_bounds__(256) void zmax_reduce()
{
    int i = blockIdx.x * 256 + threadIdx.x;
    float mx = -1e30f;
#pragma unroll
    for (int ch = 0; ch < 16; ch++) mx = fmaxf(mx, g_zpart[ch*(Bn*Cn) + i]);
    g_zmax[i] = mx;
}

// ---------------------------------------------------------------------------
// V transform -> bf16 hi/lo (float4 per thread)
// ---------------------------------------------------------------------------
__global__ __launch_bounds__(256) void vexp_kernel(const float* __restrict__ p_param)
{
    int i = blockIdx.x * 256 + threadIdx.x;
    int base = i * 4;
    int dd = base & 63;
    int bh = base >> 17;
    int h = bh & 15, b = bh >> 4;
    int c = h*64 + dd;
    float4 v = *(const float4*)(g_V + base);
    float e[4];
    const float vs[4] = {v.x, v.y, v.z, v.w};
#pragma unroll
    for (int j = 0; j < 4; j++) {
        float pvj = clamp_p(p_param[c + j]);
        float z = pvj * logf(fmaxf(fabsf(vs[j] + 5.0f), 1e-10f)) - g_zmax[b*Cn + c + j];
        e[j] = expf(z);
    }
    uint32_t h0 = pkbf(e[0], e[1]), h1 = pkbf(e[2], e[3]);
    float f0 = __uint_as_float(h0 << 16), f1 = __uint_as_float(h0 & 0xffff0000u);
    float f2 = __uint_as_float(h1 << 16), f3 = __uint_as_float(h1 & 0xffff0000u);
    uint32_t l0 = pkbf(e[0]-f0, e[1]-f1), l1 = pkbf(e[2]-f2, e[3]-f3);
    ((uint2*)g_Vh)[i] = make_uint2(h0, h1);
    ((uint2*)g_Vl)[i] = make_uint2(l0, l1);
}

// ---------------------------------------------------------------------------
// Tensor-core flash attention (causal), BQ=BK=64, 4 warps, 64 KB smem
// -> 2+ CTAs/SM. S = fp16 2-term (Qh+Ql)·Kh; P·V bf16 3-term.
// Epilogue writes Y as fp16 hi/lo into gA_hi/gA_lo.
// ---------------------------------------------------------------------------
#define FAQ_H 0
#define FAQ_L 8192
#define FASTG0 16384
#define FASTG_SZ 24576
#define FKH 0
#define FVH 8192
#define FVL 16384
#define FA_SMEM (16384 + 2*FASTG_SZ)   // 64 KB

__device__ __forceinline__ void fa_load_stage(uint32_t sbase, int bh, int kt, int tid)
{
    const char* srcs[3] = {(const char*)g_Kh, (const char*)g_Vh, (const char*)g_Vl};
#pragma unroll
    for (int j = 0; j < 12; j++) {
        int idx = tid + j * 128;          // 0..1535 16B-chunks
        int arr = idx >> 9;               // 0..2
        int rem = idx & 511;
        int row = rem >> 3, c = rem & 7;
        uint32_t sw = arr * 8192 + row * 128 + ((c ^ (row & 7)) << 4);
        size_t gb = (((size_t)bh * Tn + kt * 64 + row) * 64 + c * 8) * 2;
        cp16(sbase + sw, srcs[arr] + gb);
    }
}

__global__ __launch_bounds__(128) void fa_kernel(const float* __restrict__ p_param)
{
    extern __shared__ char smem[];
    uint32_t sb = smem_u32(smem);
    const int tid  = threadIdx.x;
    const int w    = tid >> 5;
    const int lane = tid & 31;
    const int quad = lane >> 2;
    const int idq  = lane & 3;
    const int bh = blockIdx.y;
    const int b = bh >> 4, h = bh & 15;
    const int qt = (int)gridDim.x - 1 - (int)blockIdx.x;   // heavy first
    const int q0 = qt * 64;

    // ---- prologue: Q tile (fp16 hi/lo) + first stages ----
    {
        const char* qs[2] = {(const char*)g_Qh, (const char*)g_Ql};
#pragma unroll
        for (int j = 0; j < 8; j++) {
            int idx = tid + j * 128;
            int arr = idx >> 9;
            int rem = idx & 511;
            int row = rem >> 3, c = rem & 7;
            uint32_t sw = arr * 8192 + row * 128 + ((c ^ (row & 7)) << 4);
            size_t gb = (((size_t)bh * Tn + q0 + row) * 64 + c * 8) * 2;
            cp16(sb + sw, qs[arr] + gb);
        }
        fa_load_stage(sb + FASTG0, bh, 0, tid);
        CP_COMMIT();
        if (qt >= 1) fa_load_stage(sb + FASTG0 + FASTG_SZ, bh, 1, tid);
        CP_COMMIT();
    }

    uint32_t Qh[4][4], Ql[4][4];
    float Of[8][4];
    float m0 = -1e30f, m1 = -1e30f, l0 = 0.0f, l1 = 0.0f;
#pragma unroll
    for (int nf = 0; nf < 8; nf++)
#pragma unroll
        for (int q = 0; q < 4; q++) Of[nf][q] = 0.0f;

    const int k_row = ((lane >> 4) << 3) + (lane & 7);   // + nf2*16
    const int k_cof = ((lane >> 3) & 1);                 // + ks*2
    const int v_row = (lane & 15);                       // + kf*16
    const int v_cof = (lane >> 4);                       // + nf2*2

    for (int kt = 0; kt <= qt; kt++) {
        const uint32_t sbase = sb + FASTG0 + (kt & 1) * FASTG_SZ;
        if (kt < qt) asm volatile("cp.async.wait_group 1;\n" ::: "memory");
        else         asm volatile("cp.async.wait_group 0;\n" ::: "memory");
        __syncthreads();

        if (kt == 0) {
            int row = w * 16 + (lane & 15);
#pragma unroll
            for (int ks = 0; ks < 4; ks++) {
                int c16 = ks * 2 + (lane >> 4);
                uint32_t sw = row * 128 + ((c16 ^ (row & 7)) << 4);
                ldsm4(Qh[ks][0], Qh[ks][1], Qh[ks][2], Qh[ks][3], sb + FAQ_H + sw);
                ldsm4(Ql[ks][0], Ql[ks][1], Ql[ks][2], Ql[ks][3], sb + FAQ_L + sw);
            }
        }

        // ---- S = (Qh+Ql) Kh^T  (fp16, 2 terms) ----
        float Sf[8][4];
#pragma unroll
        for (int nf = 0; nf < 8; nf++)
#pragma unroll
            for (int q = 0; q < 4; q++) Sf[nf][q] = 0.0f;

#pragma unroll
        for (int nf2 = 0; nf2 < 4; nf2++) {
            int krow = nf2 * 16 + k_row;
#pragma unroll
            for (int ks = 0; ks < 4; ks++) {
                int c16 = ks * 2 + k_cof;
                uint32_t sw = krow * 128 + ((c16 ^ (krow & 7)) << 4);
                uint32_t kh[4];
                ldsm4(kh[0], kh[1], kh[2], kh[3], sbase + FKH + sw);
                mma16816h(Sf[2*nf2],   Qh[ks], kh);
                mma16816h(Sf[2*nf2],   Ql[ks], kh);
                mma16816h(Sf[2*nf2+1], Qh[ks], kh + 2);
                mma16816h(Sf[2*nf2+1], Ql[ks], kh + 2);
            }
        }

        // ---- causal mask on diagonal tile ----
        if (kt == qt) {
            int r0 = w * 16 + quad, r1 = r0 + 8;
#pragma unroll
            for (int nf = 0; nf < 8; nf++) {
                int c0 = nf * 8 + idq * 2;
                if (c0     > r0) Sf[nf][0] = -1e30f;
                if (c0 + 1 > r0) Sf[nf][1] = -1e30f;
                if (c0     > r1) Sf[nf][2] = -1e30f;
                if (c0 + 1 > r1) Sf[nf][3] = -1e30f;
            }
        }

        // ---- softmax (register, 2 rows/thread, quad shuffles) ----
        float mx0 = -1e30f, mx1 = -1e30f;
#pragma unroll
        for (int nf = 0; nf < 8; nf++) {
            mx0 = fmaxf(mx0, fmaxf(Sf[nf][0], Sf[nf][1]));
            mx1 = fmaxf(mx1, fmaxf(Sf[nf][2], Sf[nf][3]));
        }
#pragma unroll
        for (int off = 1; off < 4; off <<= 1) {
            mx0 = fmaxf(mx0, __shfl_xor_sync(0xffffffffu, mx0, off));
            mx1 = fmaxf(mx1, __shfl_xor_sync(0xffffffffu, mx1, off));
        }
        mx0 = fmaxf(mx0, m0);
        mx1 = fmaxf(mx1, m1);
        float a0 = __expf(m0 - mx0), a1 = __expf(m1 - mx1);
        m0 = mx0; m1 = mx1;

        float s0 = 0.0f, s1 = 0.0f;
#pragma unroll
        for (int nf = 0; nf < 8; nf++) {
            Sf[nf][0] = __expf(Sf[nf][0] - mx0);
            Sf[nf][1] = __expf(Sf[nf][1] - mx0);
            Sf[nf][2] = __expf(Sf[nf][2] - mx1);
            Sf[nf][3] = __expf(Sf[nf][3] - mx1);
            s0 += Sf[nf][0] + Sf[nf][1];
            s1 += Sf[nf][2] + Sf[nf][3];
        }
#pragma unroll
        for (int off = 1; off < 4; off <<= 1) {
            s0 += __shfl_xor_sync(0xffffffffu, s0, off);
            s1 += __shfl_xor_sync(0xffffffffu, s1, off);
        }
        l0 = l0 * a0 + s0;
        l1 = l1 * a1 + s1;

#pragma unroll
        for (int nf = 0; nf < 8; nf++) {
            Of[nf][0] *= a0; Of[nf][1] *= a0;
            Of[nf][2] *= a1; Of[nf][3] *= a1;
        }

        // ---- O += P V (P from S frags, bf16x3, ldsm4t V) ----
#pragma unroll
        for (int kf = 0; kf < 4; kf++) {
            uint32_t pha[4], pla[4];
#pragma unroll
            for (int half = 0; half < 2; half++) {
                float* sp = Sf[2*kf + half];
                uint32_t u0 = pkbf(sp[0], sp[1]);
                uint32_t u1 = pkbf(sp[2], sp[3]);
                float f00 = __uint_as_float(u0 << 16), f01 = __uint_as_float(u0 & 0xffff0000u);
                float f10 = __uint_as_float(u1 << 16), f11 = __uint_as_float(u1 & 0xffff0000u);
                pha[half*2+0] = u0;
                pha[half*2+1] = u1;
                pla[half*2+0] = pkbf(sp[0] - f00, sp[1] - f01);
                pla[half*2+1] = pkbf(sp[2] - f10, sp[3] - f11);
            }
            int vrow = kf * 16 + v_row;
#pragma unroll
            for (int nf2 = 0; nf2 < 4; nf2++) {
                int c16 = nf2 * 2 + v_cof;
                uint32_t sw = vrow * 128 + ((c16 ^ (vrow & 7)) << 4);
                uint32_t vh[4], vl[4];
                ldsm4t(vh[0], vh[1], vh[2], vh[3], sbase + FVH + sw);
                ldsm4t(vl[0], vl[1], vl[2], vl[3], sbase + FVL + sw);
                mma16816(Of[2*nf2],   pha, vh);
                mma16816(Of[2*nf2],   pla, vh);
                mma16816(Of[2*nf2],   pha, vl);
                mma16816(Of[2*nf2+1], pha, vh + 2);
                mma16816(Of[2*nf2+1], pla, vh + 2);
                mma16816(Of[2*nf2+1], pha, vl + 2);
            }
        }

        __syncthreads();
        if (kt + 2 <= qt) {
            fa_load_stage(sbase, bh, kt + 2, tid);
            CP_COMMIT();
        }
    }

    // ---- epilogue: y = exp((zmax + log(O/l))/p) - 5, write fp16 hi/lo ----
    const int t0 = q0 + w * 16 + quad;
    const int t1 = t0 + 8;
    float linv0 = 1.0f / l0, linv1 = 1.0f / l1;
#pragma unroll
    for (int nf = 0; nf < 8; nf++) {
        int d0 = nf * 8 + idq * 2;
        int cg = h * 64 + d0;
        float pv0 = clamp_p(p_param[cg]);
        float pv1 = clamp_p(p_param[cg + 1]);
        float zm0 = g_zmax[b*Cn + cg];
        float zm1 = g_zmax[b*Cn + cg + 1];
        float y00 = expf((zm0 + logf(Of[nf][0] * linv0)) / pv0) - 5.0f;
        float y01 = expf((zm1 + logf(Of[nf][1] * linv0)) / pv1) - 5.0f;
        float y10 = expf((zm0 + logf(Of[nf][2] * linv1)) / pv0) - 5.0f;
        float y11 = expf((zm1 + logf(Of[nf][3] * linv1)) / pv1) - 5.0f;
        uint32_t h0 = pkhf(y00, y01);
        float2 u0 = unpkhf(h0);
        uint32_t l0p = pkhf(y00 - u0.x, y01 - u0.y);
        uint32_t h1 = pkhf(y10, y11);
        float2 u1 = unpkhf(h1);
        uint32_t l1p = pkhf(y10 - u1.x, y11 - u1.y);
        size_t i0 = ((size_t)(b*Tn + t0)*Cn + cg) >> 1;
        size_t i1 = ((size_t)(b*Tn + t1)*Cn + cg) >> 1;
        ((uint32_t*)gA_hi)[i0] = h0;
        ((uint32_t*)gA_lo)[i0] = l0p;
        ((uint32_t*)gA_hi)[i1] = h1;
        ((uint32_t*)gA_lo)[i1] = l1p;
    }
}

// ---------------------------------------------------------------------------

extern "C" void kernel_launch(void* const* d_in, const int* in_sizes, int n_in,
                              void* d_out, int out_size)
{
    const float* x       = (const float*)d_in[0];
    const float* w_attn  = (const float*)d_in[1];
    const float* b_attn  = (const float*)d_in[2];
    const float* w_proj  = (const float*)d_in[3];
    const float* b_proj  = (const float*)d_in[4];
    const float* p_param = (const float*)d_in[5];
    float* out = (float*)d_out;

    void *ah, *al, *bth;
    cudaGetSymbolAddress(&ah,  gA_hi);
    cudaGetSymbolAddress(&al,  gA_lo);
    cudaGetSymbolAddress(&bth, gBT_hi);

    cudaFuncSetAttribute(fa_kernel, cudaFuncAttributeMaxDynamicSharedMemorySize, FA_SMEM);
    cudaFuncSetAttribute(tc_gemm<0>, cudaFuncAttributeMaxDynamicSharedMemorySize, 2*49152);
    cudaFuncSetAttribute(tc_gemm<1>, cudaFuncAttributeMaxDynamicSharedMemorySize, 2*32768);

    // 1) convert x -> fp16 (hi only); transpose w_attn (fp16 hi)
    conv_fp16<<<Mn*Cn/1024, 256>>>(x, (__half*)ah);
    transpose_h<<<dim3(3072/32, Cn/32), dim3(32,8)>>>(w_attn, (__half*)bth, 3072);

    // 2) QKV GEMM (fp16 single-term) + head-major scatter (Q fp16 hi/lo, K fp16 hi, V fp32)
    tc_gemm<1><<<dim3(3072/128, Mn/128), 256, 2*32768>>>(
        (const __half*)ah, (const __half*)al, (const __half*)bth, b_attn, nullptr);

    // 3) z_max (partial + reduce) + V transform -> bf16 hi/lo
    zmax_part<<<dim3(BHn, 16), 256>>>(p_param);
    zmax_reduce<<<(Bn*Cn)/256, 256>>>();
    vexp_kernel<<<(BHn*Tn*Dn)/1024, 256>>>(p_param);

    // 4) tensor-core causal FA (fp16 2-term QK, bf16x3 PV); Y -> gA fp16 hi/lo
    fa_kernel<<<dim3(Tn/64, BHn), 128, FA_SMEM>>>(p_param);

    // 5) transpose w_proj (fp16 hi); proj GEMM (fp16 2-term A)
    transpose_h<<<dim3(Cn/32, Cn/32), dim3(32,8)>>>(w_proj, (__half*)bth, Cn);
    tc_gemm<0><<<dim3(Cn/128, Mn/128), 256, 2*49152>>>(
        (const __half*)ah, (const __half*)al, (const __half*)bth, b_proj, out);
}

// round 11
// speedup vs baseline: 6.6436x; 1.1495x over previous
#include <cuda_runtime.h>
#include <cuda_bf16.h>
#include <cuda_fp16.h>
#include <math.h>
#include <stdint.h>

#define Bn 2
#define Tn 2048
#define Cn 1024
#define Hn 16
#define Dn 64
#define Mn (Bn*Tn)          // 4096
#define BHn (Bn*Hn)         // 32

typedef unsigned long long ull;

// ---------------- device scratch ----------------
__device__ __half         g_Qh[BHn*Tn*Dn];  // head-major, pre-scaled by 0.125 (fp16 hi only)
__device__ __half         g_Kh[BHn*Tn*Dn];  // fp16 hi only
__device__ float          g_V [BHn*Tn*Dn];  // raw v (fp32) for zmax
__device__ __nv_bfloat16  g_Vh[BHn*Tn*Dn];  // exp(z-zmax) bf16 hi/lo
__device__ __nv_bfloat16  g_Vl[BHn*Tn*Dn];
__device__ float g_zmax[Bn*Cn];
__device__ float g_zpart[16*Bn*Cn];
__device__ __half gA_hi[Mn*Cn];             // fp16 A operand (x conv, then Y from FA)
__device__ __half gBT_hi[3*Cn*Cn];          // fp16 weights^T (hi only)

__device__ __forceinline__ float clamp_p(float pp) {
    float sgn = (pp >= 0.0f) ? 1.0f : -1.0f;
    return sgn * fminf(fmaxf(fabsf(pp), 1e-4f), 1e3f);
}

// ---------------- ptx helpers ----------------
__device__ __forceinline__ uint32_t smem_u32(const void* p) {
    uint32_t a;
    asm("{ .reg .u64 t; cvta.to.shared.u64 t, %1; cvt.u32.u64 %0, t; }" : "=r"(a) : "l"(p));
    return a;
}
__device__ __forceinline__ void cp16(uint32_t dst, const void* src) {
    asm volatile("cp.async.cg.shared.global [%0], [%1], 16;\n" :: "r"(dst), "l"(src));
}
#define CP_COMMIT() asm volatile("cp.async.commit_group;\n" ::: "memory")

__device__ __forceinline__ void ldsm4(uint32_t& r0, uint32_t& r1, uint32_t& r2, uint32_t& r3,
                                      uint32_t addr) {
    asm volatile("ldmatrix.sync.aligned.m8n8.x4.shared.b16 {%0,%1,%2,%3}, [%4];"
                 : "=r"(r0), "=r"(r1), "=r"(r2), "=r"(r3) : "r"(addr));
}
__device__ __forceinline__ void ldsm4t(uint32_t& r0, uint32_t& r1, uint32_t& r2, uint32_t& r3,
                                       uint32_t addr) {
    asm volatile("ldmatrix.sync.aligned.m8n8.x4.trans.shared.b16 {%0,%1,%2,%3}, [%4];"
                 : "=r"(r0), "=r"(r1), "=r"(r2), "=r"(r3) : "r"(addr));
}
__device__ __forceinline__ void mma16816(float* c, const uint32_t* a, const uint32_t* b) {
    asm volatile(
        "mma.sync.aligned.m16n8k16.row.col.f32.bf16.bf16.f32 "
        "{%0,%1,%2,%3}, {%4,%5,%6,%7}, {%8,%9}, {%0,%1,%2,%3};"
        : "+f"(c[0]), "+f"(c[1]), "+f"(c[2]), "+f"(c[3])
        : "r"(a[0]), "r"(a[1]), "r"(a[2]), "r"(a[3]), "r"(b[0]), "r"(b[1]));
}
__device__ __forceinline__ void mma16816h(float* c, const uint32_t* a, const uint32_t* b) {
    asm volatile(
        "mma.sync.aligned.m16n8k16.row.col.f32.f16.f16.f32 "
        "{%0,%1,%2,%3}, {%4,%5,%6,%7}, {%8,%9}, {%0,%1,%2,%3};"
        : "+f"(c[0]), "+f"(c[1]), "+f"(c[2]), "+f"(c[3])
        : "r"(a[0]), "r"(a[1]), "r"(a[2]), "r"(a[3]), "r"(b[0]), "r"(b[1]));
}
__device__ __forceinline__ uint32_t pkbf(float lo, float hi) {
    uint32_t r;
    asm("cvt.rn.bf16x2.f32 %0, %1, %2;" : "=r"(r) : "f"(hi), "f"(lo));
    return r;
}
__device__ __forceinline__ uint32_t pkhf(float lo, float hi) {
    uint32_t r;
    asm("cvt.rn.f16x2.f32 %0, %1, %2;" : "=r"(r) : "f"(hi), "f"(lo));
    return r;
}

// ---------------------------------------------------------------------------
// convert: fp32 -> fp16 (hi only)
// ---------------------------------------------------------------------------
__global__ __launch_bounds__(256) void conv_fp16(
    const float* __restrict__ A, __half* __restrict__ Ah)
{
    int i = blockIdx.x * 256 + threadIdx.x;
    float4 a = ((const float4*)A)[i];
    ((uint2*)Ah)[i] = make_uint2(pkhf(a.x, a.y), pkhf(a.z, a.w));
}

// ---------------------------------------------------------------------------
// transpose: W[K=1024][Nd] -> Th[Nd][1024] (fp16 hi only)
// ---------------------------------------------------------------------------
__global__ void transpose_h(const float* __restrict__ W,
                            __half* __restrict__ Th, int Nd)
{
    __shared__ float tile[32][33];
    int nx = blockIdx.x * 32, kx = blockIdx.y * 32;
    int tx = threadIdx.x, ty = threadIdx.y;
#pragma unroll
    for (int r = ty; r < 32; r += 8)
        tile[r][tx] = W[(size_t)(kx + r) * Nd + nx + tx];
    __syncthreads();
#pragma unroll
    for (int r = ty; r < 32; r += 8) {
        size_t o = (size_t)(nx + r) * 1024 + kx + tx;
        Th[o] = __float2half_rn(tile[tx][r]);
    }
}

// ---------------------------------------------------------------------------
// fp16 single-term mma.sync GEMM: CTA 128x128, warp tile 64x32 (2x4 warps),
// BK=64, cp.async double buffer, 64 KB smem. D = Ah @ Bh^T.
// MODE 0: out+bias. MODE 1: QKV scatter (Q fp16 hi, K fp16 hi, V fp32).
// ---------------------------------------------------------------------------
#define G_BHI 16384
#define G_STG 32768
#define TCG_SMEM (2*G_STG)   // 64 KB

__device__ __forceinline__ void load_stage(
    uint32_t sbase,
    const __half* __restrict__ Ah, const __half* __restrict__ Bh,
    int m0, int n0, int k0, int tid)
{
#pragma unroll
    for (int j = 0; j < 4; j++) {          // A: 128 rows x 8 chunks
        int idx = tid + j * 256;
        int row = idx >> 3, c = idx & 7;
        uint32_t sw = row * 128 + ((c ^ (row & 7)) << 4);
        size_t ga = (size_t)(m0 + row) * 1024 + k0 + c * 8;
        cp16(sbase + sw, Ah + ga);
    }
#pragma unroll
    for (int j = 0; j < 4; j++) {          // B: 128 rows x 8 chunks
        int idx = tid + j * 256;
        int row = idx >> 3, c = idx & 7;
        uint32_t sw = row * 128 + ((c ^ (row & 7)) << 4);
        size_t gb = (size_t)(n0 + row) * 1024 + k0 + c * 8;
        cp16(sbase + G_BHI + sw, Bh + gb);
    }
}

template<int MODE>
__global__ __launch_bounds__(256, 2) void tc_gemm(
    const __half* __restrict__ Ah, const __half* __restrict__ Bh,
    const float* __restrict__ bias, float* __restrict__ Cout)
{
    extern __shared__ char smem[];
    uint32_t sb = smem_u32(smem);
    const int tid  = threadIdx.x;
    const int wid  = tid >> 5;
    const int lane = tid & 31;
    const int wm = wid & 1;        // 2 warp-rows of 64
    const int wn = wid >> 1;       // 4 warp-cols of 32
    const int m0 = blockIdx.y * 128;
    const int n0 = blockIdx.x * 128;

    float acc[4][4][4];
#pragma unroll
    for (int i = 0; i < 4; i++)
#pragma unroll
        for (int j = 0; j < 4; j++)
#pragma unroll
            for (int q = 0; q < 4; q++) acc[i][j][q] = 0.0f;

    load_stage(sb,         Ah, Bh, m0, n0, 0,  tid); CP_COMMIT();
    load_stage(sb + G_STG, Ah, Bh, m0, n0, 64, tid); CP_COMMIT();

    const int a_row = wm * 64 + (lane & 15);
    const int a_c16 = (lane >> 4);
    const int b_row = wn * 32 + ((lane >> 4) << 3) + (lane & 7);
    const int b_cof = ((lane >> 3) & 1);

    for (int it = 0; it < 16; it++) {
        const int s = it & 1;
        const uint32_t sbase = sb + s * G_STG;
        if (it < 15) asm volatile("cp.async.wait_group 1;\n" ::: "memory");
        else         asm volatile("cp.async.wait_group 0;\n" ::: "memory");
        __syncthreads();

#pragma unroll
        for (int ks = 0; ks < 4; ks++) {
            uint32_t ahi[4][4];
#pragma unroll
            for (int mf = 0; mf < 4; mf++) {
                int row = a_row + mf * 16;
                int c16 = ks * 2 + a_c16;
                uint32_t ad = sbase + row * 128 + ((c16 ^ (row & 7)) << 4);
                ldsm4(ahi[mf][0], ahi[mf][1], ahi[mf][2], ahi[mf][3], ad);
            }
#pragma unroll
            for (int nf2 = 0; nf2 < 2; nf2++) {
                int row = b_row + nf2 * 16;
                int c16 = ks * 2 + b_cof;
                uint32_t bd = sbase + G_BHI + row * 128 + ((c16 ^ (row & 7)) << 4);
                uint32_t bh4[4];
                ldsm4(bh4[0], bh4[1], bh4[2], bh4[3], bd);
#pragma unroll
                for (int mf = 0; mf < 4; mf++) {
                    mma16816h(acc[mf][2*nf2],   ahi[mf], bh4);
                    mma16816h(acc[mf][2*nf2+1], ahi[mf], bh4 + 2);
                }
            }
        }
        __syncthreads();
        if (it + 2 < 16) {
            load_stage(sbase, Ah, Bh, m0, n0, (it + 2) * 64, tid);
            CP_COMMIT();
        }
    }

    const int mbase = m0 + wm * 64 + (lane >> 2);
    const int nbase = n0 + wn * 32 + (lane & 3) * 2;
#pragma unroll
    for (int mf = 0; mf < 4; mf++) {
#pragma unroll
        for (int half = 0; half < 2; half++) {
            int m = mbase + mf * 16 + half * 8;
#pragma unroll
            for (int nf = 0; nf < 4; nf++) {
                int n = nbase + nf * 8;
                float v0 = acc[mf][nf][half*2+0] + bias[n];
                float v1 = acc[mf][nf][half*2+1] + bias[n+1];
                if (MODE == 0) {
                    *(float2*)(Cout + (size_t)m * Cn + n) = make_float2(v0, v1);
                } else {
                    int sec = n >> 10;
                    int c1  = n & 1023;
                    int h   = c1 >> 6, dd = c1 & 63;
                    int bq  = m >> 11, t = m & 2047;
                    size_t idx = ((size_t)((bq * Hn + h) * Tn + t)) * 64 + dd;
                    if (sec == 2) {
                        *(float2*)(g_V + idx) = make_float2(v0, v1);
                    } else if (sec == 1) {
                        *(uint32_t*)(g_Kh + idx) = pkhf(v0, v1);
                    } else {
                        *(uint32_t*)(g_Qh + idx) = pkhf(v0 * 0.125f, v1 * 0.125f);
                    }
                }
            }
        }
    }
}

// ---------------------------------------------------------------------------
// z_max partial + reduce
// ---------------------------------------------------------------------------
__global__ __launch_bounds__(256) void zmax_part(const float* __restrict__ p_param)
{
    int bh = blockIdx.x, chunk = blockIdx.y;
    int b = bh >> 4, h = bh & 15;
    int d4 = threadIdx.x & 15;
    int g  = threadIdx.x >> 4;
    int c  = h*64 + d4*4;
    float4 pv;
    pv.x = clamp_p(p_param[c+0]); pv.y = clamp_p(p_param[c+1]);
    pv.z = clamp_p(p_param[c+2]); pv.w = clamp_p(p_param[c+3]);

    const float* vp = g_V + (size_t)bh * Tn * 64;
    float4 mx = make_float4(-1e30f, -1e30f, -1e30f, -1e30f);
    for (int t = chunk*128 + g; t < (chunk+1)*128; t += 16) {
        float4 v = *(const float4*)(vp + t*64 + d4*4);
        mx.x = fmaxf(mx.x, pv.x * logf(fmaxf(fabsf(v.x + 5.0f), 1e-10f)));
        mx.y = fmaxf(mx.y, pv.y * logf(fmaxf(fabsf(v.y + 5.0f), 1e-10f)));
        mx.z = fmaxf(mx.z, pv.z * logf(fmaxf(fabsf(v.z + 5.0f), 1e-10f)));
        mx.w = fmaxf(mx.w, pv.w * logf(fmaxf(fabsf(v.w + 5.0f), 1e-10f)));
    }
    __shared__ float4 red[256];
    red[threadIdx.x] = mx;
    __syncthreads();
    if (threadIdx.x < 16) {
        float4 m = red[threadIdx.x];
#pragma unroll
        for (int gg = 1; gg < 16; gg++) {
            float4 o = red[gg*16 + threadIdx.x];
            m.x = fmaxf(m.x, o.x); m.y = fmaxf(m.y, o.y);
            m.z = fmaxf(m.z, o.z); m.w = fmaxf(m.w, o.w);
        }
        *(float4*)(g_zpart + chunk*(Bn*Cn) + b*Cn + h*64 + threadIdx.x*4) = m;
    }
}
__global__ __launch_bounds__(256) void zmax_reduce()
{
    int i = blockIdx.x * 256 + threadIdx.x;
    float mx = -1e30f;
#pragma unroll
    for (int ch = 0; ch < 16; ch++) mx = fmaxf(mx, g_zpart[ch*(Bn*Cn) + i]);
    g_zmax[i] = mx;
}

// ---------------------------------------------------------------------------
// V transform -> bf16 hi/lo (float4 per thread)
// ---------------------------------------------------------------------------
__global__ __launch_bounds__(256) void vexp_kernel(const float* __restrict__ p_param)
{
    int i = blockIdx.x * 256 + threadIdx.x;
    int base = i * 4;
    int dd = base & 63;
    int bh = base >> 17;
    int h = bh & 15, b = bh >> 4;
    int c = h*64 + dd;
    float4 v = *(const float4*)(g_V + base);
    float e[4];
    const float vs[4] = {v.x, v.y, v.z, v.w};
#pragma unroll
    for (int j = 0; j < 4; j++) {
        float pvj = clamp_p(p_param[c + j]);
        float z = pvj * logf(fmaxf(fabsf(vs[j] + 5.0f), 1e-10f)) - g_zmax[b*Cn + c + j];
        e[j] = expf(z);
    }
    uint32_t h0 = pkbf(e[0], e[1]), h1 = pkbf(e[2], e[3]);
    float f0 = __uint_as_float(h0 << 16), f1 = __uint_as_float(h0 & 0xffff0000u);
    float f2 = __uint_as_float(h1 << 16), f3 = __uint_as_float(h1 & 0xffff0000u);
    uint32_t l0 = pkbf(e[0]-f0, e[1]-f1), l1 = pkbf(e[2]-f2, e[3]-f3);
    ((uint2*)g_Vh)[i] = make_uint2(h0, h1);
    ((uint2*)g_Vl)[i] = make_uint2(l0, l1);
}

// ---------------------------------------------------------------------------
// Tensor-core flash attention (causal), BQ=BK=64, 4 warps, 56 KB smem
// -> up to 4 CTAs/SM. S = fp16 1-term Qh·Kh; P·V bf16 3-term.
// Epilogue writes Y as fp16 hi into gA_hi.
// ---------------------------------------------------------------------------
#define FAQ_H 0
#define FASTG0 8192
#define FASTG_SZ 24576
#define FKH 0
#define FVH 8192
#define FVL 16384
#define FA_SMEM (8192 + 2*FASTG_SZ)   // 56 KB

__device__ __forceinline__ void fa_load_stage(uint32_t sbase, int bh, int kt, int tid)
{
    const char* srcs[3] = {(const char*)g_Kh, (const char*)g_Vh, (const char*)g_Vl};
#pragma unroll
    for (int j = 0; j < 12; j++) {
        int idx = tid + j * 128;          // 0..1535 16B-chunks
        int arr = idx >> 9;               // 0..2
        int rem = idx & 511;
        int row = rem >> 3, c = rem & 7;
        uint32_t sw = arr * 8192 + row * 128 + ((c ^ (row & 7)) << 4);
        size_t gb = (((size_t)bh * Tn + kt * 64 + row) * 64 + c * 8) * 2;
        cp16(sbase + sw, srcs[arr] + gb);
    }
}

__global__ __launch_bounds__(128) void fa_kernel(const float* __restrict__ p_param)
{
    extern __shared__ char smem[];
    uint32_t sb = smem_u32(smem);
    const int tid  = threadIdx.x;
    const int w    = tid >> 5;
    const int lane = tid & 31;
    const int quad = lane >> 2;
    const int idq  = lane & 3;
    const int bh = blockIdx.y;
    const int b = bh >> 4, h = bh & 15;
    const int qt = (int)gridDim.x - 1 - (int)blockIdx.x;   // heavy first
    const int q0 = qt * 64;

    // ---- prologue: Q tile (fp16 hi) + first stages ----
    {
#pragma unroll
        for (int j = 0; j < 4; j++) {
            int idx = tid + j * 128;      // 0..511 chunks (64 rows x 8)
            int row = idx >> 3, c = idx & 7;
            uint32_t sw = row * 128 + ((c ^ (row & 7)) << 4);
            size_t gb = (((size_t)bh * Tn + q0 + row) * 64 + c * 8) * 2;
            cp16(sb + FAQ_H + sw, (const char*)g_Qh + gb);
        }
        fa_load_stage(sb + FASTG0, bh, 0, tid);
        CP_COMMIT();
        if (qt >= 1) fa_load_stage(sb + FASTG0 + FASTG_SZ, bh, 1, tid);
        CP_COMMIT();
    }

    uint32_t Qh[4][4];
    float Of[8][4];
    float m0 = -1e30f, m1 = -1e30f, l0 = 0.0f, l1 = 0.0f;
#pragma unroll
    for (int nf = 0; nf < 8; nf++)
#pragma unroll
        for (int q = 0; q < 4; q++) Of[nf][q] = 0.0f;

    const int k_row = ((lane >> 4) << 3) + (lane & 7);   // + nf2*16
    const int k_cof = ((lane >> 3) & 1);                 // + ks*2
    const int v_row = (lane & 15);                       // + kf*16
    const int v_cof = (lane >> 4);                       // + nf2*2

    for (int kt = 0; kt <= qt; kt++) {
        const uint32_t sbase = sb + FASTG0 + (kt & 1) * FASTG_SZ;
        if (kt < qt) asm volatile("cp.async.wait_group 1;\n" ::: "memory");
        else         asm volatile("cp.async.wait_group 0;\n" ::: "memory");
        __syncthreads();

        if (kt == 0) {
            int row = w * 16 + (lane & 15);
#pragma unroll
            for (int ks = 0; ks < 4; ks++) {
                int c16 = ks * 2 + (lane >> 4);
                uint32_t sw = row * 128 + ((c16 ^ (row & 7)) << 4);
                ldsm4(Qh[ks][0], Qh[ks][1], Qh[ks][2], Qh[ks][3], sb + FAQ_H + sw);
            }
        }

        // ---- S = Qh Kh^T  (fp16, 1 term) ----
        float Sf[8][4];
#pragma unroll
        for (int nf = 0; nf < 8; nf++)
#pragma unroll
            for (int q = 0; q < 4; q++) Sf[nf][q] = 0.0f;

#pragma unroll
        for (int nf2 = 0; nf2 < 4; nf2++) {
            int krow = nf2 * 16 + k_row;
#pragma unroll
            for (int ks = 0; ks < 4; ks++) {
                int c16 = ks * 2 + k_cof;
                uint32_t sw = krow * 128 + ((c16 ^ (krow & 7)) << 4);
                uint32_t kh[4];
                ldsm4(kh[0], kh[1], kh[2], kh[3], sbase + FKH + sw);
                mma16816h(Sf[2*nf2],   Qh[ks], kh);
                mma16816h(Sf[2*nf2+1], Qh[ks], kh + 2);
            }
        }

        // ---- causal mask on diagonal tile ----
        if (kt == qt) {
            int r0 = w * 16 + quad, r1 = r0 + 8;
#pragma unroll
            for (int nf = 0; nf < 8; nf++) {
                int c0 = nf * 8 + idq * 2;
                if (c0     > r0) Sf[nf][0] = -1e30f;
                if (c0 + 1 > r0) Sf[nf][1] = -1e30f;
                if (c0     > r1) Sf[nf][2] = -1e30f;
                if (c0 + 1 > r1) Sf[nf][3] = -1e30f;
            }
        }

        // ---- softmax (register, 2 rows/thread, quad shuffles) ----
        float mx0 = -1e30f, mx1 = -1e30f;
#pragma unroll
        for (int nf = 0; nf < 8; nf++) {
            mx0 = fmaxf(mx0, fmaxf(Sf[nf][0], Sf[nf][1]));
            mx1 = fmaxf(mx1, fmaxf(Sf[nf][2], Sf[nf][3]));
        }
#pragma unroll
        for (int off = 1; off < 4; off <<= 1) {
            mx0 = fmaxf(mx0, __shfl_xor_sync(0xffffffffu, mx0, off));
            mx1 = fmaxf(mx1, __shfl_xor_sync(0xffffffffu, mx1, off));
        }
        mx0 = fmaxf(mx0, m0);
        mx1 = fmaxf(mx1, m1);
        float a0 = __expf(m0 - mx0), a1 = __expf(m1 - mx1);
        m0 = mx0; m1 = mx1;

        float s0 = 0.0f, s1 = 0.0f;
#pragma unroll
        for (int nf = 0; nf < 8; nf++) {
            Sf[nf][0] = __expf(Sf[nf][0] - mx0);
            Sf[nf][1] = __expf(Sf[nf][1] - mx0);
            Sf[nf][2] = __expf(Sf[nf][2] - mx1);
            Sf[nf][3] = __expf(Sf[nf][3] - mx1);
            s0 += Sf[nf][0] + Sf[nf][1];
            s1 += Sf[nf][2] + Sf[nf][3];
        }
#pragma unroll
        for (int off = 1; off < 4; off <<= 1) {
            s0 += __shfl_xor_sync(0xffffffffu, s0, off);
            s1 += __shfl_xor_sync(0xffffffffu, s1, off);
        }
        l0 = l0 * a0 + s0;
        l1 = l1 * a1 + s1;

#pragma unroll
        for (int nf = 0; nf < 8; nf++) {
            Of[nf][0] *= a0; Of[nf][1] *= a0;
            Of[nf][2] *= a1; Of[nf][3] *= a1;
        }

        // ---- O += P V (P from S frags, bf16x3, ldsm4t V) ----
#pragma unroll
        for (int kf = 0; kf < 4; kf++) {
            uint32_t pha[4], pla[4];
#pragma unroll
            for (int half = 0; half < 2; half++) {
                float* sp = Sf[2*kf + half];
                uint32_t u0 = pkbf(sp[0], sp[1]);
                uint32_t u1 = pkbf(sp[2], sp[3]);
                float f00 = __uint_as_float(u0 << 16), f01 = __uint_as_float(u0 & 0xffff0000u);
                float f10 = __uint_as_float(u1 << 16), f11 = __uint_as_float(u1 & 0xffff0000u);
                pha[half*2+0] = u0;
                pha[half*2+1] = u1;
                pla[half*2+0] = pkbf(sp[0] - f00, sp[1] - f01);
                pla[half*2+1] = pkbf(sp[2] - f10, sp[3] - f11);
            }
            int vrow = kf * 16 + v_row;
#pragma unroll
            for (int nf2 = 0; nf2 < 4; nf2++) {
                int c16 = nf2 * 2 + v_cof;
                uint32_t sw = vrow * 128 + ((c16 ^ (vrow & 7)) << 4);
                uint32_t vh[4], vl[4];
                ldsm4t(vh[0], vh[1], vh[2], vh[3], sbase + FVH + sw);
                ldsm4t(vl[0], vl[1], vl[2], vl[3], sbase + FVL + sw);
                mma16816(Of[2*nf2],   pha, vh);
                mma16816(Of[2*nf2],   pla, vh);
                mma16816(Of[2*nf2],   pha, vl);
                mma16816(Of[2*nf2+1], pha, vh + 2);
                mma16816(Of[2*nf2+1], pla, vh + 2);
                mma16816(Of[2*nf2+1], pha, vl + 2);
            }
        }

        __syncthreads();
        if (kt + 2 <= qt) {
            fa_load_stage(sbase, bh, kt + 2, tid);
            CP_COMMIT();
        }
    }

    // ---- epilogue: y = exp((zmax + log(O/l))/p) - 5, write fp16 hi ----
    const int t0 = q0 + w * 16 + quad;
    const int t1 = t0 + 8;
    float linv0 = 1.0f / l0, linv1 = 1.0f / l1;
#pragma unroll
    for (int nf = 0; nf < 8; nf++) {
        int d0 = nf * 8 + idq * 2;
        int cg = h * 64 + d0;
        float pv0 = clamp_p(p_param[cg]);
        float pv1 = clamp_p(p_param[cg + 1]);
        float zm0 = g_zmax[b*Cn + cg];
        float zm1 = g_zmax[b*Cn + cg + 1];
        float y00 = expf((zm0 + logf(Of[nf][0] * linv0)) / pv0) - 5.0f;
        float y01 = expf((zm1 + logf(Of[nf][1] * linv0)) / pv1) - 5.0f;
        float y10 = expf((zm0 + logf(Of[nf][2] * linv1)) / pv0) - 5.0f;
        float y11 = expf((zm1 + logf(Of[nf][3] * linv1)) / pv1) - 5.0f;
        size_t i0 = ((size_t)(b*Tn + t0)*Cn + cg) >> 1;
        size_t i1 = ((size_t)(b*Tn + t1)*Cn + cg) >> 1;
        ((uint32_t*)gA_hi)[i0] = pkhf(y00, y01);
        ((uint32_t*)gA_hi)[i1] = pkhf(y10, y11);
    }
}

// ---------------------------------------------------------------------------

extern "C" void kernel_launch(void* const* d_in, const int* in_sizes, int n_in,
                              void* d_out, int out_size)
{
    const float* x       = (const float*)d_in[0];
    const float* w_attn  = (const float*)d_in[1];
    const float* b_attn  = (const float*)d_in[2];
    const float* w_proj  = (const float*)d_in[3];
    const float* b_proj  = (const float*)d_in[4];
    const float* p_param = (const float*)d_in[5];
    float* out = (float*)d_out;

    void *ah, *bth;
    cudaGetSymbolAddress(&ah,  gA_hi);
    cudaGetSymbolAddress(&bth, gBT_hi);

    cudaFuncSetAttribute(fa_kernel, cudaFuncAttributeMaxDynamicSharedMemorySize, FA_SMEM);
    cudaFuncSetAttribute(tc_gemm<0>, cudaFuncAttributeMaxDynamicSharedMemorySize, TCG_SMEM);
    cudaFuncSetAttribute(tc_gemm<1>, cudaFuncAttributeMaxDynamicSharedMemorySize, TCG_SMEM);

    // 1) convert x -> fp16; transpose w_attn (fp16 hi)
    conv_fp16<<<Mn*Cn/1024, 256>>>(x, (__half*)ah);
    transpose_h<<<dim3(3072/32, Cn/32), dim3(32,8)>>>(w_attn, (__half*)bth, 3072);

    // 2) QKV GEMM (fp16 single-term) + head-major scatter (Q/K fp16 hi, V fp32)
    tc_gemm<1><<<dim3(3072/128, Mn/128), 256, TCG_SMEM>>>(
        (const __half*)ah, (const __half*)bth, b_attn, nullptr);

    // 3) z_max (partial + reduce) + V transform -> bf16 hi/lo
    zmax_part<<<dim3(BHn, 16), 256>>>(p_param);
    zmax_reduce<<<(Bn*Cn)/256, 256>>>();
    vexp_kernel<<<(BHn*Tn*Dn)/1024, 256>>>(p_param);

    // 4) tensor-core causal FA (fp16 1-term QK, bf16x3 PV); Y -> gA fp16 hi
    fa_kernel<<<dim3(Tn/64, BHn), 128, FA_SMEM>>>(p_param);

    // 5) transpose w_proj (fp16 hi); proj GEMM (fp16 single-term)
    transpose_h<<<dim3(Cn/32, Cn/32), dim3(32,8)>>>(w_proj, (__half*)bth, Cn);
    tc_gemm<0><<<dim3(Cn/128, Mn/128), 256, TCG_SMEM>>>(
        (const __half*)ah, (const __half*)bth, b_proj, out);
}

// round 12
// speedup vs baseline: 6.9476x; 1.0458x over previous
#include <cuda_runtime.h>
#include <cuda_bf16.h>
#include <cuda_fp16.h>
#include <math.h>
#include <stdint.h>

#define Bn 2
#define Tn 2048
#define Cn 1024
#define Hn 16
#define Dn 64
#define Mn (Bn*Tn)          // 4096
#define BHn (Bn*Hn)         // 32

typedef unsigned long long ull;

// ---------------- device scratch ----------------
__device__ __half         g_Qh[BHn*Tn*Dn];  // head-major, pre-scaled by 0.125 (fp16 hi only)
__device__ __half         g_Kh[BHn*Tn*Dn];  // fp16 hi only
__device__ float          g_V [BHn*Tn*Dn];  // raw v (fp32) for zmax
__device__ __nv_bfloat16  g_Vh[BHn*Tn*Dn];  // exp(z-zmax) bf16 hi/lo
__device__ __nv_bfloat16  g_Vl[BHn*Tn*Dn];
__device__ float g_zmax[Bn*Cn];
__device__ float g_zpart[16*Bn*Cn];
__device__ __half gA_hi[Mn*Cn];             // fp16 A operand (x conv, then Y from FA)
__device__ __half gBT_hi[3*Cn*Cn];          // fp16 weights^T (hi only)

__device__ __forceinline__ float clamp_p(float pp) {
    float sgn = (pp >= 0.0f) ? 1.0f : -1.0f;
    return sgn * fminf(fmaxf(fabsf(pp), 1e-4f), 1e3f);
}

// ---------------- ptx helpers ----------------
__device__ __forceinline__ uint32_t smem_u32(const void* p) {
    uint32_t a;
    asm("{ .reg .u64 t; cvta.to.shared.u64 t, %1; cvt.u32.u64 %0, t; }" : "=r"(a) : "l"(p));
    return a;
}
__device__ __forceinline__ void cp16(uint32_t dst, const void* src) {
    asm volatile("cp.async.cg.shared.global [%0], [%1], 16;\n" :: "r"(dst), "l"(src));
}
#define CP_COMMIT() asm volatile("cp.async.commit_group;\n" ::: "memory")

__device__ __forceinline__ void ldsm4(uint32_t& r0, uint32_t& r1, uint32_t& r2, uint32_t& r3,
                                      uint32_t addr) {
    asm volatile("ldmatrix.sync.aligned.m8n8.x4.shared.b16 {%0,%1,%2,%3}, [%4];"
                 : "=r"(r0), "=r"(r1), "=r"(r2), "=r"(r3) : "r"(addr));
}
__device__ __forceinline__ void ldsm4t(uint32_t& r0, uint32_t& r1, uint32_t& r2, uint32_t& r3,
                                       uint32_t addr) {
    asm volatile("ldmatrix.sync.aligned.m8n8.x4.trans.shared.b16 {%0,%1,%2,%3}, [%4];"
                 : "=r"(r0), "=r"(r1), "=r"(r2), "=r"(r3) : "r"(addr));
}
__device__ __forceinline__ void mma16816(float* c, const uint32_t* a, const uint32_t* b) {
    asm volatile(
        "mma.sync.aligned.m16n8k16.row.col.f32.bf16.bf16.f32 "
        "{%0,%1,%2,%3}, {%4,%5,%6,%7}, {%8,%9}, {%0,%1,%2,%3};"
        : "+f"(c[0]), "+f"(c[1]), "+f"(c[2]), "+f"(c[3])
        : "r"(a[0]), "r"(a[1]), "r"(a[2]), "r"(a[3]), "r"(b[0]), "r"(b[1]));
}
__device__ __forceinline__ void mma16816h(float* c, const uint32_t* a, const uint32_t* b) {
    asm volatile(
        "mma.sync.aligned.m16n8k16.row.col.f32.f16.f16.f32 "
        "{%0,%1,%2,%3}, {%4,%5,%6,%7}, {%8,%9}, {%0,%1,%2,%3};"
        : "+f"(c[0]), "+f"(c[1]), "+f"(c[2]), "+f"(c[3])
        : "r"(a[0]), "r"(a[1]), "r"(a[2]), "r"(a[3]), "r"(b[0]), "r"(b[1]));
}
__device__ __forceinline__ uint32_t pkbf(float lo, float hi) {
    uint32_t r;
    asm("cvt.rn.bf16x2.f32 %0, %1, %2;" : "=r"(r) : "f"(hi), "f"(lo));
    return r;
}
__device__ __forceinline__ uint32_t pkhf(float lo, float hi) {
    uint32_t r;
    asm("cvt.rn.f16x2.f32 %0, %1, %2;" : "=r"(r) : "f"(hi), "f"(lo));
    return r;
}

// ---------------------------------------------------------------------------
// convert: fp32 -> fp16 (hi only)
// ---------------------------------------------------------------------------
__global__ __launch_bounds__(256) void conv_fp16(
    const float* __restrict__ A, __half* __restrict__ Ah)
{
    int i = blockIdx.x * 256 + threadIdx.x;
    float4 a = ((const float4*)A)[i];
    ((uint2*)Ah)[i] = make_uint2(pkhf(a.x, a.y), pkhf(a.z, a.w));
}

// ---------------------------------------------------------------------------
// transpose: W[K=1024][Nd] -> Th[Nd][1024] (fp16 hi only)
// ---------------------------------------------------------------------------
__global__ void transpose_h(const float* __restrict__ W,
                            __half* __restrict__ Th, int Nd)
{
    __shared__ float tile[32][33];
    int nx = blockIdx.x * 32, kx = blockIdx.y * 32;
    int tx = threadIdx.x, ty = threadIdx.y;
#pragma unroll
    for (int r = ty; r < 32; r += 8)
        tile[r][tx] = W[(size_t)(kx + r) * Nd + nx + tx];
    __syncthreads();
#pragma unroll
    for (int r = ty; r < 32; r += 8) {
        size_t o = (size_t)(nx + r) * 1024 + kx + tx;
        Th[o] = __float2half_rn(tile[tx][r]);
    }
}

// ---------------------------------------------------------------------------
// fp16 single-term mma.sync GEMM: CTA 128x128, warp tile 64x32 (2x4 warps),
// BK=64, cp.async double buffer, 64 KB smem. D = Ah @ Bh^T.
// MODE 0: out+bias. MODE 1: QKV scatter (Q fp16 hi, K fp16 hi, V fp32).
// ---------------------------------------------------------------------------
#define G_BHI 16384
#define G_STG 32768
#define TCG_SMEM (2*G_STG)   // 64 KB

__device__ __forceinline__ void load_stage(
    uint32_t sbase,
    const __half* __restrict__ Ah, const __half* __restrict__ Bh,
    int m0, int n0, int k0, int tid)
{
#pragma unroll
    for (int j = 0; j < 4; j++) {          // A: 128 rows x 8 chunks
        int idx = tid + j * 256;
        int row = idx >> 3, c = idx & 7;
        uint32_t sw = row * 128 + ((c ^ (row & 7)) << 4);
        size_t ga = (size_t)(m0 + row) * 1024 + k0 + c * 8;
        cp16(sbase + sw, Ah + ga);
    }
#pragma unroll
    for (int j = 0; j < 4; j++) {          // B: 128 rows x 8 chunks
        int idx = tid + j * 256;
        int row = idx >> 3, c = idx & 7;
        uint32_t sw = row * 128 + ((c ^ (row & 7)) << 4);
        size_t gb = (size_t)(n0 + row) * 1024 + k0 + c * 8;
        cp16(sbase + G_BHI + sw, Bh + gb);
    }
}

template<int MODE>
__global__ __launch_bounds__(256, 2) void tc_gemm(
    const __half* __restrict__ Ah, const __half* __restrict__ Bh,
    const float* __restrict__ bias, float* __restrict__ Cout)
{
    extern __shared__ char smem[];
    uint32_t sb = smem_u32(smem);
    const int tid  = threadIdx.x;
    const int wid  = tid >> 5;
    const int lane = tid & 31;
    const int wm = wid & 1;        // 2 warp-rows of 64
    const int wn = wid >> 1;       // 4 warp-cols of 32
    const int m0 = blockIdx.y * 128;
    const int n0 = blockIdx.x * 128;

    float acc[4][4][4];
#pragma unroll
    for (int i = 0; i < 4; i++)
#pragma unroll
        for (int j = 0; j < 4; j++)
#pragma unroll
            for (int q = 0; q < 4; q++) acc[i][j][q] = 0.0f;

    load_stage(sb,         Ah, Bh, m0, n0, 0,  tid); CP_COMMIT();
    load_stage(sb + G_STG, Ah, Bh, m0, n0, 64, tid); CP_COMMIT();

    const int a_row = wm * 64 + (lane & 15);
    const int a_c16 = (lane >> 4);
    const int b_row = wn * 32 + ((lane >> 4) << 3) + (lane & 7);
    const int b_cof = ((lane >> 3) & 1);

    for (int it = 0; it < 16; it++) {
        const int s = it & 1;
        const uint32_t sbase = sb + s * G_STG;
        if (it < 15) asm volatile("cp.async.wait_group 1;\n" ::: "memory");
        else         asm volatile("cp.async.wait_group 0;\n" ::: "memory");
        __syncthreads();

#pragma unroll
        for (int ks = 0; ks < 4; ks++) {
            uint32_t ahi[4][4];
#pragma unroll
            for (int mf = 0; mf < 4; mf++) {
                int row = a_row + mf * 16;
                int c16 = ks * 2 + a_c16;
                uint32_t ad = sbase + row * 128 + ((c16 ^ (row & 7)) << 4);
                ldsm4(ahi[mf][0], ahi[mf][1], ahi[mf][2], ahi[mf][3], ad);
            }
#pragma unroll
            for (int nf2 = 0; nf2 < 2; nf2++) {
                int row = b_row + nf2 * 16;
                int c16 = ks * 2 + b_cof;
                uint32_t bd = sbase + G_BHI + row * 128 + ((c16 ^ (row & 7)) << 4);
                uint32_t bh4[4];
                ldsm4(bh4[0], bh4[1], bh4[2], bh4[3], bd);
#pragma unroll
                for (int mf = 0; mf < 4; mf++) {
                    mma16816h(acc[mf][2*nf2],   ahi[mf], bh4);
                    mma16816h(acc[mf][2*nf2+1], ahi[mf], bh4 + 2);
                }
            }
        }
        __syncthreads();
        if (it + 2 < 16) {
            load_stage(sbase, Ah, Bh, m0, n0, (it + 2) * 64, tid);
            CP_COMMIT();
        }
    }

    const int mbase = m0 + wm * 64 + (lane >> 2);
    const int nbase = n0 + wn * 32 + (lane & 3) * 2;
#pragma unroll
    for (int mf = 0; mf < 4; mf++) {
#pragma unroll
        for (int half = 0; half < 2; half++) {
            int m = mbase + mf * 16 + half * 8;
#pragma unroll
            for (int nf = 0; nf < 4; nf++) {
                int n = nbase + nf * 8;
                float v0 = acc[mf][nf][half*2+0] + bias[n];
                float v1 = acc[mf][nf][half*2+1] + bias[n+1];
                if (MODE == 0) {
                    *(float2*)(Cout + (size_t)m * Cn + n) = make_float2(v0, v1);
                } else {
                    int sec = n >> 10;
                    int c1  = n & 1023;
                    int h   = c1 >> 6, dd = c1 & 63;
                    int bq  = m >> 11, t = m & 2047;
                    size_t idx = ((size_t)((bq * Hn + h) * Tn + t)) * 64 + dd;
                    if (sec == 2) {
                        *(float2*)(g_V + idx) = make_float2(v0, v1);
                    } else if (sec == 1) {
                        *(uint32_t*)(g_Kh + idx) = pkhf(v0, v1);
                    } else {
                        *(uint32_t*)(g_Qh + idx) = pkhf(v0 * 0.125f, v1 * 0.125f);
                    }
                }
            }
        }
    }
}

// ---------------------------------------------------------------------------
// z_max partial + reduce (MUFU fast math; formula must match vexp exactly)
// ---------------------------------------------------------------------------
__global__ __launch_bounds__(256) void zmax_part(const float* __restrict__ p_param)
{
    int bh = blockIdx.x, chunk = blockIdx.y;
    int b = bh >> 4, h = bh & 15;
    int d4 = threadIdx.x & 15;
    int g  = threadIdx.x >> 4;
    int c  = h*64 + d4*4;
    float4 pv;
    pv.x = clamp_p(p_param[c+0]); pv.y = clamp_p(p_param[c+1]);
    pv.z = clamp_p(p_param[c+2]); pv.w = clamp_p(p_param[c+3]);

    const float* vp = g_V + (size_t)bh * Tn * 64;
    float4 mx = make_float4(-1e30f, -1e30f, -1e30f, -1e30f);
    for (int t = chunk*128 + g; t < (chunk+1)*128; t += 16) {
        float4 v = *(const float4*)(vp + t*64 + d4*4);
        mx.x = fmaxf(mx.x, pv.x * __logf(fmaxf(fabsf(v.x + 5.0f), 1e-10f)));
        mx.y = fmaxf(mx.y, pv.y * __logf(fmaxf(fabsf(v.y + 5.0f), 1e-10f)));
        mx.z = fmaxf(mx.z, pv.z * __logf(fmaxf(fabsf(v.z + 5.0f), 1e-10f)));
        mx.w = fmaxf(mx.w, pv.w * __logf(fmaxf(fabsf(v.w + 5.0f), 1e-10f)));
    }
    __shared__ float4 red[256];
    red[threadIdx.x] = mx;
    __syncthreads();
    if (threadIdx.x < 16) {
        float4 m = red[threadIdx.x];
#pragma unroll
        for (int gg = 1; gg < 16; gg++) {
            float4 o = red[gg*16 + threadIdx.x];
            m.x = fmaxf(m.x, o.x); m.y = fmaxf(m.y, o.y);
            m.z = fmaxf(m.z, o.z); m.w = fmaxf(m.w, o.w);
        }
        *(float4*)(g_zpart + chunk*(Bn*Cn) + b*Cn + h*64 + threadIdx.x*4) = m;
    }
}
__global__ __launch_bounds__(256) void zmax_reduce()
{
    int i = blockIdx.x * 256 + threadIdx.x;
    float mx = -1e30f;
#pragma unroll
    for (int ch = 0; ch < 16; ch++) mx = fmaxf(mx, g_zpart[ch*(Bn*Cn) + i]);
    g_zmax[i] = mx;
}

// ---------------------------------------------------------------------------
// V transform -> bf16 hi/lo (float4 per thread, MUFU fast math)
// ---------------------------------------------------------------------------
__global__ __launch_bounds__(256) void vexp_kernel(const float* __restrict__ p_param)
{
    int i = blockIdx.x * 256 + threadIdx.x;
    int base = i * 4;
    int dd = base & 63;
    int bh = base >> 17;
    int h = bh & 15, b = bh >> 4;
    int c = h*64 + dd;
    float4 v = *(const float4*)(g_V + base);
    float e[4];
    const float vs[4] = {v.x, v.y, v.z, v.w};
#pragma unroll
    for (int j = 0; j < 4; j++) {
        float pvj = clamp_p(p_param[c + j]);
        float z = pvj * __logf(fmaxf(fabsf(vs[j] + 5.0f), 1e-10f)) - g_zmax[b*Cn + c + j];
        e[j] = __expf(z);
    }
    uint32_t h0 = pkbf(e[0], e[1]), h1 = pkbf(e[2], e[3]);
    float f0 = __uint_as_float(h0 << 16), f1 = __uint_as_float(h0 & 0xffff0000u);
    float f2 = __uint_as_float(h1 << 16), f3 = __uint_as_float(h1 & 0xffff0000u);
    uint32_t l0 = pkbf(e[0]-f0, e[1]-f1), l1 = pkbf(e[2]-f2, e[3]-f3);
    ((uint2*)g_Vh)[i] = make_uint2(h0, h1);
    ((uint2*)g_Vl)[i] = make_uint2(l0, l1);
}

// ---------------------------------------------------------------------------
// Tensor-core flash attention (causal), BQ=BK=64, 4 warps, 56 KB smem.
// S = fp16 1-term Qh·Kh; P·V bf16 3-term. MUFU fast math in epilogue.
// ---------------------------------------------------------------------------
#define FAQ_H 0
#define FASTG0 8192
#define FASTG_SZ 24576
#define FKH 0
#define FVH 8192
#define FVL 16384
#define FA_SMEM (8192 + 2*FASTG_SZ)   // 56 KB

__device__ __forceinline__ void fa_load_stage(uint32_t sbase, int bh, int kt, int tid)
{
    const char* srcs[3] = {(const char*)g_Kh, (const char*)g_Vh, (const char*)g_Vl};
#pragma unroll
    for (int j = 0; j < 12; j++) {
        int idx = tid + j * 128;          // 0..1535 16B-chunks
        int arr = idx >> 9;               // 0..2
        int rem = idx & 511;
        int row = rem >> 3, c = rem & 7;
        uint32_t sw = arr * 8192 + row * 128 + ((c ^ (row & 7)) << 4);
        size_t gb = (((size_t)bh * Tn + kt * 64 + row) * 64 + c * 8) * 2;
        cp16(sbase + sw, srcs[arr] + gb);
    }
}

__global__ __launch_bounds__(128) void fa_kernel(const float* __restrict__ p_param)
{
    extern __shared__ char smem[];
    uint32_t sb = smem_u32(smem);
    const int tid  = threadIdx.x;
    const int w    = tid >> 5;
    const int lane = tid & 31;
    const int quad = lane >> 2;
    const int idq  = lane & 3;
    const int bh = blockIdx.y;
    const int b = bh >> 4, h = bh & 15;
    const int qt = (int)gridDim.x - 1 - (int)blockIdx.x;   // heavy first
    const int q0 = qt * 64;

    // ---- prologue: Q tile (fp16 hi) + first stages ----
    {
#pragma unroll
        for (int j = 0; j < 4; j++) {
            int idx = tid + j * 128;      // 0..511 chunks (64 rows x 8)
            int row = idx >> 3, c = idx & 7;
            uint32_t sw = row * 128 + ((c ^ (row & 7)) << 4);
            size_t gb = (((size_t)bh * Tn + q0 + row) * 64 + c * 8) * 2;
            cp16(sb + FAQ_H + sw, (const char*)g_Qh + gb);
        }
        fa_load_stage(sb + FASTG0, bh, 0, tid);
        CP_COMMIT();
        if (qt >= 1) fa_load_stage(sb + FASTG0 + FASTG_SZ, bh, 1, tid);
        CP_COMMIT();
    }

    uint32_t Qh[4][4];
    float Of[8][4];
    float m0 = -1e30f, m1 = -1e30f, l0 = 0.0f, l1 = 0.0f;
#pragma unroll
    for (int nf = 0; nf < 8; nf++)
#pragma unroll
        for (int q = 0; q < 4; q++) Of[nf][q] = 0.0f;

    const int k_row = ((lane >> 4) << 3) + (lane & 7);   // + nf2*16
    const int k_cof = ((lane >> 3) & 1);                 // + ks*2
    const int v_row = (lane & 15);                       // + kf*16
    const int v_cof = (lane >> 4);                       // + nf2*2

    for (int kt = 0; kt <= qt; kt++) {
        const uint32_t sbase = sb + FASTG0 + (kt & 1) * FASTG_SZ;
        if (kt < qt) asm volatile("cp.async.wait_group 1;\n" ::: "memory");
        else         asm volatile("cp.async.wait_group 0;\n" ::: "memory");
        __syncthreads();

        if (kt == 0) {
            int row = w * 16 + (lane & 15);
#pragma unroll
            for (int ks = 0; ks < 4; ks++) {
                int c16 = ks * 2 + (lane >> 4);
                uint32_t sw = row * 128 + ((c16 ^ (row & 7)) << 4);
                ldsm4(Qh[ks][0], Qh[ks][1], Qh[ks][2], Qh[ks][3], sb + FAQ_H + sw);
            }
        }

        // ---- S = Qh Kh^T  (fp16, 1 term) ----
        float Sf[8][4];
#pragma unroll
        for (int nf = 0; nf < 8; nf++)
#pragma unroll
            for (int q = 0; q < 4; q++) Sf[nf][q] = 0.0f;

#pragma unroll
        for (int nf2 = 0; nf2 < 4; nf2++) {
            int krow = nf2 * 16 + k_row;
#pragma unroll
            for (int ks = 0; ks < 4; ks++) {
                int c16 = ks * 2 + k_cof;
                uint32_t sw = krow * 128 + ((c16 ^ (krow & 7)) << 4);
                uint32_t kh[4];
                ldsm4(kh[0], kh[1], kh[2], kh[3], sbase + FKH + sw);
                mma16816h(Sf[2*nf2],   Qh[ks], kh);
                mma16816h(Sf[2*nf2+1], Qh[ks], kh + 2);
            }
        }

        // ---- causal mask on diagonal tile ----
        if (kt == qt) {
            int r0 = w * 16 + quad, r1 = r0 + 8;
#pragma unroll
            for (int nf = 0; nf < 8; nf++) {
                int c0 = nf * 8 + idq * 2;
                if (c0     > r0) Sf[nf][0] = -1e30f;
                if (c0 + 1 > r0) Sf[nf][1] = -1e30f;
                if (c0     > r1) Sf[nf][2] = -1e30f;
                if (c0 + 1 > r1) Sf[nf][3] = -1e30f;
            }
        }

        // ---- softmax (register, 2 rows/thread, quad shuffles) ----
        float mx0 = -1e30f, mx1 = -1e30f;
#pragma unroll
        for (int nf = 0; nf < 8; nf++) {
            mx0 = fmaxf(mx0, fmaxf(Sf[nf][0], Sf[nf][1]));
            mx1 = fmaxf(mx1, fmaxf(Sf[nf][2], Sf[nf][3]));
        }
#pragma unroll
        for (int off = 1; off < 4; off <<= 1) {
            mx0 = fmaxf(mx0, __shfl_xor_sync(0xffffffffu, mx0, off));
            mx1 = fmaxf(mx1, __shfl_xor_sync(0xffffffffu, mx1, off));
        }
        mx0 = fmaxf(mx0, m0);
        mx1 = fmaxf(mx1, m1);
        float a0 = __expf(m0 - mx0), a1 = __expf(m1 - mx1);
        m0 = mx0; m1 = mx1;

        float s0 = 0.0f, s1 = 0.0f;
#pragma unroll
        for (int nf = 0; nf < 8; nf++) {
            Sf[nf][0] = __expf(Sf[nf][0] - mx0);
            Sf[nf][1] = __expf(Sf[nf][1] - mx0);
            Sf[nf][2] = __expf(Sf[nf][2] - mx1);
            Sf[nf][3] = __expf(Sf[nf][3] - mx1);
            s0 += Sf[nf][0] + Sf[nf][1];
            s1 += Sf[nf][2] + Sf[nf][3];
        }
#pragma unroll
        for (int off = 1; off < 4; off <<= 1) {
            s0 += __shfl_xor_sync(0xffffffffu, s0, off);
            s1 += __shfl_xor_sync(0xffffffffu, s1, off);
        }
        l0 = l0 * a0 + s0;
        l1 = l1 * a1 + s1;

#pragma unroll
        for (int nf = 0; nf < 8; nf++) {
            Of[nf][0] *= a0; Of[nf][1] *= a0;
            Of[nf][2] *= a1; Of[nf][3] *= a1;
        }

        // ---- O += P V (P from S frags, bf16x3, ldsm4t V) ----
#pragma unroll
        for (int kf = 0; kf < 4; kf++) {
            uint32_t pha[4], pla[4];
#pragma unroll
            for (int half = 0; half < 2; half++) {
                float* sp = Sf[2*kf + half];
                uint32_t u0 = pkbf(sp[0], sp[1]);
                uint32_t u1 = pkbf(sp[2], sp[3]);
                float f00 = __uint_as_float(u0 << 16), f01 = __uint_as_float(u0 & 0xffff0000u);
                float f10 = __uint_as_float(u1 << 16), f11 = __uint_as_float(u1 & 0xffff0000u);
                pha[half*2+0] = u0;
                pha[half*2+1] = u1;
                pla[half*2+0] = pkbf(sp[0] - f00, sp[1] - f01);
                pla[half*2+1] = pkbf(sp[2] - f10, sp[3] - f11);
            }
            int vrow = kf * 16 + v_row;
#pragma unroll
            for (int nf2 = 0; nf2 < 4; nf2++) {
                int c16 = nf2 * 2 + v_cof;
                uint32_t sw = vrow * 128 + ((c16 ^ (vrow & 7)) << 4);
                uint32_t vh[4], vl[4];
                ldsm4t(vh[0], vh[1], vh[2], vh[3], sbase + FVH + sw);
                ldsm4t(vl[0], vl[1], vl[2], vl[3], sbase + FVL + sw);
                mma16816(Of[2*nf2],   pha, vh);
                mma16816(Of[2*nf2],   pla, vh);
                mma16816(Of[2*nf2],   pha, vl);
                mma16816(Of[2*nf2+1], pha, vh + 2);
                mma16816(Of[2*nf2+1], pla, vh + 2);
                mma16816(Of[2*nf2+1], pha, vl + 2);
            }
        }

        __syncthreads();
        if (kt + 2 <= qt) {
            fa_load_stage(sbase, bh, kt + 2, tid);
            CP_COMMIT();
        }
    }

    // ---- epilogue: y = exp((zmax + log(O/l))/p) - 5, write fp16 hi ----
    const int t0 = q0 + w * 16 + quad;
    const int t1 = t0 + 8;
    float linv0 = 1.0f / l0, linv1 = 1.0f / l1;
#pragma unroll
    for (int nf = 0; nf < 8; nf++) {
        int d0 = nf * 8 + idq * 2;
        int cg = h * 64 + d0;
        float pv0 = clamp_p(p_param[cg]);
        float pv1 = clamp_p(p_param[cg + 1]);
        float zm0 = g_zmax[b*Cn + cg];
        float zm1 = g_zmax[b*Cn + cg + 1];
        float y00 = __expf((zm0 + __logf(Of[nf][0] * linv0)) / pv0) - 5.0f;
        float y01 = __expf((zm1 + __logf(Of[nf][1] * linv0)) / pv1) - 5.0f;
        float y10 = __expf((zm0 + __logf(Of[nf][2] * linv1)) / pv0) - 5.0f;
        float y11 = __expf((zm1 + __logf(Of[nf][3] * linv1)) / pv1) - 5.0f;
        size_t i0 = ((size_t)(b*Tn + t0)*Cn + cg) >> 1;
        size_t i1 = ((size_t)(b*Tn + t1)*Cn + cg) >> 1;
        ((uint32_t*)gA_hi)[i0] = pkhf(y00, y01);
        ((uint32_t*)gA_hi)[i1] = pkhf(y10, y11);
    }
}

// ---------------------------------------------------------------------------

extern "C" void kernel_launch(void* const* d_in, const int* in_sizes, int n_in,
                              void* d_out, int out_size)
{
    const float* x       = (const float*)d_in[0];
    const float* w_attn  = (const float*)d_in[1];
    const float* b_attn  = (const float*)d_in[2];
    const float* w_proj  = (const float*)d_in[3];
    const float* b_proj  = (const float*)d_in[4];
    const float* p_param = (const float*)d_in[5];
    float* out = (float*)d_out;

    void *ah, *bth;
    cudaGetSymbolAddress(&ah,  gA_hi);
    cudaGetSymbolAddress(&bth, gBT_hi);

    cudaFuncSetAttribute(fa_kernel, cudaFuncAttributeMaxDynamicSharedMemorySize, FA_SMEM);
    cudaFuncSetAttribute(tc_gemm<0>, cudaFuncAttributeMaxDynamicSharedMemorySize, TCG_SMEM);
    cudaFuncSetAttribute(tc_gemm<1>, cudaFuncAttributeMaxDynamicSharedMemorySize, TCG_SMEM);

    // 1) convert x -> fp16; transpose w_attn (fp16 hi)
    conv_fp16<<<Mn*Cn/1024, 256>>>(x, (__half*)ah);
    transpose_h<<<dim3(3072/32, Cn/32), dim3(32,8)>>>(w_attn, (__half*)bth, 3072);

    // 2) QKV GEMM (fp16 single-term) + head-major scatter (Q/K fp16 hi, V fp32)
    tc_gemm<1><<<dim3(3072/128, Mn/128), 256, TCG_SMEM>>>(
        (const __half*)ah, (const __half*)bth, b_attn, nullptr);

    // 3) z_max (partial + reduce) + V transform -> bf16 hi/lo
    zmax_part<<<dim3(BHn, 16), 256>>>(p_param);
    zmax_reduce<<<(Bn*Cn)/256, 256>>>();
    vexp_kernel<<<(BHn*Tn*Dn)/1024, 256>>>(p_param);

    // 4) tensor-core causal FA (fp16 1-term QK, bf16x3 PV); Y -> gA fp16 hi
    fa_kernel<<<dim3(Tn/64, BHn), 128, FA_SMEM>>>(p_param);

    // 5) transpose w_proj (fp16 hi); proj GEMM (fp16 single-term)
    transpose_h<<<dim3(Cn/32, Cn/32), dim3(32,8)>>>(w_proj, (__half*)bth, Cn);
    tc_gemm<0><<<dim3(Cn/128, Mn/128), 256, TCG_SMEM>>>(
        (const __half*)ah, (const __half*)bth, b_proj, out);
}

// round 13
// speedup vs baseline: 7.0732x; 1.0181x over previous
#include <cuda_runtime.h>
#include <cuda_bf16.h>
#include <cuda_fp16.h>
#include <math.h>
#include <stdint.h>

#define Bn 2
#define Tn 2048
#define Cn 1024
#define Hn 16
#define Dn 64
#define Mn (Bn*Tn)          // 4096
#define BHn (Bn*Hn)         // 32

typedef unsigned long long ull;

// ---------------- device scratch ----------------
__device__ __half         g_Qh[BHn*Tn*Dn];  // head-major, pre-scaled by 0.125 (fp16 hi only)
__device__ __half         g_Kh[BHn*Tn*Dn];  // fp16 hi only
__device__ float          g_V [BHn*Tn*Dn];  // raw v (fp32) for zmax
__device__ __nv_bfloat16  g_Vh[BHn*Tn*Dn];  // transformed V bf16 hi/lo
__device__ __nv_bfloat16  g_Vl[BHn*Tn*Dn];
__device__ float g_zmax[Bn*Cn];
__device__ float g_E   [Bn*Cn];             // exp(zmax)
__device__ float g_Einv[Bn*Cn];             // exp(-zmax)
__device__ float g_zpmax[16*Bn*Cn];         // partial wmax
__device__ float g_zpmin[16*Bn*Cn];         // partial wmin
__device__ __half gA_hi[Mn*Cn];             // fp16 A operand (x conv, then Y from FA)
__device__ __half gBT_hi[3*Cn*Cn];          // fp16 w_attn^T
__device__ __half gBT2  [Cn*Cn];            // fp16 w_proj^T

__device__ __forceinline__ float clamp_p(float pp) {
    float sgn = (pp >= 0.0f) ? 1.0f : -1.0f;
    return sgn * fminf(fmaxf(fabsf(pp), 1e-4f), 1e3f);
}

// ---------------- ptx helpers ----------------
__device__ __forceinline__ uint32_t smem_u32(const void* p) {
    uint32_t a;
    asm("{ .reg .u64 t; cvta.to.shared.u64 t, %1; cvt.u32.u64 %0, t; }" : "=r"(a) : "l"(p));
    return a;
}
__device__ __forceinline__ void cp16(uint32_t dst, const void* src) {
    asm volatile("cp.async.cg.shared.global [%0], [%1], 16;\n" :: "r"(dst), "l"(src));
}
#define CP_COMMIT() asm volatile("cp.async.commit_group;\n" ::: "memory")

__device__ __forceinline__ void ldsm4(uint32_t& r0, uint32_t& r1, uint32_t& r2, uint32_t& r3,
                                      uint32_t addr) {
    asm volatile("ldmatrix.sync.aligned.m8n8.x4.shared.b16 {%0,%1,%2,%3}, [%4];"
                 : "=r"(r0), "=r"(r1), "=r"(r2), "=r"(r3) : "r"(addr));
}
__device__ __forceinline__ void ldsm4t(uint32_t& r0, uint32_t& r1, uint32_t& r2, uint32_t& r3,
                                       uint32_t addr) {
    asm volatile("ldmatrix.sync.aligned.m8n8.x4.trans.shared.b16 {%0,%1,%2,%3}, [%4];"
                 : "=r"(r0), "=r"(r1), "=r"(r2), "=r"(r3) : "r"(addr));
}
__device__ __forceinline__ void mma16816(float* c, const uint32_t* a, const uint32_t* b) {
    asm volatile(
        "mma.sync.aligned.m16n8k16.row.col.f32.bf16.bf16.f32 "
        "{%0,%1,%2,%3}, {%4,%5,%6,%7}, {%8,%9}, {%0,%1,%2,%3};"
        : "+f"(c[0]), "+f"(c[1]), "+f"(c[2]), "+f"(c[3])
        : "r"(a[0]), "r"(a[1]), "r"(a[2]), "r"(a[3]), "r"(b[0]), "r"(b[1]));
}
__device__ __forceinline__ void mma16816h(float* c, const uint32_t* a, const uint32_t* b) {
    asm volatile(
        "mma.sync.aligned.m16n8k16.row.col.f32.f16.f16.f32 "
        "{%0,%1,%2,%3}, {%4,%5,%6,%7}, {%8,%9}, {%0,%1,%2,%3};"
        : "+f"(c[0]), "+f"(c[1]), "+f"(c[2]), "+f"(c[3])
        : "r"(a[0]), "r"(a[1]), "r"(a[2]), "r"(a[3]), "r"(b[0]), "r"(b[1]));
}
__device__ __forceinline__ uint32_t pkbf(float lo, float hi) {
    uint32_t r;
    asm("cvt.rn.bf16x2.f32 %0, %1, %2;" : "=r"(r) : "f"(hi), "f"(lo));
    return r;
}
__device__ __forceinline__ uint32_t pkhf(float lo, float hi) {
    uint32_t r;
    asm("cvt.rn.f16x2.f32 %0, %1, %2;" : "=r"(r) : "f"(hi), "f"(lo));
    return r;
}

// ---------------------------------------------------------------------------
// mega prep: [0,4096) conv x->fp16; [4096,7168) transpose w_attn;
// [7168,8192) transpose w_proj.
// ---------------------------------------------------------------------------
__global__ __launch_bounds__(256) void prep_kernel(
    const float* __restrict__ x,
    const float* __restrict__ w_attn,
    const float* __restrict__ w_proj)
{
    __shared__ float tile[32][33];
    int bid = blockIdx.x;
    int tid = threadIdx.x;
    if (bid < 4096) {
        int i = bid * 256 + tid;
        float4 a = ((const float4*)x)[i];
        ((uint2*)gA_hi)[i] = make_uint2(pkhf(a.x, a.y), pkhf(a.z, a.w));
        return;
    }
    const float* W;
    __half* Th;
    int Nd, bx, by;
    if (bid < 7168) {
        int t = bid - 4096;
        W = w_attn; Th = gBT_hi; Nd = 3072;
        bx = t % 96; by = t / 96;
    } else {
        int t = bid - 7168;
        W = w_proj; Th = gBT2; Nd = 1024;
        bx = t % 32; by = t / 32;
    }
    int nx = bx * 32, kx = by * 32;
    int tx = tid & 31, ty = tid >> 5;   // 32x8
#pragma unroll
    for (int r = ty; r < 32; r += 8)
        tile[r][tx] = W[(size_t)(kx + r) * Nd + nx + tx];
    __syncthreads();
#pragma unroll
    for (int r = ty; r < 32; r += 8) {
        size_t o = (size_t)(nx + r) * 1024 + kx + tx;
        Th[o] = __float2half_rn(tile[tx][r]);
    }
}

// ---------------------------------------------------------------------------
// fp16 single-term mma.sync GEMM: CTA 128x128, warp tile 64x32 (2x4 warps),
// BK=64, cp.async double buffer, 64 KB smem. D = Ah @ Bh^T.
// MODE 0: out+bias. MODE 1: QKV scatter (Q fp16 hi, K fp16 hi, V fp32).
// ---------------------------------------------------------------------------
#define G_BHI 16384
#define G_STG 32768
#define TCG_SMEM (2*G_STG)   // 64 KB

__device__ __forceinline__ void load_stage(
    uint32_t sbase,
    const __half* __restrict__ Ah, const __half* __restrict__ Bh,
    int m0, int n0, int k0, int tid)
{
#pragma unroll
    for (int j = 0; j < 4; j++) {          // A: 128 rows x 8 chunks
        int idx = tid + j * 256;
        int row = idx >> 3, c = idx & 7;
        uint32_t sw = row * 128 + ((c ^ (row & 7)) << 4);
        size_t ga = (size_t)(m0 + row) * 1024 + k0 + c * 8;
        cp16(sbase + sw, Ah + ga);
    }
#pragma unroll
    for (int j = 0; j < 4; j++) {          // B: 128 rows x 8 chunks
        int idx = tid + j * 256;
        int row = idx >> 3, c = idx & 7;
        uint32_t sw = row * 128 + ((c ^ (row & 7)) << 4);
        size_t gb = (size_t)(n0 + row) * 1024 + k0 + c * 8;
        cp16(sbase + G_BHI + sw, Bh + gb);
    }
}

template<int MODE>
__global__ __launch_bounds__(256, 2) void tc_gemm(
    const __half* __restrict__ Ah, const __half* __restrict__ Bh,
    const float* __restrict__ bias, float* __restrict__ Cout)
{
    extern __shared__ char smem[];
    uint32_t sb = smem_u32(smem);
    const int tid  = threadIdx.x;
    const int wid  = tid >> 5;
    const int lane = tid & 31;
    const int wm = wid & 1;        // 2 warp-rows of 64
    const int wn = wid >> 1;       // 4 warp-cols of 32
    const int m0 = blockIdx.y * 128;
    const int n0 = blockIdx.x * 128;

    float acc[4][4][4];
#pragma unroll
    for (int i = 0; i < 4; i++)
#pragma unroll
        for (int j = 0; j < 4; j++)
#pragma unroll
            for (int q = 0; q < 4; q++) acc[i][j][q] = 0.0f;

    load_stage(sb,         Ah, Bh, m0, n0, 0,  tid); CP_COMMIT();
    load_stage(sb + G_STG, Ah, Bh, m0, n0, 64, tid); CP_COMMIT();

    const int a_row = wm * 64 + (lane & 15);
    const int a_c16 = (lane >> 4);
    const int b_row = wn * 32 + ((lane >> 4) << 3) + (lane & 7);
    const int b_cof = ((lane >> 3) & 1);

    for (int it = 0; it < 16; it++) {
        const int s = it & 1;
        const uint32_t sbase = sb + s * G_STG;
        if (it < 15) asm volatile("cp.async.wait_group 1;\n" ::: "memory");
        else         asm volatile("cp.async.wait_group 0;\n" ::: "memory");
        __syncthreads();

#pragma unroll
        for (int ks = 0; ks < 4; ks++) {
            uint32_t ahi[4][4];
#pragma unroll
            for (int mf = 0; mf < 4; mf++) {
                int row = a_row + mf * 16;
                int c16 = ks * 2 + a_c16;
                uint32_t ad = sbase + row * 128 + ((c16 ^ (row & 7)) << 4);
                ldsm4(ahi[mf][0], ahi[mf][1], ahi[mf][2], ahi[mf][3], ad);
            }
#pragma unroll
            for (int nf2 = 0; nf2 < 2; nf2++) {
                int row = b_row + nf2 * 16;
                int c16 = ks * 2 + b_cof;
                uint32_t bd = sbase + G_BHI + row * 128 + ((c16 ^ (row & 7)) << 4);
                uint32_t bh4[4];
                ldsm4(bh4[0], bh4[1], bh4[2], bh4[3], bd);
#pragma unroll
                for (int mf = 0; mf < 4; mf++) {
                    mma16816h(acc[mf][2*nf2],   ahi[mf], bh4);
                    mma16816h(acc[mf][2*nf2+1], ahi[mf], bh4 + 2);
                }
            }
        }
        __syncthreads();
        if (it + 2 < 16) {
            load_stage(sbase, Ah, Bh, m0, n0, (it + 2) * 64, tid);
            CP_COMMIT();
        }
    }

    const int mbase = m0 + wm * 64 + (lane >> 2);
    const int nbase = n0 + wn * 32 + (lane & 3) * 2;
#pragma unroll
    for (int mf = 0; mf < 4; mf++) {
#pragma unroll
        for (int half = 0; half < 2; half++) {
            int m = mbase + mf * 16 + half * 8;
#pragma unroll
            for (int nf = 0; nf < 4; nf++) {
                int n = nbase + nf * 8;
                float v0 = acc[mf][nf][half*2+0] + bias[n];
                float v1 = acc[mf][nf][half*2+1] + bias[n+1];
                if (MODE == 0) {
                    *(float2*)(Cout + (size_t)m * Cn + n) = make_float2(v0, v1);
                } else {
                    int sec = n >> 10;
                    int c1  = n & 1023;
                    int h   = c1 >> 6, dd = c1 & 63;
                    int bq  = m >> 11, t = m & 2047;
                    size_t idx = ((size_t)((bq * Hn + h) * Tn + t)) * 64 + dd;
                    if (sec == 2) {
                        *(float2*)(g_V + idx) = make_float2(v0, v1);
                    } else if (sec == 1) {
                        *(uint32_t*)(g_Kh + idx) = pkhf(v0, v1);
                    } else {
                        *(uint32_t*)(g_Qh + idx) = pkhf(v0 * 0.125f, v1 * 0.125f);
                    }
                }
            }
        }
    }
}

// ---------------------------------------------------------------------------
// w-range partial: track wmax/wmin of w = clip(|v+5|) -- no transcendentals
// ---------------------------------------------------------------------------
__global__ __launch_bounds__(256) void zmax_part(void)
{
    int bh = blockIdx.x, chunk = blockIdx.y;
    int b = bh >> 4, h = bh & 15;
    int d4 = threadIdx.x & 15;
    int g  = threadIdx.x >> 4;

    const float* vp = g_V + (size_t)bh * Tn * 64;
    float4 mx = make_float4(-1e30f, -1e30f, -1e30f, -1e30f);
    float4 mn = make_float4( 1e30f,  1e30f,  1e30f,  1e30f);
    for (int t = chunk*128 + g; t < (chunk+1)*128; t += 16) {
        float4 v = *(const float4*)(vp + t*64 + d4*4);
        float w0 = fmaxf(fabsf(v.x + 5.0f), 1e-10f);
        float w1 = fmaxf(fabsf(v.y + 5.0f), 1e-10f);
        float w2 = fmaxf(fabsf(v.z + 5.0f), 1e-10f);
        float w3 = fmaxf(fabsf(v.w + 5.0f), 1e-10f);
        mx.x = fmaxf(mx.x, w0); mn.x = fminf(mn.x, w0);
        mx.y = fmaxf(mx.y, w1); mn.y = fminf(mn.y, w1);
        mx.z = fmaxf(mx.z, w2); mn.z = fminf(mn.z, w2);
        mx.w = fmaxf(mx.w, w3); mn.w = fminf(mn.w, w3);
    }
    __shared__ float4 redx[256];
    __shared__ float4 redn[256];
    redx[threadIdx.x] = mx;
    redn[threadIdx.x] = mn;
    __syncthreads();
    if (threadIdx.x < 16) {
        float4 m = redx[threadIdx.x];
        float4 q = redn[threadIdx.x];
#pragma unroll
        for (int gg = 1; gg < 16; gg++) {
            float4 o = redx[gg*16 + threadIdx.x];
            float4 u = redn[gg*16 + threadIdx.x];
            m.x = fmaxf(m.x, o.x); m.y = fmaxf(m.y, o.y);
            m.z = fmaxf(m.z, o.z); m.w = fmaxf(m.w, o.w);
            q.x = fminf(q.x, u.x); q.y = fminf(q.y, u.y);
            q.z = fminf(q.z, u.z); q.w = fminf(q.w, u.w);
        }
        int off = chunk*(Bn*Cn) + b*Cn + h*64 + threadIdx.x*4;
        *(float4*)(g_zpmax + off) = m;
        *(float4*)(g_zpmin + off) = q;
    }
}
__global__ __launch_bounds__(256) void zmax_reduce(const float* __restrict__ p_param)
{
    int i = blockIdx.x * 256 + threadIdx.x;   // 0..2047
    float wmax = -1e30f, wmin = 1e30f;
#pragma unroll
    for (int ch = 0; ch < 16; ch++) {
        wmax = fmaxf(wmax, g_zpmax[ch*(Bn*Cn) + i]);
        wmin = fminf(wmin, g_zpmin[ch*(Bn*Cn) + i]);
    }
    float p = clamp_p(p_param[i & (Cn-1)]);
    float zm = (p >= 0.0f) ? p * __logf(wmax) : p * __logf(wmin);
    g_zmax[i] = zm;
    g_E[i]    = __expf(zm);
    g_Einv[i] = __expf(-zm);
}

// ---------------------------------------------------------------------------
// V transform -> bf16 hi/lo. p==1 fast path: V = w * Einv (no MUFU).
// ---------------------------------------------------------------------------
__global__ __launch_bounds__(256) void vexp_kernel(const float* __restrict__ p_param)
{
    int i = blockIdx.x * 256 + threadIdx.x;
    int base = i * 4;
    int dd = base & 63;
    int bh = base >> 17;
    int h = bh & 15, b = bh >> 4;
    int c = h*64 + dd;
    float4 v = *(const float4*)(g_V + base);
    float e[4];
    const float vs[4] = {v.x, v.y, v.z, v.w};
#pragma unroll
    for (int j = 0; j < 4; j++) {
        float pvj = clamp_p(p_param[c + j]);
        float w = fmaxf(fabsf(vs[j] + 5.0f), 1e-10f);
        if (pvj == 1.0f) {
            e[j] = w * g_Einv[b*Cn + c + j];
        } else {
            e[j] = __expf(pvj * __logf(w) - g_zmax[b*Cn + c + j]);
        }
    }
    uint32_t h0 = pkbf(e[0], e[1]), h1 = pkbf(e[2], e[3]);
    float f0 = __uint_as_float(h0 << 16), f1 = __uint_as_float(h0 & 0xffff0000u);
    float f2 = __uint_as_float(h1 << 16), f3 = __uint_as_float(h1 & 0xffff0000u);
    uint32_t l0 = pkbf(e[0]-f0, e[1]-f1), l1 = pkbf(e[2]-f2, e[3]-f3);
    ((uint2*)g_Vh)[i] = make_uint2(h0, h1);
    ((uint2*)g_Vl)[i] = make_uint2(l0, l1);
}

// ---------------------------------------------------------------------------
// Tensor-core flash attention (causal), BQ=BK=64, 4 warps, 56 KB smem.
// S = fp16 1-term Qh·Kh; P·V bf16 3-term. p==1 fast-path epilogue.
// ---------------------------------------------------------------------------
#define FAQ_H 0
#define FASTG0 8192
#define FASTG_SZ 24576
#define FKH 0
#define FVH 8192
#define FVL 16384
#define FA_SMEM (8192 + 2*FASTG_SZ)   // 56 KB

__device__ __forceinline__ void fa_load_stage(uint32_t sbase, int bh, int kt, int tid)
{
    const char* srcs[3] = {(const char*)g_Kh, (const char*)g_Vh, (const char*)g_Vl};
#pragma unroll
    for (int j = 0; j < 12; j++) {
        int idx = tid + j * 128;          // 0..1535 16B-chunks
        int arr = idx >> 9;               // 0..2
        int rem = idx & 511;
        int row = rem >> 3, c = rem & 7;
        uint32_t sw = arr * 8192 + row * 128 + ((c ^ (row & 7)) << 4);
        size_t gb = (((size_t)bh * Tn + kt * 64 + row) * 64 + c * 8) * 2;
        cp16(sbase + sw, srcs[arr] + gb);
    }
}

__global__ __launch_bounds__(128) void fa_kernel(const float* __restrict__ p_param)
{
    extern __shared__ char smem[];
    uint32_t sb = smem_u32(smem);
    const int tid  = threadIdx.x;
    const int w    = tid >> 5;
    const int lane = tid & 31;
    const int quad = lane >> 2;
    const int idq  = lane & 3;
    const int bh = blockIdx.y;
    const int b = bh >> 4, h = bh & 15;
    const int qt = (int)gridDim.x - 1 - (int)blockIdx.x;   // heavy first
    const int q0 = qt * 64;

    // ---- prologue: Q tile (fp16 hi) + first stages ----
    {
#pragma unroll
        for (int j = 0; j < 4; j++) {
            int idx = tid + j * 128;      // 0..511 chunks (64 rows x 8)
            int row = idx >> 3, c = idx & 7;
            uint32_t sw = row * 128 + ((c ^ (row & 7)) << 4);
            size_t gb = (((size_t)bh * Tn + q0 + row) * 64 + c * 8) * 2;
            cp16(sb + FAQ_H + sw, (const char*)g_Qh + gb);
        }
        fa_load_stage(sb + FASTG0, bh, 0, tid);
        CP_COMMIT();
        if (qt >= 1) fa_load_stage(sb + FASTG0 + FASTG_SZ, bh, 1, tid);
        CP_COMMIT();
    }

    uint32_t Qh[4][4];
    float Of[8][4];
    float m0 = -1e30f, m1 = -1e30f, l0 = 0.0f, l1 = 0.0f;
#pragma unroll
    for (int nf = 0; nf < 8; nf++)
#pragma unroll
        for (int q = 0; q < 4; q++) Of[nf][q] = 0.0f;

    const int k_row = ((lane >> 4) << 3) + (lane & 7);   // + nf2*16
    const int k_cof = ((lane >> 3) & 1);                 // + ks*2
    const int v_row = (lane & 15);                       // + kf*16
    const int v_cof = (lane >> 4);                       // + nf2*2

    for (int kt = 0; kt <= qt; kt++) {
        const uint32_t sbase = sb + FASTG0 + (kt & 1) * FASTG_SZ;
        if (kt < qt) asm volatile("cp.async.wait_group 1;\n" ::: "memory");
        else         asm volatile("cp.async.wait_group 0;\n" ::: "memory");
        __syncthreads();

        if (kt == 0) {
            int row = w * 16 + (lane & 15);
#pragma unroll
            for (int ks = 0; ks < 4; ks++) {
                int c16 = ks * 2 + (lane >> 4);
                uint32_t sw = row * 128 + ((c16 ^ (row & 7)) << 4);
                ldsm4(Qh[ks][0], Qh[ks][1], Qh[ks][2], Qh[ks][3], sb + FAQ_H + sw);
            }
        }

        // ---- S = Qh Kh^T  (fp16, 1 term) ----
        float Sf[8][4];
#pragma unroll
        for (int nf = 0; nf < 8; nf++)
#pragma unroll
            for (int q = 0; q < 4; q++) Sf[nf][q] = 0.0f;

#pragma unroll
        for (int nf2 = 0; nf2 < 4; nf2++) {
            int krow = nf2 * 16 + k_row;
#pragma unroll
            for (int ks = 0; ks < 4; ks++) {
                int c16 = ks * 2 + k_cof;
                uint32_t sw = krow * 128 + ((c16 ^ (krow & 7)) << 4);
                uint32_t kh[4];
                ldsm4(kh[0], kh[1], kh[2], kh[3], sbase + FKH + sw);
                mma16816h(Sf[2*nf2],   Qh[ks], kh);
                mma16816h(Sf[2*nf2+1], Qh[ks], kh + 2);
            }
        }

        // ---- causal mask on diagonal tile ----
        if (kt == qt) {
            int r0 = w * 16 + quad, r1 = r0 + 8;
#pragma unroll
            for (int nf = 0; nf < 8; nf++) {
                int c0 = nf * 8 + idq * 2;
                if (c0     > r0) Sf[nf][0] = -1e30f;
                if (c0 + 1 > r0) Sf[nf][1] = -1e30f;
                if (c0     > r1) Sf[nf][2] = -1e30f;
                if (c0 + 1 > r1) Sf[nf][3] = -1e30f;
            }
        }

        // ---- softmax (register, 2 rows/thread, quad shuffles) ----
        float mx0 = -1e30f, mx1 = -1e30f;
#pragma unroll
        for (int nf = 0; nf < 8; nf++) {
            mx0 = fmaxf(mx0, fmaxf(Sf[nf][0], Sf[nf][1]));
            mx1 = fmaxf(mx1, fmaxf(Sf[nf][2], Sf[nf][3]));
        }
#pragma unroll
        for (int off = 1; off < 4; off <<= 1) {
            mx0 = fmaxf(mx0, __shfl_xor_sync(0xffffffffu, mx0, off));
            mx1 = fmaxf(mx1, __shfl_xor_sync(0xffffffffu, mx1, off));
        }
        mx0 = fmaxf(mx0, m0);
        mx1 = fmaxf(mx1, m1);
        float a0 = __expf(m0 - mx0), a1 = __expf(m1 - mx1);
        m0 = mx0; m1 = mx1;

        float s0 = 0.0f, s1 = 0.0f;
#pragma unroll
        for (int nf = 0; nf < 8; nf++) {
            Sf[nf][0] = __expf(Sf[nf][0] - mx0);
            Sf[nf][1] = __expf(Sf[nf][1] - mx0);
            Sf[nf][2] = __expf(Sf[nf][2] - mx1);
            Sf[nf][3] = __expf(Sf[nf][3] - mx1);
            s0 += Sf[nf][0] + Sf[nf][1];
            s1 += Sf[nf][2] + Sf[nf][3];
        }
#pragma unroll
        for (int off = 1; off < 4; off <<= 1) {
            s0 += __shfl_xor_sync(0xffffffffu, s0, off);
            s1 += __shfl_xor_sync(0xffffffffu, s1, off);
        }
        l0 = l0 * a0 + s0;
        l1 = l1 * a1 + s1;

#pragma unroll
        for (int nf = 0; nf < 8; nf++) {
            Of[nf][0] *= a0; Of[nf][1] *= a0;
            Of[nf][2] *= a1; Of[nf][3] *= a1;
        }

        // ---- O += P V (P from S frags, bf16x3, ldsm4t V) ----
#pragma unroll
        for (int kf = 0; kf < 4; kf++) {
            uint32_t pha[4], pla[4];
#pragma unroll
            for (int half = 0; half < 2; half++) {
                float* sp = Sf[2*kf + half];
                uint32_t u0 = pkbf(sp[0], sp[1]);
                uint32_t u1 = pkbf(sp[2], sp[3]);
                float f00 = __uint_as_float(u0 << 16), f01 = __uint_as_float(u0 & 0xffff0000u);
                float f10 = __uint_as_float(u1 << 16), f11 = __uint_as_float(u1 & 0xffff0000u);
                pha[half*2+0] = u0;
                pha[half*2+1] = u1;
                pla[half*2+0] = pkbf(sp[0] - f00, sp[1] - f01);
                pla[half*2+1] = pkbf(sp[2] - f10, sp[3] - f11);
            }
            int vrow = kf * 16 + v_row;
#pragma unroll
            for (int nf2 = 0; nf2 < 4; nf2++) {
                int c16 = nf2 * 2 + v_cof;
                uint32_t sw = vrow * 128 + ((c16 ^ (vrow & 7)) << 4);
                uint32_t vh[4], vl[4];
                ldsm4t(vh[0], vh[1], vh[2], vh[3], sbase + FVH + sw);
                ldsm4t(vl[0], vl[1], vl[2], vl[3], sbase + FVL + sw);
                mma16816(Of[2*nf2],   pha, vh);
                mma16816(Of[2*nf2],   pla, vh);
                mma16816(Of[2*nf2],   pha, vl);
                mma16816(Of[2*nf2+1], pha, vh + 2);
                mma16816(Of[2*nf2+1], pla, vh + 2);
                mma16816(Of[2*nf2+1], pha, vl + 2);
            }
        }

        __syncthreads();
        if (kt + 2 <= qt) {
            fa_load_stage(sbase, bh, kt + 2, tid);
            CP_COMMIT();
        }
    }

    // ---- epilogue: p==1: y = mean*E - 5; else general. Write fp16 hi ----
    const int t0 = q0 + w * 16 + quad;
    const int t1 = t0 + 8;
    float linv0 = 1.0f / l0, linv1 = 1.0f / l1;
#pragma unroll
    for (int nf = 0; nf < 8; nf++) {
        int d0 = nf * 8 + idq * 2;
        int cg = h * 64 + d0;
        float pv0 = clamp_p(p_param[cg]);
        float pv1 = clamp_p(p_param[cg + 1]);
        float me00 = Of[nf][0] * linv0, me01 = Of[nf][1] * linv0;
        float me10 = Of[nf][2] * linv1, me11 = Of[nf][3] * linv1;
        float y00, y01, y10, y11;
        if (pv0 == 1.0f) {
            float E0 = g_E[b*Cn + cg];
            y00 = me00 * E0 - 5.0f;
            y10 = me10 * E0 - 5.0f;
        } else {
            float zm0 = g_zmax[b*Cn + cg];
            y00 = __expf((zm0 + __logf(me00)) / pv0) - 5.0f;
            y10 = __expf((zm0 + __logf(me10)) / pv0) - 5.0f;
        }
        if (pv1 == 1.0f) {
            float E1 = g_E[b*Cn + cg + 1];
            y01 = me01 * E1 - 5.0f;
            y11 = me11 * E1 - 5.0f;
        } else {
            float zm1 = g_zmax[b*Cn + cg + 1];
            y01 = __expf((zm1 + __logf(me01)) / pv1) - 5.0f;
            y11 = __expf((zm1 + __logf(me11)) / pv1) - 5.0f;
        }
        size_t i0 = ((size_t)(b*Tn + t0)*Cn + cg) >> 1;
        size_t i1 = ((size_t)(b*Tn + t1)*Cn + cg) >> 1;
        ((uint32_t*)gA_hi)[i0] = pkhf(y00, y01);
        ((uint32_t*)gA_hi)[i1] = pkhf(y10, y11);
    }
}

// ---------------------------------------------------------------------------

extern "C" void kernel_launch(void* const* d_in, const int* in_sizes, int n_in,
                              void* d_out, int out_size)
{
    const float* x       = (const float*)d_in[0];
    const float* w_attn  = (const float*)d_in[1];
    const float* b_attn  = (const float*)d_in[2];
    const float* w_proj  = (const float*)d_in[3];
    const float* b_proj  = (const float*)d_in[4];
    const float* p_param = (const float*)d_in[5];
    float* out = (float*)d_out;

    void *ah, *bth, *bt2;
    cudaGetSymbolAddress(&ah,  gA_hi);
    cudaGetSymbolAddress(&bth, gBT_hi);
    cudaGetSymbolAddress(&bt2, gBT2);

    cudaFuncSetAttribute(fa_kernel, cudaFuncAttributeMaxDynamicSharedMemorySize, FA_SMEM);
    cudaFuncSetAttribute(tc_gemm<0>, cudaFuncAttributeMaxDynamicSharedMemorySize, TCG_SMEM);
    cudaFuncSetAttribute(tc_gemm<1>, cudaFuncAttributeMaxDynamicSharedMemorySize, TCG_SMEM);

    // 1) mega prep: conv x -> fp16, transpose w_attn, transpose w_proj
    prep_kernel<<<8192, 256>>>(x, w_attn, w_proj);

    // 2) QKV GEMM (fp16 single-term) + head-major scatter (Q/K fp16 hi, V fp32)
    tc_gemm<1><<<dim3(3072/128, Mn/128), 256, TCG_SMEM>>>(
        (const __half*)ah, (const __half*)bth, b_attn, nullptr);

    // 3) w-range partial + reduce (zmax/E/Einv) + V transform -> bf16 hi/lo
    zmax_part<<<dim3(BHn, 16), 256>>>();
    zmax_reduce<<<(Bn*Cn)/256, 256>>>(p_param);
    vexp_kernel<<<(BHn*Tn*Dn)/1024, 256>>>(p_param);

    // 4) tensor-core causal FA (fp16 1-term QK, bf16x3 PV); Y -> gA fp16 hi
    fa_kernel<<<dim3(Tn/64, BHn), 128, FA_SMEM>>>(p_param);

    // 5) proj GEMM (fp16 single-term)
    tc_gemm<0><<<dim3(Cn/128, Mn/128), 256, TCG_SMEM>>>(
        (const __half*)ah, (const __half*)bt2, b_proj, out);
}

// round 14
// speedup vs baseline: 7.2673x; 1.0274x over previous
#include <cuda_runtime.h>
#include <cuda_bf16.h>
#include <cuda_fp16.h>
#include <math.h>
#include <stdint.h>

#define Bn 2
#define Tn 2048
#define Cn 1024
#define Hn 16
#define Dn 64
#define Mn (Bn*Tn)          // 4096
#define BHn (Bn*Hn)         // 32

typedef unsigned long long ull;

// ---------------- device scratch ----------------
__device__ __half         g_Qh[BHn*Tn*Dn];  // head-major, pre-scaled by 0.125 (fp16 hi only)
__device__ __half         g_Kh[BHn*Tn*Dn];  // fp16 hi only
__device__ float          g_V [BHn*Tn*Dn];  // raw v (fp32) -- only for p!=1 channels
__device__ __nv_bfloat16  g_Vh[BHn*Tn*Dn];  // transformed V bf16 hi/lo
__device__ __nv_bfloat16  g_Vl[BHn*Tn*Dn];
__device__ float g_zmax[Bn*Cn];
__device__ float g_zpmax[16*Bn*Cn];         // partial wmax (p!=1 only)
__device__ float g_zpmin[16*Bn*Cn];         // partial wmin (p!=1 only)
__device__ __half gA_hi[Mn*Cn];             // fp16 A operand (x conv, then Y from FA)
__device__ __half gBT_hi[3*Cn*Cn];          // fp16 w_attn^T
__device__ __half gBT2  [Cn*Cn];            // fp16 w_proj^T

__device__ __forceinline__ float clamp_p(float pp) {
    float sgn = (pp >= 0.0f) ? 1.0f : -1.0f;
    return sgn * fminf(fmaxf(fabsf(pp), 1e-4f), 1e3f);
}

// ---------------- ptx helpers ----------------
__device__ __forceinline__ uint32_t smem_u32(const void* p) {
    uint32_t a;
    asm("{ .reg .u64 t; cvta.to.shared.u64 t, %1; cvt.u32.u64 %0, t; }" : "=r"(a) : "l"(p));
    return a;
}
__device__ __forceinline__ void cp16(uint32_t dst, const void* src) {
    asm volatile("cp.async.cg.shared.global [%0], [%1], 16;\n" :: "r"(dst), "l"(src));
}
#define CP_COMMIT() asm volatile("cp.async.commit_group;\n" ::: "memory")

__device__ __forceinline__ void ldsm4(uint32_t& r0, uint32_t& r1, uint32_t& r2, uint32_t& r3,
                                      uint32_t addr) {
    asm volatile("ldmatrix.sync.aligned.m8n8.x4.shared.b16 {%0,%1,%2,%3}, [%4];"
                 : "=r"(r0), "=r"(r1), "=r"(r2), "=r"(r3) : "r"(addr));
}
__device__ __forceinline__ void ldsm4t(uint32_t& r0, uint32_t& r1, uint32_t& r2, uint32_t& r3,
                                       uint32_t addr) {
    asm volatile("ldmatrix.sync.aligned.m8n8.x4.trans.shared.b16 {%0,%1,%2,%3}, [%4];"
                 : "=r"(r0), "=r"(r1), "=r"(r2), "=r"(r3) : "r"(addr));
}
__device__ __forceinline__ void mma16816(float* c, const uint32_t* a, const uint32_t* b) {
    asm volatile(
        "mma.sync.aligned.m16n8k16.row.col.f32.bf16.bf16.f32 "
        "{%0,%1,%2,%3}, {%4,%5,%6,%7}, {%8,%9}, {%0,%1,%2,%3};"
        : "+f"(c[0]), "+f"(c[1]), "+f"(c[2]), "+f"(c[3])
        : "r"(a[0]), "r"(a[1]), "r"(a[2]), "r"(a[3]), "r"(b[0]), "r"(b[1]));
}
__device__ __forceinline__ void mma16816h(float* c, const uint32_t* a, const uint32_t* b) {
    asm volatile(
        "mma.sync.aligned.m16n8k16.row.col.f32.f16.f16.f32 "
        "{%0,%1,%2,%3}, {%4,%5,%6,%7}, {%8,%9}, {%0,%1,%2,%3};"
        : "+f"(c[0]), "+f"(c[1]), "+f"(c[2]), "+f"(c[3])
        : "r"(a[0]), "r"(a[1]), "r"(a[2]), "r"(a[3]), "r"(b[0]), "r"(b[1]));
}
__device__ __forceinline__ uint32_t pkbf(float lo, float hi) {
    uint32_t r;
    asm("cvt.rn.bf16x2.f32 %0, %1, %2;" : "=r"(r) : "f"(hi), "f"(lo));
    return r;
}
__device__ __forceinline__ uint32_t pkhf(float lo, float hi) {
    uint32_t r;
    asm("cvt.rn.f16x2.f32 %0, %1, %2;" : "=r"(r) : "f"(hi), "f"(lo));
    return r;
}
// split two floats into bf16 hi word + lo word
__device__ __forceinline__ void bfsplit(float a, float b, uint32_t& hi, uint32_t& lo) {
    hi = pkbf(a, b);
    float f0 = __uint_as_float(hi << 16);
    float f1 = __uint_as_float(hi & 0xffff0000u);
    lo = pkbf(a - f0, b - f1);
}

// ---------------------------------------------------------------------------
// mega prep: [0,4096) conv x->fp16; [4096,7168) transpose w_attn;
// [7168,8192) transpose w_proj.
// ---------------------------------------------------------------------------
__global__ __launch_bounds__(256) void prep_kernel(
    const float* __restrict__ x,
    const float* __restrict__ w_attn,
    const float* __restrict__ w_proj)
{
    __shared__ float tile[32][33];
    int bid = blockIdx.x;
    int tid = threadIdx.x;
    if (bid < 4096) {
        int i = bid * 256 + tid;
        float4 a = ((const float4*)x)[i];
        ((uint2*)gA_hi)[i] = make_uint2(pkhf(a.x, a.y), pkhf(a.z, a.w));
        return;
    }
    const float* W;
    __half* Th;
    int Nd, bx, by;
    if (bid < 7168) {
        int t = bid - 4096;
        W = w_attn; Th = gBT_hi; Nd = 3072;
        bx = t % 96; by = t / 96;
    } else {
        int t = bid - 7168;
        W = w_proj; Th = gBT2; Nd = 1024;
        bx = t % 32; by = t / 32;
    }
    int nx = bx * 32, kx = by * 32;
    int tx = tid & 31, ty = tid >> 5;   // 32x8
#pragma unroll
    for (int r = ty; r < 32; r += 8)
        tile[r][tx] = W[(size_t)(kx + r) * Nd + nx + tx];
    __syncthreads();
#pragma unroll
    for (int r = ty; r < 32; r += 8) {
        size_t o = (size_t)(nx + r) * 1024 + kx + tx;
        Th[o] = __float2half_rn(tile[tx][r]);
    }
}

// ---------------------------------------------------------------------------
// fp16 single-term mma.sync GEMM: CTA 128x128, warp tile 64x32 (2x4 warps),
// BK=64, cp.async double buffer, 64 KB smem. D = Ah @ Bh^T.
// MODE 0: out+bias. MODE 1: QKV scatter; V section fused transform for p==1.
// ---------------------------------------------------------------------------
#define G_BHI 16384
#define G_STG 32768
#define TCG_SMEM (2*G_STG)   // 64 KB

__device__ __forceinline__ void load_stage(
    uint32_t sbase,
    const __half* __restrict__ Ah, const __half* __restrict__ Bh,
    int m0, int n0, int k0, int tid)
{
#pragma unroll
    for (int j = 0; j < 4; j++) {          // A: 128 rows x 8 chunks
        int idx = tid + j * 256;
        int row = idx >> 3, c = idx & 7;
        uint32_t sw = row * 128 + ((c ^ (row & 7)) << 4);
        size_t ga = (size_t)(m0 + row) * 1024 + k0 + c * 8;
        cp16(sbase + sw, Ah + ga);
    }
#pragma unroll
    for (int j = 0; j < 4; j++) {          // B: 128 rows x 8 chunks
        int idx = tid + j * 256;
        int row = idx >> 3, c = idx & 7;
        uint32_t sw = row * 128 + ((c ^ (row & 7)) << 4);
        size_t gb = (size_t)(n0 + row) * 1024 + k0 + c * 8;
        cp16(sbase + G_BHI + sw, Bh + gb);
    }
}

template<int MODE>
__global__ __launch_bounds__(256, 2) void tc_gemm(
    const __half* __restrict__ Ah, const __half* __restrict__ Bh,
    const float* __restrict__ bias, float* __restrict__ Cout,
    const float* __restrict__ p_param)
{
    extern __shared__ char smem[];
    uint32_t sb = smem_u32(smem);
    const int tid  = threadIdx.x;
    const int wid  = tid >> 5;
    const int lane = tid & 31;
    const int wm = wid & 1;        // 2 warp-rows of 64
    const int wn = wid >> 1;       // 4 warp-cols of 32
    const int m0 = blockIdx.y * 128;
    const int n0 = blockIdx.x * 128;

    float acc[4][4][4];
#pragma unroll
    for (int i = 0; i < 4; i++)
#pragma unroll
        for (int j = 0; j < 4; j++)
#pragma unroll
            for (int q = 0; q < 4; q++) acc[i][j][q] = 0.0f;

    load_stage(sb,         Ah, Bh, m0, n0, 0,  tid); CP_COMMIT();
    load_stage(sb + G_STG, Ah, Bh, m0, n0, 64, tid); CP_COMMIT();

    const int a_row = wm * 64 + (lane & 15);
    const int a_c16 = (lane >> 4);
    const int b_row = wn * 32 + ((lane >> 4) << 3) + (lane & 7);
    const int b_cof = ((lane >> 3) & 1);

    for (int it = 0; it < 16; it++) {
        const int s = it & 1;
        const uint32_t sbase = sb + s * G_STG;
        if (it < 15) asm volatile("cp.async.wait_group 1;\n" ::: "memory");
        else         asm volatile("cp.async.wait_group 0;\n" ::: "memory");
        __syncthreads();

#pragma unroll
        for (int ks = 0; ks < 4; ks++) {
            uint32_t ahi[4][4];
#pragma unroll
            for (int mf = 0; mf < 4; mf++) {
                int row = a_row + mf * 16;
                int c16 = ks * 2 + a_c16;
                uint32_t ad = sbase + row * 128 + ((c16 ^ (row & 7)) << 4);
                ldsm4(ahi[mf][0], ahi[mf][1], ahi[mf][2], ahi[mf][3], ad);
            }
#pragma unroll
            for (int nf2 = 0; nf2 < 2; nf2++) {
                int row = b_row + nf2 * 16;
                int c16 = ks * 2 + b_cof;
                uint32_t bd = sbase + G_BHI + row * 128 + ((c16 ^ (row & 7)) << 4);
                uint32_t bh4[4];
                ldsm4(bh4[0], bh4[1], bh4[2], bh4[3], bd);
#pragma unroll
                for (int mf = 0; mf < 4; mf++) {
                    mma16816h(acc[mf][2*nf2],   ahi[mf], bh4);
                    mma16816h(acc[mf][2*nf2+1], ahi[mf], bh4 + 2);
                }
            }
        }
        __syncthreads();
        if (it + 2 < 16) {
            load_stage(sbase, Ah, Bh, m0, n0, (it + 2) * 64, tid);
            CP_COMMIT();
        }
    }

    const int mbase = m0 + wm * 64 + (lane >> 2);
    const int nbase = n0 + wn * 32 + (lane & 3) * 2;
    // section is uniform per CTA (n0 is 128-aligned, sections 1024-aligned)
    const int sec = n0 >> 10;
    // per-thread channel pairs (depend on nf only)
    float pp0[4], pp1[4];
    if (MODE == 1 && sec == 2) {
#pragma unroll
        for (int nf = 0; nf < 4; nf++) {
            int c1 = (nbase + nf * 8) & 1023;
            pp0[nf] = clamp_p(p_param[c1]);
            pp1[nf] = clamp_p(p_param[c1 + 1]);
        }
    }
#pragma unroll
    for (int mf = 0; mf < 4; mf++) {
#pragma unroll
        for (int half = 0; half < 2; half++) {
            int m = mbase + mf * 16 + half * 8;
#pragma unroll
            for (int nf = 0; nf < 4; nf++) {
                int n = nbase + nf * 8;
                float v0 = acc[mf][nf][half*2+0] + bias[n];
                float v1 = acc[mf][nf][half*2+1] + bias[n+1];
                if (MODE == 0) {
                    *(float2*)(Cout + (size_t)m * Cn + n) = make_float2(v0, v1);
                } else {
                    int c1  = n & 1023;
                    int h   = c1 >> 6, dd = c1 & 63;
                    int bq  = m >> 11, t = m & 2047;
                    size_t idx = ((size_t)((bq * Hn + h) * Tn + t)) * 64 + dd;
                    if (sec == 2) {
                        if (pp0[nf] == 1.0f && pp1[nf] == 1.0f) {
                            // fused V transform (p==1): V = clip(|v+5|)
                            float w0 = fmaxf(fabsf(v0 + 5.0f), 1e-10f);
                            float w1 = fmaxf(fabsf(v1 + 5.0f), 1e-10f);
                            uint32_t hh, ll;
                            bfsplit(w0, w1, hh, ll);
                            ((uint32_t*)g_Vh)[idx >> 1] = hh;
                            ((uint32_t*)g_Vl)[idx >> 1] = ll;
                        } else {
                            *(float2*)(g_V + idx) = make_float2(v0, v1);
                        }
                    } else if (sec == 1) {
                        *(uint32_t*)(g_Kh + idx) = pkhf(v0, v1);
                    } else {
                        *(uint32_t*)(g_Qh + idx) = pkhf(v0 * 0.125f, v1 * 0.125f);
                    }
                }
            }
        }
    }
}

// ---------------------------------------------------------------------------
// w-range partial: only for channels with p != 1 (skips all loads otherwise)
// ---------------------------------------------------------------------------
__global__ __launch_bounds__(256) void zmax_part(const float* __restrict__ p_param)
{
    int bh = blockIdx.x, chunk = blockIdx.y;
    int b = bh >> 4, h = bh & 15;
    int d4 = threadIdx.x & 15;
    int g  = threadIdx.x >> 4;
    int c  = h*64 + d4*4;

    bool need = (clamp_p(p_param[c+0]) != 1.0f) || (clamp_p(p_param[c+1]) != 1.0f) ||
                (clamp_p(p_param[c+2]) != 1.0f) || (clamp_p(p_param[c+3]) != 1.0f);

    float4 mx = make_float4(-1e30f, -1e30f, -1e30f, -1e30f);
    float4 mn = make_float4( 1e30f,  1e30f,  1e30f,  1e30f);
    if (need) {
        const float* vp = g_V + (size_t)bh * Tn * 64;
        for (int t = chunk*128 + g; t < (chunk+1)*128; t += 16) {
            float4 v = *(const float4*)(vp + t*64 + d4*4);
            float w0 = fmaxf(fabsf(v.x + 5.0f), 1e-10f);
            float w1 = fmaxf(fabsf(v.y + 5.0f), 1e-10f);
            float w2 = fmaxf(fabsf(v.z + 5.0f), 1e-10f);
            float w3 = fmaxf(fabsf(v.w + 5.0f), 1e-10f);
            mx.x = fmaxf(mx.x, w0); mn.x = fminf(mn.x, w0);
            mx.y = fmaxf(mx.y, w1); mn.y = fminf(mn.y, w1);
            mx.z = fmaxf(mx.z, w2); mn.z = fminf(mn.z, w2);
            mx.w = fmaxf(mx.w, w3); mn.w = fminf(mn.w, w3);
        }
    }
    __shared__ float4 redx[256];
    __shared__ float4 redn[256];
    redx[threadIdx.x] = mx;
    redn[threadIdx.x] = mn;
    __syncthreads();
    if (threadIdx.x < 16) {
        float4 m = redx[threadIdx.x];
        float4 q = redn[threadIdx.x];
#pragma unroll
        for (int gg = 1; gg < 16; gg++) {
            float4 o = redx[gg*16 + threadIdx.x];
            float4 u = redn[gg*16 + threadIdx.x];
            m.x = fmaxf(m.x, o.x); m.y = fmaxf(m.y, o.y);
            m.z = fmaxf(m.z, o.z); m.w = fmaxf(m.w, o.w);
            q.x = fminf(q.x, u.x); q.y = fminf(q.y, u.y);
            q.z = fminf(q.z, u.z); q.w = fminf(q.w, u.w);
        }
        int off = chunk*(Bn*Cn) + b*Cn + h*64 + threadIdx.x*4;
        *(float4*)(g_zpmax + off) = m;
        *(float4*)(g_zpmin + off) = q;
    }
}
__global__ __launch_bounds__(256) void zmax_reduce(const float* __restrict__ p_param)
{
    int i = blockIdx.x * 256 + threadIdx.x;   // 0..2047
    float p = clamp_p(p_param[i & (Cn-1)]);
    if (p == 1.0f) { g_zmax[i] = 0.0f; return; }
    float wmax = -1e30f, wmin = 1e30f;
#pragma unroll
    for (int ch = 0; ch < 16; ch++) {
        wmax = fmaxf(wmax, g_zpmax[ch*(Bn*Cn) + i]);
        wmin = fminf(wmin, g_zpmin[ch*(Bn*Cn) + i]);
    }
    g_zmax[i] = (p >= 0.0f) ? p * __logf(wmax) : p * __logf(wmin);
}

// ---------------------------------------------------------------------------
// V transform fixup: only for channel pairs with p != 1 (no-op otherwise)
// ---------------------------------------------------------------------------
__global__ __launch_bounds__(256) void vexp_kernel(const float* __restrict__ p_param)
{
    int i = blockIdx.x * 256 + threadIdx.x;
    int base = i * 4;
    int dd = base & 63;
    int bh = base >> 17;
    int h = bh & 15, b = bh >> 4;
    int c = h*64 + dd;
    float p0 = clamp_p(p_param[c+0]), p1 = clamp_p(p_param[c+1]);
    float p2 = clamp_p(p_param[c+2]), p3 = clamp_p(p_param[c+3]);
    bool f01 = (p0 == 1.0f) && (p1 == 1.0f);
    bool f23 = (p2 == 1.0f) && (p3 == 1.0f);
    if (f01 && f23) return;
    if (!f01) {
        float2 v = *(const float2*)(g_V + base);
        float w0 = fmaxf(fabsf(v.x + 5.0f), 1e-10f);
        float w1 = fmaxf(fabsf(v.y + 5.0f), 1e-10f);
        float e0 = (p0 == 1.0f) ? w0 : __expf(p0 * __logf(w0) - g_zmax[b*Cn + c]);
        float e1 = (p1 == 1.0f) ? w1 : __expf(p1 * __logf(w1) - g_zmax[b*Cn + c + 1]);
        uint32_t hh, ll;
        bfsplit(e0, e1, hh, ll);
        ((uint32_t*)g_Vh)[base >> 1] = hh;
        ((uint32_t*)g_Vl)[base >> 1] = ll;
    }
    if (!f23) {
        float2 v = *(const float2*)(g_V + base + 2);
        float w0 = fmaxf(fabsf(v.x + 5.0f), 1e-10f);
        float w1 = fmaxf(fabsf(v.y + 5.0f), 1e-10f);
        float e0 = (p2 == 1.0f) ? w0 : __expf(p2 * __logf(w0) - g_zmax[b*Cn + c + 2]);
        float e1 = (p3 == 1.0f) ? w1 : __expf(p3 * __logf(w1) - g_zmax[b*Cn + c + 3]);
        uint32_t hh, ll;
        bfsplit(e0, e1, hh, ll);
        ((uint32_t*)g_Vh)[(base + 2) >> 1] = hh;
        ((uint32_t*)g_Vl)[(base + 2) >> 1] = ll;
    }
}

// ---------------------------------------------------------------------------
// Tensor-core flash attention (causal), BQ=BK=64, 4 warps, 56 KB smem.
// S = fp16 1-term Qh·Kh; P·V bf16 3-term. p==1: y = mean - 5.
// ---------------------------------------------------------------------------
#define FAQ_H 0
#define FASTG0 8192
#define FASTG_SZ 24576
#define FKH 0
#define FVH 8192
#define FVL 16384
#define FA_SMEM (8192 + 2*FASTG_SZ)   // 56 KB

__device__ __forceinline__ void fa_load_stage(uint32_t sbase, int bh, int kt, int tid)
{
    const char* srcs[3] = {(const char*)g_Kh, (const char*)g_Vh, (const char*)g_Vl};
#pragma unroll
    for (int j = 0; j < 12; j++) {
        int idx = tid + j * 128;          // 0..1535 16B-chunks
        int arr = idx >> 9;               // 0..2
        int rem = idx & 511;
        int row = rem >> 3, c = rem & 7;
        uint32_t sw = arr * 8192 + row * 128 + ((c ^ (row & 7)) << 4);
        size_t gb = (((size_t)bh * Tn + kt * 64 + row) * 64 + c * 8) * 2;
        cp16(sbase + sw, srcs[arr] + gb);
    }
}

__global__ __launch_bounds__(128) void fa_kernel(const float* __restrict__ p_param)
{
    extern __shared__ char smem[];
    uint32_t sb = smem_u32(smem);
    const int tid  = threadIdx.x;
    const int w    = tid >> 5;
    const int lane = tid & 31;
    const int quad = lane >> 2;
    const int idq  = lane & 3;
    const int bh = blockIdx.y;
    const int b = bh >> 4, h = bh & 15;
    const int qt = (int)gridDim.x - 1 - (int)blockIdx.x;   // heavy first
    const int q0 = qt * 64;

    // ---- prologue: Q tile (fp16 hi) + first stages ----
    {
#pragma unroll
        for (int j = 0; j < 4; j++) {
            int idx = tid + j * 128;      // 0..511 chunks (64 rows x 8)
            int row = idx >> 3, c = idx & 7;
            uint32_t sw = row * 128 + ((c ^ (row & 7)) << 4);
            size_t gb = (((size_t)bh * Tn + q0 + row) * 64 + c * 8) * 2;
            cp16(sb + FAQ_H + sw, (const char*)g_Qh + gb);
        }
        fa_load_stage(sb + FASTG0, bh, 0, tid);
        CP_COMMIT();
        if (qt >= 1) fa_load_stage(sb + FASTG0 + FASTG_SZ, bh, 1, tid);
        CP_COMMIT();
    }

    uint32_t Qh[4][4];
    float Of[8][4];
    float m0 = -1e30f, m1 = -1e30f, l0 = 0.0f, l1 = 0.0f;
#pragma unroll
    for (int nf = 0; nf < 8; nf++)
#pragma unroll
        for (int q = 0; q < 4; q++) Of[nf][q] = 0.0f;

    const int k_row = ((lane >> 4) << 3) + (lane & 7);   // + nf2*16
    const int k_cof = ((lane >> 3) & 1);                 // + ks*2
    const int v_row = (lane & 15);                       // + kf*16
    const int v_cof = (lane >> 4);                       // + nf2*2

    for (int kt = 0; kt <= qt; kt++) {
        const uint32_t sbase = sb + FASTG0 + (kt & 1) * FASTG_SZ;
        if (kt < qt) asm volatile("cp.async.wait_group 1;\n" ::: "memory");
        else         asm volatile("cp.async.wait_group 0;\n" ::: "memory");
        __syncthreads();

        if (kt == 0) {
            int row = w * 16 + (lane & 15);
#pragma unroll
            for (int ks = 0; ks < 4; ks++) {
                int c16 = ks * 2 + (lane >> 4);
                uint32_t sw = row * 128 + ((c16 ^ (row & 7)) << 4);
                ldsm4(Qh[ks][0], Qh[ks][1], Qh[ks][2], Qh[ks][3], sb + FAQ_H + sw);
            }
        }

        // ---- S = Qh Kh^T  (fp16, 1 term) ----
        float Sf[8][4];
#pragma unroll
        for (int nf = 0; nf < 8; nf++)
#pragma unroll
            for (int q = 0; q < 4; q++) Sf[nf][q] = 0.0f;

#pragma unroll
        for (int nf2 = 0; nf2 < 4; nf2++) {
            int krow = nf2 * 16 + k_row;
#pragma unroll
            for (int ks = 0; ks < 4; ks++) {
                int c16 = ks * 2 + k_cof;
                uint32_t sw = krow * 128 + ((c16 ^ (krow & 7)) << 4);
                uint32_t kh[4];
                ldsm4(kh[0], kh[1], kh[2], kh[3], sbase + FKH + sw);
                mma16816h(Sf[2*nf2],   Qh[ks], kh);
                mma16816h(Sf[2*nf2+1], Qh[ks], kh + 2);
            }
        }

        // ---- causal mask on diagonal tile ----
        if (kt == qt) {
            int r0 = w * 16 + quad, r1 = r0 + 8;
#pragma unroll
            for (int nf = 0; nf < 8; nf++) {
                int c0 = nf * 8 + idq * 2;
                if (c0     > r0) Sf[nf][0] = -1e30f;
                if (c0 + 1 > r0) Sf[nf][1] = -1e30f;
                if (c0     > r1) Sf[nf][2] = -1e30f;
                if (c0 + 1 > r1) Sf[nf][3] = -1e30f;
            }
        }

        // ---- softmax (register, 2 rows/thread, quad shuffles) ----
        float mx0 = -1e30f, mx1 = -1e30f;
#pragma unroll
        for (int nf = 0; nf < 8; nf++) {
            mx0 = fmaxf(mx0, fmaxf(Sf[nf][0], Sf[nf][1]));
            mx1 = fmaxf(mx1, fmaxf(Sf[nf][2], Sf[nf][3]));
        }
#pragma unroll
        for (int off = 1; off < 4; off <<= 1) {
            mx0 = fmaxf(mx0, __shfl_xor_sync(0xffffffffu, mx0, off));
            mx1 = fmaxf(mx1, __shfl_xor_sync(0xffffffffu, mx1, off));
        }
        mx0 = fmaxf(mx0, m0);
        mx1 = fmaxf(mx1, m1);
        float a0 = __expf(m0 - mx0), a1 = __expf(m1 - mx1);
        m0 = mx0; m1 = mx1;

        float s0 = 0.0f, s1 = 0.0f;
#pragma unroll
        for (int nf = 0; nf < 8; nf++) {
            Sf[nf][0] = __expf(Sf[nf][0] - mx0);
            Sf[nf][1] = __expf(Sf[nf][1] - mx0);
            Sf[nf][2] = __expf(Sf[nf][2] - mx1);
            Sf[nf][3] = __expf(Sf[nf][3] - mx1);
            s0 += Sf[nf][0] + Sf[nf][1];
            s1 += Sf[nf][2] + Sf[nf][3];
        }
#pragma unroll
        for (int off = 1; off < 4; off <<= 1) {
            s0 += __shfl_xor_sync(0xffffffffu, s0, off);
            s1 += __shfl_xor_sync(0xffffffffu, s1, off);
        }
        l0 = l0 * a0 + s0;
        l1 = l1 * a1 + s1;

#pragma unroll
        for (int nf = 0; nf < 8; nf++) {
            Of[nf][0] *= a0; Of[nf][1] *= a0;
            Of[nf][2] *= a1; Of[nf][3] *= a1;
        }

        // ---- O += P V (P from S frags, bf16x3, ldsm4t V) ----
#pragma unroll
        for (int kf = 0; kf < 4; kf++) {
            uint32_t pha[4], pla[4];
#pragma unroll
            for (int half = 0; half < 2; half++) {
                float* sp = Sf[2*kf + half];
                bfsplit(sp[0], sp[1], pha[half*2+0], pla[half*2+0]);
                bfsplit(sp[2], sp[3], pha[half*2+1], pla[half*2+1]);
            }
            int vrow = kf * 16 + v_row;
#pragma unroll
            for (int nf2 = 0; nf2 < 4; nf2++) {
                int c16 = nf2 * 2 + v_cof;
                uint32_t sw = vrow * 128 + ((c16 ^ (vrow & 7)) << 4);
                uint32_t vh[4], vl[4];
                ldsm4t(vh[0], vh[1], vh[2], vh[3], sbase + FVH + sw);
                ldsm4t(vl[0], vl[1], vl[2], vl[3], sbase + FVL + sw);
                mma16816(Of[2*nf2],   pha, vh);
                mma16816(Of[2*nf2],   pla, vh);
                mma16816(Of[2*nf2],   pha, vl);
                mma16816(Of[2*nf2+1], pha, vh + 2);
                mma16816(Of[2*nf2+1], pla, vh + 2);
                mma16816(Of[2*nf2+1], pha, vl + 2);
            }
        }

        __syncthreads();
        if (kt + 2 <= qt) {
            fa_load_stage(sbase, bh, kt + 2, tid);
            CP_COMMIT();
        }
    }

    // ---- epilogue: p==1: y = mean - 5 (V unnormalized); else general ----
    const int t0 = q0 + w * 16 + quad;
    const int t1 = t0 + 8;
    float linv0 = 1.0f / l0, linv1 = 1.0f / l1;
#pragma unroll
    for (int nf = 0; nf < 8; nf++) {
        int d0 = nf * 8 + idq * 2;
        int cg = h * 64 + d0;
        float pv0 = clamp_p(p_param[cg]);
        float pv1 = clamp_p(p_param[cg + 1]);
        float me00 = Of[nf][0] * linv0, me01 = Of[nf][1] * linv0;
        float me10 = Of[nf][2] * linv1, me11 = Of[nf][3] * linv1;
        float y00, y01, y10, y11;
        if (pv0 == 1.0f) {
            y00 = me00 - 5.0f;
            y10 = me10 - 5.0f;
        } else {
            float zm0 = g_zmax[b*Cn + cg];
            y00 = __expf((zm0 + __logf(me00)) / pv0) - 5.0f;
            y10 = __expf((zm0 + __logf(me10)) / pv0) - 5.0f;
        }
        if (pv1 == 1.0f) {
            y01 = me01 - 5.0f;
            y11 = me11 - 5.0f;
        } else {
            float zm1 = g_zmax[b*Cn + cg + 1];
            y01 = __expf((zm1 + __logf(me01)) / pv1) - 5.0f;
            y11 = __expf((zm1 + __logf(me11)) / pv1) - 5.0f;
        }
        size_t i0 = ((size_t)(b*Tn + t0)*Cn + cg) >> 1;
        size_t i1 = ((size_t)(b*Tn + t1)*Cn + cg) >> 1;
        ((uint32_t*)gA_hi)[i0] = pkhf(y00, y01);
        ((uint32_t*)gA_hi)[i1] = pkhf(y10, y11);
    }
}

// ---------------------------------------------------------------------------

extern "C" void kernel_launch(void* const* d_in, const int* in_sizes, int n_in,
                              void* d_out, int out_size)
{
    const float* x       = (const float*)d_in[0];
    const float* w_attn  = (const float*)d_in[1];
    const float* b_attn  = (const float*)d_in[2];
    const float* w_proj  = (const float*)d_in[3];
    const float* b_proj  = (const float*)d_in[4];
    const float* p_param = (const float*)d_in[5];
    float* out = (float*)d_out;

    void *ah, *bth, *bt2;
    cudaGetSymbolAddress(&ah,  gA_hi);
    cudaGetSymbolAddress(&bth, gBT_hi);
    cudaGetSymbolAddress(&bt2, gBT2);

    cudaFuncSetAttribute(fa_kernel, cudaFuncAttributeMaxDynamicSharedMemorySize, FA_SMEM);
    cudaFuncSetAttribute(tc_gemm<0>, cudaFuncAttributeMaxDynamicSharedMemorySize, TCG_SMEM);
    cudaFuncSetAttribute(tc_gemm<1>, cudaFuncAttributeMaxDynamicSharedMemorySize, TCG_SMEM);

    // 1) mega prep: conv x -> fp16, transpose w_attn, transpose w_proj
    prep_kernel<<<8192, 256>>>(x, w_attn, w_proj);

    // 2) QKV GEMM + scatter; V transform fused for p==1 channels
    tc_gemm<1><<<dim3(3072/128, Mn/128), 256, TCG_SMEM>>>(
        (const __half*)ah, (const __half*)bth, b_attn, nullptr, p_param);

    // 3) zmax machinery (p!=1 channels only; near-no-op when p==1 everywhere)
    zmax_part<<<dim3(BHn, 16), 256>>>(p_param);
    zmax_reduce<<<(Bn*Cn)/256, 256>>>(p_param);
    vexp_kernel<<<(BHn*Tn*Dn)/1024, 256>>>(p_param);

    // 4) tensor-core causal FA (fp16 1-term QK, bf16x3 PV); Y -> gA fp16 hi
    fa_kernel<<<dim3(Tn/64, BHn), 128, FA_SMEM>>>(p_param);

    // 5) proj GEMM (fp16 single-term)
    tc_gemm<0><<<dim3(Cn/128, Mn/128), 256, TCG_SMEM>>>(
        (const __half*)ah, (const __half*)bt2, b_proj, out, nullptr);
}